// round 1
// baseline (speedup 1.0000x reference)
#include <cuda_runtime.h>
#include <math.h>

#define S_TOK 5376
#define DIM   1536
#define NH    12
#define HD    128
#define NF    21
#define IMG   256
#define WKV   3840   // 15 frames * 256 tokens
#define BM    64
#define BN    64

// -------- scratch (device-global; no allocation allowed) --------
__device__ float g_q[(size_t)S_TOK * DIM];
__device__ float g_k[(size_t)S_TOK * DIM];
__device__ float g_v[(size_t)S_TOK * DIM];
__device__ float g_attn[(size_t)S_TOK * DIM];

// ----------------------------------------------------------------
// SGEMM (NT): C[m][n] = sum_k A[m][k]*B[n][k] + bias[n]
// A: [M,K] row-major, B: [N,K] row-major. BM=BN=128, BK=8, 8x8/thread.
// M%128==0, N%128==0, K%8==0 (holds for all our shapes).
// ----------------------------------------------------------------
__global__ __launch_bounds__(256, 2) void sgemm_nt(
    const float* __restrict__ A, const float* __restrict__ B,
    const float* __restrict__ bias, float* __restrict__ C,
    int M, int N, int K)
{
    __shared__ float As[8][128];
    __shared__ float Bs[8][128];

    const int t  = threadIdx.x;
    const int m0 = blockIdx.y * 128;
    const int n0 = blockIdx.x * 128;
    const int tm = (t >> 4) << 3;   // 0..120
    const int tn = (t & 15) << 3;   // 0..120
    const int lr = t >> 1;          // 0..127
    const int lc = (t & 1) << 2;    // 0 or 4

    const float* Ap = A + (size_t)(m0 + lr) * K + lc;
    const float* Bp = B + (size_t)(n0 + lr) * K + lc;

    float acc[8][8];
    #pragma unroll
    for (int i = 0; i < 8; ++i)
        #pragma unroll
        for (int j = 0; j < 8; ++j) acc[i][j] = 0.f;

    for (int k0 = 0; k0 < K; k0 += 8) {
        float4 av = *(const float4*)(Ap + k0);
        float4 bv = *(const float4*)(Bp + k0);
        __syncthreads();
        As[lc + 0][lr] = av.x; As[lc + 1][lr] = av.y;
        As[lc + 2][lr] = av.z; As[lc + 3][lr] = av.w;
        Bs[lc + 0][lr] = bv.x; Bs[lc + 1][lr] = bv.y;
        Bs[lc + 2][lr] = bv.z; Bs[lc + 3][lr] = bv.w;
        __syncthreads();
        #pragma unroll
        for (int kk = 0; kk < 8; ++kk) {
            float a[8], b[8];
            *(float4*)&a[0] = *(const float4*)&As[kk][tm];
            *(float4*)&a[4] = *(const float4*)&As[kk][tm + 4];
            *(float4*)&b[0] = *(const float4*)&Bs[kk][tn];
            *(float4*)&b[4] = *(const float4*)&Bs[kk][tn + 4];
            #pragma unroll
            for (int i = 0; i < 8; ++i)
                #pragma unroll
                for (int j = 0; j < 8; ++j)
                    acc[i][j] += a[i] * b[j];
        }
    }

    #pragma unroll
    for (int i = 0; i < 8; ++i) {
        #pragma unroll
        for (int j = 0; j < 8; j += 4) {
            float4 o;
            o.x = acc[i][j + 0] + bias[n0 + tn + j + 0];
            o.y = acc[i][j + 1] + bias[n0 + tn + j + 1];
            o.z = acc[i][j + 2] + bias[n0 + tn + j + 2];
            o.w = acc[i][j + 3] + bias[n0 + tn + j + 3];
            *(float4*)&C[(size_t)(m0 + tm + i) * N + n0 + tn + j] = o;
        }
    }
}

// ----------------------------------------------------------------
// Fused RMSNorm (over full dim=1536) + RoPE (per-head, interleaved
// pairs) applied in-place to g_q and g_k. One block per token.
// ----------------------------------------------------------------
__global__ __launch_bounds__(256) void normrope_kernel(
    const float* __restrict__ gq, const float* __restrict__ gk,
    const float* __restrict__ freqs)
{
    const int tok = blockIdx.x;
    const int t   = threadIdx.x;
    float* qr = g_q + (size_t)tok * DIM;
    float* kr = g_k + (size_t)tok * DIM;

    __shared__ float red[16];
    __shared__ float s_scq, s_sck;

    float sq = 0.f, sk = 0.f;
    for (int i = t; i < DIM; i += 256) {
        float a = qr[i]; sq += a * a;
        float b = kr[i]; sk += b * b;
    }
    #pragma unroll
    for (int m = 16; m >= 1; m >>= 1) {
        sq += __shfl_xor_sync(0xffffffffu, sq, m);
        sk += __shfl_xor_sync(0xffffffffu, sk, m);
    }
    if ((t & 31) == 0) { red[t >> 5] = sq; red[8 + (t >> 5)] = sk; }
    __syncthreads();
    if (t == 0) {
        float a = 0.f, b = 0.f;
        #pragma unroll
        for (int w = 0; w < 8; ++w) { a += red[w]; b += red[8 + w]; }
        s_scq = rsqrtf(a * (1.f / DIM) + 1e-6f);
        s_sck = rsqrtf(b * (1.f / DIM) + 1e-6f);
    }
    __syncthreads();
    const float scq = s_scq, sck = s_sck;

    // 768 pairs (12 heads x 64 pairs), 3 per thread
    for (int p = t; p < DIM / 2; p += 256) {
        int hh = p >> 6, i = p & 63;
        int c0 = hh * HD + 2 * i;
        float fr = freqs[(size_t)tok * (HD / 2) + i];
        float cs = cosf(fr), sn = sinf(fr);
        float qe = qr[c0] * scq * gq[c0];
        float qo = qr[c0 + 1] * scq * gq[c0 + 1];
        qr[c0]     = qe * cs - qo * sn;
        qr[c0 + 1] = qe * sn + qo * cs;
        float ke = kr[c0] * sck * gk[c0];
        float ko = kr[c0 + 1] * sck * gk[c0 + 1];
        kr[c0]     = ke * cs - ko * sn;
        kr[c0 + 1] = ke * sn + ko * cs;
    }
}

// ----------------------------------------------------------------
// Sliding-window attention, flash style. Grid (4 mtiles, 21, 12).
// KV window per frame f is contiguous: [clip(f-7,0,6)*256, +3840).
// smem: QsT[128][68] (k-major, transposed), KsT[128][68], Vs[64][128],
//       Ss[64][68]. Thread t: ty=t/16 owns rows 4ty..4ty+3,
//       tx=t%16 owns score cols 4tx..4tx+3 and O d-cols tx+16c.
// ----------------------------------------------------------------
#define ATTN_SMEM_FLOATS (128*68 + 128*68 + 64*128 + 64*68)

__global__ __launch_bounds__(256) void attn_kernel()
{
    extern __shared__ float sm[];
    float* QsT = sm;                 // [128][68]
    float* KsT = QsT + 128 * 68;     // [128][68]
    float* Vs  = KsT + 128 * 68;     // [64][128]
    float* Ss  = Vs + 64 * 128;      // [64][68]

    const int t  = threadIdx.x;
    const int mt = blockIdx.x, f = blockIdx.y, h = blockIdx.z;
    const int q0 = f * IMG + mt * BM;
    int st = f - 7; st = st < 0 ? 0 : (st > 6 ? 6 : st);
    const int kbase = st * IMG;
    const int ty = t >> 4, tx = t & 15;
    const float scale = 0.08838834764831845f;  // 1/sqrt(128)

    // load Q tile transposed (k-major) with scale folded in
    for (int i = t; i < BM * (HD / 4); i += 256) {
        int r = i >> 5, c4 = (i & 31) << 2;
        float4 qv = *(const float4*)&g_q[(size_t)(q0 + r) * DIM + h * HD + c4];
        QsT[(c4 + 0) * 68 + r] = qv.x * scale;
        QsT[(c4 + 1) * 68 + r] = qv.y * scale;
        QsT[(c4 + 2) * 68 + r] = qv.z * scale;
        QsT[(c4 + 3) * 68 + r] = qv.w * scale;
    }

    float Mi[4], Li[4], O[4][8];
    #pragma unroll
    for (int i = 0; i < 4; ++i) {
        Mi[i] = -INFINITY; Li[i] = 0.f;
        #pragma unroll
        for (int c = 0; c < 8; ++c) O[i][c] = 0.f;
    }

    for (int c = 0; c < WKV / BN; ++c) {
        __syncthreads();   // protect KsT/Vs/Ss from previous iteration readers
        const int kb = kbase + c * BN;
        for (int i = t; i < BN * (HD / 4); i += 256) {
            int r = i >> 5, c4 = (i & 31) << 2;
            float4 kv = *(const float4*)&g_k[(size_t)(kb + r) * DIM + h * HD + c4];
            KsT[(c4 + 0) * 68 + r] = kv.x;
            KsT[(c4 + 1) * 68 + r] = kv.y;
            KsT[(c4 + 2) * 68 + r] = kv.z;
            KsT[(c4 + 3) * 68 + r] = kv.w;
            float4 vv = *(const float4*)&g_v[(size_t)(kb + r) * DIM + h * HD + c4];
            *(float4*)&Vs[r * HD + c4] = vv;
        }
        __syncthreads();

        // scores: acc[i][j] = S[4ty+i][4tx+j]
        float acc[4][4];
        #pragma unroll
        for (int i = 0; i < 4; ++i)
            #pragma unroll
            for (int j = 0; j < 4; ++j) acc[i][j] = 0.f;

        #pragma unroll 8
        for (int k = 0; k < HD; ++k) {
            float4 qv = *(const float4*)&QsT[k * 68 + (ty << 2)];
            float4 kv = *(const float4*)&KsT[k * 68 + (tx << 2)];
            acc[0][0] += qv.x * kv.x; acc[0][1] += qv.x * kv.y;
            acc[0][2] += qv.x * kv.z; acc[0][3] += qv.x * kv.w;
            acc[1][0] += qv.y * kv.x; acc[1][1] += qv.y * kv.y;
            acc[1][2] += qv.y * kv.z; acc[1][3] += qv.y * kv.w;
            acc[2][0] += qv.z * kv.x; acc[2][1] += qv.z * kv.y;
            acc[2][2] += qv.z * kv.z; acc[2][3] += qv.z * kv.w;
            acc[3][0] += qv.w * kv.x; acc[3][1] += qv.w * kv.y;
            acc[3][2] += qv.w * kv.z; acc[3][3] += qv.w * kv.w;
        }

        // online softmax per owned row; 16 threads of a ty-group agree via shfl
        #pragma unroll
        for (int i = 0; i < 4; ++i) {
            float cm = fmaxf(fmaxf(acc[i][0], acc[i][1]), fmaxf(acc[i][2], acc[i][3]));
            cm = fmaxf(cm, __shfl_xor_sync(0xffffffffu, cm, 1, 16));
            cm = fmaxf(cm, __shfl_xor_sync(0xffffffffu, cm, 2, 16));
            cm = fmaxf(cm, __shfl_xor_sync(0xffffffffu, cm, 4, 16));
            cm = fmaxf(cm, __shfl_xor_sync(0xffffffffu, cm, 8, 16));
            float Mn = fmaxf(Mi[i], cm);
            float al = expf(Mi[i] - Mn);
            Mi[i] = Mn;
            float4 p;
            p.x = expf(acc[i][0] - Mn);
            p.y = expf(acc[i][1] - Mn);
            p.z = expf(acc[i][2] - Mn);
            p.w = expf(acc[i][3] - Mn);
            float rs = p.x + p.y + p.z + p.w;
            rs += __shfl_xor_sync(0xffffffffu, rs, 1, 16);
            rs += __shfl_xor_sync(0xffffffffu, rs, 2, 16);
            rs += __shfl_xor_sync(0xffffffffu, rs, 4, 16);
            rs += __shfl_xor_sync(0xffffffffu, rs, 8, 16);
            Li[i] = Li[i] * al + rs;
            #pragma unroll
            for (int cc = 0; cc < 8; ++cc) O[i][cc] *= al;
            *(float4*)&Ss[(4 * ty + i) * 68 + (tx << 2)] = p;
        }
        __syncthreads();

        // O += P @ V   (thread: 4 rows x 8 d-cols, d-cols tx+16*cc)
        #pragma unroll 4
        for (int j = 0; j < BN; ++j) {
            float pv0 = Ss[(4 * ty + 0) * 68 + j];
            float pv1 = Ss[(4 * ty + 1) * 68 + j];
            float pv2 = Ss[(4 * ty + 2) * 68 + j];
            float pv3 = Ss[(4 * ty + 3) * 68 + j];
            #pragma unroll
            for (int cc = 0; cc < 8; ++cc) {
                float vv = Vs[j * HD + tx + (cc << 4)];
                O[0][cc] += pv0 * vv;
                O[1][cc] += pv1 * vv;
                O[2][cc] += pv2 * vv;
                O[3][cc] += pv3 * vv;
            }
        }
    }

    #pragma unroll
    for (int i = 0; i < 4; ++i) {
        float inv = 1.f / Li[i];
        int row = q0 + 4 * ty + i;
        #pragma unroll
        for (int cc = 0; cc < 8; ++cc) {
            g_attn[(size_t)row * DIM + h * HD + tx + (cc << 4)] = O[i][cc] * inv;
        }
    }
}

// ----------------------------------------------------------------
extern "C" void kernel_launch(void* const* d_in, const int* in_sizes, int n_in,
                              void* d_out, int out_size)
{
    const float* x     = (const float*)d_in[0];
    const float* freqs = (const float*)d_in[1];
    const float* Wq    = (const float*)d_in[2];
    const float* bq    = (const float*)d_in[3];
    const float* Wk    = (const float*)d_in[4];
    const float* bk    = (const float*)d_in[5];
    const float* Wv    = (const float*)d_in[6];
    const float* bv    = (const float*)d_in[7];
    const float* Wo    = (const float*)d_in[8];
    const float* bo    = (const float*)d_in[9];
    const float* gq    = (const float*)d_in[10];
    const float* gk    = (const float*)d_in[11];
    float* out = (float*)d_out;

    void *pq, *pk, *pv, *pa;
    cudaGetSymbolAddress(&pq, g_q);
    cudaGetSymbolAddress(&pk, g_k);
    cudaGetSymbolAddress(&pv, g_v);
    cudaGetSymbolAddress(&pa, g_attn);

    dim3 gg(DIM / 128, S_TOK / 128);  // (12, 42)
    sgemm_nt<<<gg, 256>>>(x, Wq, bq, (float*)pq, S_TOK, DIM, DIM);
    sgemm_nt<<<gg, 256>>>(x, Wk, bk, (float*)pk, S_TOK, DIM, DIM);
    sgemm_nt<<<gg, 256>>>(x, Wv, bv, (float*)pv, S_TOK, DIM, DIM);

    normrope_kernel<<<S_TOK, 256>>>(gq, gk, freqs);

    static_assert(ATTN_SMEM_FLOATS * 4 < 227 * 1024, "smem");
    cudaFuncSetAttribute(attn_kernel, cudaFuncAttributeMaxDynamicSharedMemorySize,
                         ATTN_SMEM_FLOATS * 4);
    attn_kernel<<<dim3(IMG / BM, NF, NH), 256, ATTN_SMEM_FLOATS * 4>>>();

    sgemm_nt<<<gg, 256>>>((const float*)pa, Wo, bo, out, S_TOK, DIM, DIM);
}

// round 4
// speedup vs baseline: 1.3500x; 1.3500x over previous
#include <cuda_runtime.h>
#include <math.h>
#include <stdint.h>

#define S_TOK 5376
#define DIM   1536
#define NH    12
#define HD    128
#define NF    21
#define IMG   256
#define WKV   3840
#define BM    64
#define BN    64

// -------- scratch (device-global; no allocation allowed) --------
__device__ float g_q[(size_t)S_TOK * DIM];
__device__ float g_k[(size_t)S_TOK * DIM];
__device__ float g_v[(size_t)S_TOK * DIM];
__device__ float g_attn[(size_t)S_TOK * DIM];

__device__ __forceinline__ uint32_t f2tf(float x) {
    uint32_t r;
    asm("cvt.rna.tf32.f32 %0, %1;" : "=r"(r) : "f"(x));
    return r;
}

#define MMA_TF32(c, a, b) \
    asm volatile("mma.sync.aligned.m16n8k8.row.col.f32.tf32.tf32.f32 " \
                 "{%0,%1,%2,%3}, {%4,%5,%6,%7}, {%8,%9}, {%0,%1,%2,%3};" \
                 : "+f"((c)[0]), "+f"((c)[1]), "+f"((c)[2]), "+f"((c)[3]) \
                 : "r"((a)[0]), "r"((a)[1]), "r"((a)[2]), "r"((a)[3]), \
                   "r"((b)[0]), "r"((b)[1]))

// ================= tf32 mma.sync GEMM (NT) =======================
// C[m][n] = sum_k A[m][k]*B[n][k] + bias[n]
// CTA tile 128x128, K-chunk 32, 8 warps (2x4), warp tile 64x32.
#define GBM 128
#define GBN 128
#define GBK 32
#define LDST 36                       // smem row stride (words), conflict-free
#define GTILE (GBM * LDST)            // words per A (or B) buffer
#define GEMM_SMEM (4 * GTILE * 4)     // 2 bufs x (A+B) x 4B = 73728

__global__ __launch_bounds__(256) void tf32_gemm_nt(
    const float* __restrict__ A, const float* __restrict__ B,
    const float* __restrict__ bias, float* __restrict__ C,
    int M, int N, int K)
{
    extern __shared__ uint32_t sm[];
    uint32_t* As = sm;                // [2][GTILE]
    uint32_t* Bs = sm + 2 * GTILE;    // [2][GTILE]

    const int t    = threadIdx.x;
    const int lane = t & 31;
    const int wid  = t >> 5;
    const int m0   = blockIdx.y * GBM;
    const int n0   = blockIdx.x * GBN;
    const int wm   = (wid & 1) * 64;  // warp m-offset in tile
    const int wn   = (wid >> 1) * 32; // warp n-offset in tile
    const int fr   = lane >> 2;       // fragment row 0..7
    const int fc   = lane & 3;        // fragment col 0..3

    float acc[4][4][4];
    #pragma unroll
    for (int mi = 0; mi < 4; ++mi)
        #pragma unroll
        for (int ni = 0; ni < 4; ++ni)
            #pragma unroll
            for (int r = 0; r < 4; ++r) acc[mi][ni][r] = 0.f;

    auto load_tile = [&](int buf, int k0) {
        #pragma unroll
        for (int i = 0; i < 4; ++i) {
            int idx = t + i * 256;        // 0..1023
            int row = idx >> 3, f4 = idx & 7;
            float4 av = *(const float4*)(A + (size_t)(m0 + row) * K + k0 + f4 * 4);
            *(uint4*)&As[buf * GTILE + row * LDST + f4 * 4] =
                make_uint4(f2tf(av.x), f2tf(av.y), f2tf(av.z), f2tf(av.w));
            float4 bv = *(const float4*)(B + (size_t)(n0 + row) * K + k0 + f4 * 4);
            *(uint4*)&Bs[buf * GTILE + row * LDST + f4 * 4] =
                make_uint4(f2tf(bv.x), f2tf(bv.y), f2tf(bv.z), f2tf(bv.w));
        }
    };

    const int NCH = K / GBK;           // 48
    load_tile(0, 0);
    __syncthreads();

    for (int c = 0; c < NCH; ++c) {
        const int buf = c & 1;
        if (c + 1 < NCH) load_tile((c + 1) & 1, (c + 1) * GBK);

        const uint32_t* Ab = &As[buf * GTILE];
        const uint32_t* Bb = &Bs[buf * GTILE];
        #pragma unroll
        for (int k8 = 0; k8 < 4; ++k8) {
            const int kc = k8 * 8;
            uint32_t af[4][4];
            #pragma unroll
            for (int mi = 0; mi < 4; ++mi) {
                const uint32_t* p = Ab + (wm + mi * 16) * LDST + kc;
                af[mi][0] = p[fr * LDST + fc];
                af[mi][1] = p[(fr + 8) * LDST + fc];
                af[mi][2] = p[fr * LDST + fc + 4];
                af[mi][3] = p[(fr + 8) * LDST + fc + 4];
            }
            uint32_t bf[4][2];
            #pragma unroll
            for (int ni = 0; ni < 4; ++ni) {
                const uint32_t* p = Bb + (wn + ni * 8 + fr) * LDST + kc + fc;
                bf[ni][0] = p[0];
                bf[ni][1] = p[4];
            }
            #pragma unroll
            for (int mi = 0; mi < 4; ++mi)
                #pragma unroll
                for (int ni = 0; ni < 4; ++ni)
                    MMA_TF32(acc[mi][ni], af[mi], bf[ni]);
        }
        __syncthreads();
    }

    // epilogue: c0,c1 -> (row, col..col+1), c2,c3 -> (row+8, col..col+1)
    const int c2 = fc * 2;
    #pragma unroll
    for (int mi = 0; mi < 4; ++mi) {
        #pragma unroll
        for (int ni = 0; ni < 4; ++ni) {
            int row = m0 + wm + mi * 16 + fr;
            int col = n0 + wn + ni * 8 + c2;
            float b0 = bias[col], b1 = bias[col + 1];
            float2 lo = make_float2(acc[mi][ni][0] + b0, acc[mi][ni][1] + b1);
            float2 hi = make_float2(acc[mi][ni][2] + b0, acc[mi][ni][3] + b1);
            *(float2*)&C[(size_t)row * N + col] = lo;
            *(float2*)&C[(size_t)(row + 8) * N + col] = hi;
        }
    }
}

// ----------------------------------------------------------------
// Fused RMSNorm + RoPE (unchanged)
// ----------------------------------------------------------------
__global__ __launch_bounds__(256) void normrope_kernel(
    const float* __restrict__ gq, const float* __restrict__ gk,
    const float* __restrict__ freqs)
{
    const int tok = blockIdx.x;
    const int t   = threadIdx.x;
    float* qr = g_q + (size_t)tok * DIM;
    float* kr = g_k + (size_t)tok * DIM;

    __shared__ float red[16];
    __shared__ float s_scq, s_sck;

    float sq = 0.f, sk = 0.f;
    for (int i = t; i < DIM; i += 256) {
        float a = qr[i]; sq += a * a;
        float b = kr[i]; sk += b * b;
    }
    #pragma unroll
    for (int m = 16; m >= 1; m >>= 1) {
        sq += __shfl_xor_sync(0xffffffffu, sq, m);
        sk += __shfl_xor_sync(0xffffffffu, sk, m);
    }
    if ((t & 31) == 0) { red[t >> 5] = sq; red[8 + (t >> 5)] = sk; }
    __syncthreads();
    if (t == 0) {
        float a = 0.f, b = 0.f;
        #pragma unroll
        for (int w = 0; w < 8; ++w) { a += red[w]; b += red[8 + w]; }
        s_scq = rsqrtf(a * (1.f / DIM) + 1e-6f);
        s_sck = rsqrtf(b * (1.f / DIM) + 1e-6f);
    }
    __syncthreads();
    const float scq = s_scq, sck = s_sck;

    for (int p = t; p < DIM / 2; p += 256) {
        int hh = p >> 6, i = p & 63;
        int c0 = hh * HD + 2 * i;
        float fr = freqs[(size_t)tok * (HD / 2) + i];
        float cs = cosf(fr), sn = sinf(fr);
        float qe = qr[c0] * scq * gq[c0];
        float qo = qr[c0 + 1] * scq * gq[c0 + 1];
        qr[c0]     = qe * cs - qo * sn;
        qr[c0 + 1] = qe * sn + qo * cs;
        float ke = kr[c0] * sck * gk[c0];
        float ko = kr[c0 + 1] * sck * gk[c0 + 1];
        kr[c0]     = ke * cs - ko * sn;
        kr[c0 + 1] = ke * sn + ko * cs;
    }
}

// ----------------------------------------------------------------
// Sliding-window attention (unchanged from round 1)
// ----------------------------------------------------------------
#define ATTN_SMEM_FLOATS (128*68 + 128*68 + 64*128 + 64*68)

__global__ __launch_bounds__(256) void attn_kernel()
{
    extern __shared__ float smf[];
    float* QsT = smf;
    float* KsT = QsT + 128 * 68;
    float* Vs  = KsT + 128 * 68;
    float* Ss  = Vs + 64 * 128;

    const int t  = threadIdx.x;
    const int mt = blockIdx.x, f = blockIdx.y, h = blockIdx.z;
    const int q0 = f * IMG + mt * BM;
    int st = f - 7; st = st < 0 ? 0 : (st > 6 ? 6 : st);
    const int kbase = st * IMG;
    const int ty = t >> 4, tx = t & 15;
    const float scale = 0.08838834764831845f;

    for (int i = t; i < BM * (HD / 4); i += 256) {
        int r = i >> 5, c4 = (i & 31) << 2;
        float4 qv = *(const float4*)&g_q[(size_t)(q0 + r) * DIM + h * HD + c4];
        QsT[(c4 + 0) * 68 + r] = qv.x * scale;
        QsT[(c4 + 1) * 68 + r] = qv.y * scale;
        QsT[(c4 + 2) * 68 + r] = qv.z * scale;
        QsT[(c4 + 3) * 68 + r] = qv.w * scale;
    }

    float Mi[4], Li[4], O[4][8];
    #pragma unroll
    for (int i = 0; i < 4; ++i) {
        Mi[i] = -INFINITY; Li[i] = 0.f;
        #pragma unroll
        for (int c = 0; c < 8; ++c) O[i][c] = 0.f;
    }

    for (int c = 0; c < WKV / BN; ++c) {
        __syncthreads();
        const int kb = kbase + c * BN;
        for (int i = t; i < BN * (HD / 4); i += 256) {
            int r = i >> 5, c4 = (i & 31) << 2;
            float4 kv = *(const float4*)&g_k[(size_t)(kb + r) * DIM + h * HD + c4];
            KsT[(c4 + 0) * 68 + r] = kv.x;
            KsT[(c4 + 1) * 68 + r] = kv.y;
            KsT[(c4 + 2) * 68 + r] = kv.z;
            KsT[(c4 + 3) * 68 + r] = kv.w;
            float4 vv = *(const float4*)&g_v[(size_t)(kb + r) * DIM + h * HD + c4];
            *(float4*)&Vs[r * HD + c4] = vv;
        }
        __syncthreads();

        float acc[4][4];
        #pragma unroll
        for (int i = 0; i < 4; ++i)
            #pragma unroll
            for (int j = 0; j < 4; ++j) acc[i][j] = 0.f;

        #pragma unroll 8
        for (int k = 0; k < HD; ++k) {
            float4 qv = *(const float4*)&QsT[k * 68 + (ty << 2)];
            float4 kv = *(const float4*)&KsT[k * 68 + (tx << 2)];
            acc[0][0] += qv.x * kv.x; acc[0][1] += qv.x * kv.y;
            acc[0][2] += qv.x * kv.z; acc[0][3] += qv.x * kv.w;
            acc[1][0] += qv.y * kv.x; acc[1][1] += qv.y * kv.y;
            acc[1][2] += qv.y * kv.z; acc[1][3] += qv.y * kv.w;
            acc[2][0] += qv.z * kv.x; acc[2][1] += qv.z * kv.y;
            acc[2][2] += qv.z * kv.z; acc[2][3] += qv.z * kv.w;
            acc[3][0] += qv.w * kv.x; acc[3][1] += qv.w * kv.y;
            acc[3][2] += qv.w * kv.z; acc[3][3] += qv.w * kv.w;
        }

        #pragma unroll
        for (int i = 0; i < 4; ++i) {
            float cm = fmaxf(fmaxf(acc[i][0], acc[i][1]), fmaxf(acc[i][2], acc[i][3]));
            cm = fmaxf(cm, __shfl_xor_sync(0xffffffffu, cm, 1, 16));
            cm = fmaxf(cm, __shfl_xor_sync(0xffffffffu, cm, 2, 16));
            cm = fmaxf(cm, __shfl_xor_sync(0xffffffffu, cm, 4, 16));
            cm = fmaxf(cm, __shfl_xor_sync(0xffffffffu, cm, 8, 16));
            float Mn = fmaxf(Mi[i], cm);
            float al = expf(Mi[i] - Mn);
            Mi[i] = Mn;
            float4 p;
            p.x = expf(acc[i][0] - Mn);
            p.y = expf(acc[i][1] - Mn);
            p.z = expf(acc[i][2] - Mn);
            p.w = expf(acc[i][3] - Mn);
            float rs = p.x + p.y + p.z + p.w;
            rs += __shfl_xor_sync(0xffffffffu, rs, 1, 16);
            rs += __shfl_xor_sync(0xffffffffu, rs, 2, 16);
            rs += __shfl_xor_sync(0xffffffffu, rs, 4, 16);
            rs += __shfl_xor_sync(0xffffffffu, rs, 8, 16);
            Li[i] = Li[i] * al + rs;
            #pragma unroll
            for (int cc = 0; cc < 8; ++cc) O[i][cc] *= al;
            *(float4*)&Ss[(4 * ty + i) * 68 + (tx << 2)] = p;
        }
        __syncthreads();

        #pragma unroll 4
        for (int j = 0; j < BN; ++j) {
            float pv0 = Ss[(4 * ty + 0) * 68 + j];
            float pv1 = Ss[(4 * ty + 1) * 68 + j];
            float pv2 = Ss[(4 * ty + 2) * 68 + j];
            float pv3 = Ss[(4 * ty + 3) * 68 + j];
            #pragma unroll
            for (int cc = 0; cc < 8; ++cc) {
                float vv = Vs[j * HD + tx + (cc << 4)];
                O[0][cc] += pv0 * vv;
                O[1][cc] += pv1 * vv;
                O[2][cc] += pv2 * vv;
                O[3][cc] += pv3 * vv;
            }
        }
    }

    #pragma unroll
    for (int i = 0; i < 4; ++i) {
        float inv = 1.f / Li[i];
        int row = q0 + 4 * ty + i;
        #pragma unroll
        for (int cc = 0; cc < 8; ++cc) {
            g_attn[(size_t)row * DIM + h * HD + tx + (cc << 4)] = O[i][cc] * inv;
        }
    }
}

// ----------------------------------------------------------------
extern "C" void kernel_launch(void* const* d_in, const int* in_sizes, int n_in,
                              void* d_out, int out_size)
{
    const float* x     = (const float*)d_in[0];
    const float* freqs = (const float*)d_in[1];
    const float* Wq    = (const float*)d_in[2];
    const float* bq    = (const float*)d_in[3];
    const float* Wk    = (const float*)d_in[4];
    const float* bk    = (const float*)d_in[5];
    const float* Wv    = (const float*)d_in[6];
    const float* bv    = (const float*)d_in[7];
    const float* Wo    = (const float*)d_in[8];
    const float* bo    = (const float*)d_in[9];
    const float* gq    = (const float*)d_in[10];
    const float* gk    = (const float*)d_in[11];
    float* out = (float*)d_out;

    void *pq, *pk, *pv, *pa;
    cudaGetSymbolAddress(&pq, g_q);
    cudaGetSymbolAddress(&pk, g_k);
    cudaGetSymbolAddress(&pv, g_v);
    cudaGetSymbolAddress(&pa, g_attn);

    cudaFuncSetAttribute(tf32_gemm_nt, cudaFuncAttributeMaxDynamicSharedMemorySize, GEMM_SMEM);

    dim3 gg(DIM / 128, S_TOK / 128);  // (12, 42)
    tf32_gemm_nt<<<gg, 256, GEMM_SMEM>>>(x, Wq, bq, (float*)pq, S_TOK, DIM, DIM);
    tf32_gemm_nt<<<gg, 256, GEMM_SMEM>>>(x, Wk, bk, (float*)pk, S_TOK, DIM, DIM);
    tf32_gemm_nt<<<gg, 256, GEMM_SMEM>>>(x, Wv, bv, (float*)pv, S_TOK, DIM, DIM);

    normrope_kernel<<<S_TOK, 256>>>(gq, gk, freqs);

    cudaFuncSetAttribute(attn_kernel, cudaFuncAttributeMaxDynamicSharedMemorySize,
                         ATTN_SMEM_FLOATS * 4);
    attn_kernel<<<dim3(IMG / BM, NF, NH), 256, ATTN_SMEM_FLOATS * 4>>>();

    tf32_gemm_nt<<<gg, 256, GEMM_SMEM>>>((const float*)pa, Wo, bo, out, S_TOK, DIM, DIM);
}

// round 5
// speedup vs baseline: 2.9085x; 2.1543x over previous
#include <cuda_runtime.h>
#include <math.h>
#include <stdint.h>

#define S_TOK 5376
#define DIM   1536
#define NH    12
#define HD    128
#define NF    21
#define IMG   256
#define WKV   3840

// -------- scratch (device-global; no allocation allowed) --------
__device__ float g_q[(size_t)S_TOK * DIM];
__device__ float g_k[(size_t)S_TOK * DIM];
__device__ float g_v[(size_t)S_TOK * DIM];
__device__ float g_attn[(size_t)S_TOK * DIM];

__device__ __forceinline__ uint32_t f2tf(float x) {
    uint32_t r;
    asm("cvt.rna.tf32.f32 %0, %1;" : "=r"(r) : "f"(x));
    return r;
}

#define MMA_TF32(c, a, b) \
    asm volatile("mma.sync.aligned.m16n8k8.row.col.f32.tf32.tf32.f32 " \
                 "{%0,%1,%2,%3}, {%4,%5,%6,%7}, {%8,%9}, {%0,%1,%2,%3};" \
                 : "+f"((c)[0]), "+f"((c)[1]), "+f"((c)[2]), "+f"((c)[3]) \
                 : "r"((a)[0]), "r"((a)[1]), "r"((a)[2]), "r"((a)[3]), \
                   "r"((b)[0]), "r"((b)[1]))

// ================= tf32 mma.sync GEMM (NT) =======================
#define GBM 128
#define GBN 128
#define GBK 32
#define LDST 36
#define GTILE (GBM * LDST)
#define GEMM_SMEM (4 * GTILE * 4)

__global__ __launch_bounds__(256) void tf32_gemm_nt(
    const float* __restrict__ A, const float* __restrict__ B,
    const float* __restrict__ bias, float* __restrict__ C,
    int M, int N, int K)
{
    extern __shared__ uint32_t sm[];
    uint32_t* As = sm;
    uint32_t* Bs = sm + 2 * GTILE;

    const int t    = threadIdx.x;
    const int lane = t & 31;
    const int wid  = t >> 5;
    const int m0   = blockIdx.y * GBM;
    const int n0   = blockIdx.x * GBN;
    const int wm   = (wid & 1) * 64;
    const int wn   = (wid >> 1) * 32;
    const int fr   = lane >> 2;
    const int fc   = lane & 3;

    float acc[4][4][4];
    #pragma unroll
    for (int mi = 0; mi < 4; ++mi)
        #pragma unroll
        for (int ni = 0; ni < 4; ++ni)
            #pragma unroll
            for (int r = 0; r < 4; ++r) acc[mi][ni][r] = 0.f;

    auto load_tile = [&](int buf, int k0) {
        #pragma unroll
        for (int i = 0; i < 4; ++i) {
            int idx = t + i * 256;
            int row = idx >> 3, f4 = idx & 7;
            float4 av = *(const float4*)(A + (size_t)(m0 + row) * K + k0 + f4 * 4);
            *(uint4*)&As[buf * GTILE + row * LDST + f4 * 4] =
                make_uint4(f2tf(av.x), f2tf(av.y), f2tf(av.z), f2tf(av.w));
            float4 bv = *(const float4*)(B + (size_t)(n0 + row) * K + k0 + f4 * 4);
            *(uint4*)&Bs[buf * GTILE + row * LDST + f4 * 4] =
                make_uint4(f2tf(bv.x), f2tf(bv.y), f2tf(bv.z), f2tf(bv.w));
        }
    };

    const int NCH = K / GBK;
    load_tile(0, 0);
    __syncthreads();

    for (int c = 0; c < NCH; ++c) {
        const int buf = c & 1;
        if (c + 1 < NCH) load_tile((c + 1) & 1, (c + 1) * GBK);

        const uint32_t* Ab = &As[buf * GTILE];
        const uint32_t* Bb = &Bs[buf * GTILE];
        #pragma unroll
        for (int k8 = 0; k8 < 4; ++k8) {
            const int kc = k8 * 8;
            uint32_t af[4][4];
            #pragma unroll
            for (int mi = 0; mi < 4; ++mi) {
                const uint32_t* p = Ab + (wm + mi * 16) * LDST + kc;
                af[mi][0] = p[fr * LDST + fc];
                af[mi][1] = p[(fr + 8) * LDST + fc];
                af[mi][2] = p[fr * LDST + fc + 4];
                af[mi][3] = p[(fr + 8) * LDST + fc + 4];
            }
            uint32_t bf[4][2];
            #pragma unroll
            for (int ni = 0; ni < 4; ++ni) {
                const uint32_t* p = Bb + (wn + ni * 8 + fr) * LDST + kc + fc;
                bf[ni][0] = p[0];
                bf[ni][1] = p[4];
            }
            #pragma unroll
            for (int mi = 0; mi < 4; ++mi)
                #pragma unroll
                for (int ni = 0; ni < 4; ++ni)
                    MMA_TF32(acc[mi][ni], af[mi], bf[ni]);
        }
        __syncthreads();
    }

    const int c2 = fc * 2;
    #pragma unroll
    for (int mi = 0; mi < 4; ++mi) {
        #pragma unroll
        for (int ni = 0; ni < 4; ++ni) {
            int row = m0 + wm + mi * 16 + fr;
            int col = n0 + wn + ni * 8 + c2;
            float b0 = bias[col], b1 = bias[col + 1];
            float2 lo = make_float2(acc[mi][ni][0] + b0, acc[mi][ni][1] + b1);
            float2 hi = make_float2(acc[mi][ni][2] + b0, acc[mi][ni][3] + b1);
            *(float2*)&C[(size_t)row * N + col] = lo;
            *(float2*)&C[(size_t)(row + 8) * N + col] = hi;
        }
    }
}

// ----------------------------------------------------------------
// Fused RMSNorm + RoPE (unchanged)
// ----------------------------------------------------------------
__global__ __launch_bounds__(256) void normrope_kernel(
    const float* __restrict__ gq, const float* __restrict__ gk,
    const float* __restrict__ freqs)
{
    const int tok = blockIdx.x;
    const int t   = threadIdx.x;
    float* qr = g_q + (size_t)tok * DIM;
    float* kr = g_k + (size_t)tok * DIM;

    __shared__ float red[16];
    __shared__ float s_scq, s_sck;

    float sq = 0.f, sk = 0.f;
    for (int i = t; i < DIM; i += 256) {
        float a = qr[i]; sq += a * a;
        float b = kr[i]; sk += b * b;
    }
    #pragma unroll
    for (int m = 16; m >= 1; m >>= 1) {
        sq += __shfl_xor_sync(0xffffffffu, sq, m);
        sk += __shfl_xor_sync(0xffffffffu, sk, m);
    }
    if ((t & 31) == 0) { red[t >> 5] = sq; red[8 + (t >> 5)] = sk; }
    __syncthreads();
    if (t == 0) {
        float a = 0.f, b = 0.f;
        #pragma unroll
        for (int w = 0; w < 8; ++w) { a += red[w]; b += red[8 + w]; }
        s_scq = rsqrtf(a * (1.f / DIM) + 1e-6f);
        s_sck = rsqrtf(b * (1.f / DIM) + 1e-6f);
    }
    __syncthreads();
    const float scq = s_scq, sck = s_sck;

    for (int p = t; p < DIM / 2; p += 256) {
        int hh = p >> 6, i = p & 63;
        int c0 = hh * HD + 2 * i;
        float fr = freqs[(size_t)tok * (HD / 2) + i];
        float cs = cosf(fr), sn = sinf(fr);
        float qe = qr[c0] * scq * gq[c0];
        float qo = qr[c0 + 1] * scq * gq[c0 + 1];
        qr[c0]     = qe * cs - qo * sn;
        qr[c0 + 1] = qe * sn + qo * cs;
        float ke = kr[c0] * sck * gk[c0];
        float ko = kr[c0 + 1] * sck * gk[c0 + 1];
        kr[c0]     = ke * cs - ko * sn;
        kr[c0 + 1] = ke * sn + ko * cs;
    }
}

// ================= tensor-core flash attention ===================
#define ABM 128
#define ABN 64
#define KST 132
#define VST 68
#define PST 68
#define ATTN_SMEM ((64 * KST + 128 * VST + 128 * PST) * 4)

__global__ __launch_bounds__(256) void attn_mma_kernel()
{
    extern __shared__ float smf[];
    float* Ks  = smf;                       // [64][KST]  (tok, k)
    float* VsT = Ks + 64 * KST;             // [128][VST] (d, tok swizzled)
    float* Ps  = VsT + 128 * VST;           // [128][PST] (q, tok)

    const int t    = threadIdx.x;
    const int lane = t & 31;
    const int w    = t >> 5;
    const int fr   = lane >> 2;
    const int fc   = lane & 3;
    const int mt = blockIdx.x, f = blockIdx.y, h = blockIdx.z;
    const int q0 = f * IMG + mt * ABM;
    int st = f - 7; st = st < 0 ? 0 : (st > 6 ? 6 : st);
    const int kbase = st * IMG;
    const float scale = 0.08838834764831845f;  // 1/sqrt(128)

    // ---- preload Q as A-fragments (scale folded) ----
    uint32_t qf[16][4];
    {
        const float* Q0 = g_q + (size_t)(q0 + 16 * w + fr) * DIM + h * HD;
        const float* Q8 = Q0 + 8 * DIM;
        #pragma unroll
        for (int ks = 0; ks < 16; ++ks) {
            const int kc = ks * 8;
            qf[ks][0] = f2tf(Q0[kc + fc] * scale);
            qf[ks][1] = f2tf(Q8[kc + fc] * scale);
            qf[ks][2] = f2tf(Q0[kc + fc + 4] * scale);
            qf[ks][3] = f2tf(Q8[kc + fc + 4] * scale);
        }
    }

    float o[16][4];
    #pragma unroll
    for (int nf = 0; nf < 16; ++nf)
        #pragma unroll
        for (int r = 0; r < 4; ++r) o[nf][r] = 0.f;
    float Mlo = -INFINITY, Mhi = -INFINITY, Llo = 0.f, Lhi = 0.f;

    const int prow0 = (16 * w + fr) * PST;
    const int prow8 = (16 * w + fr + 8) * PST;

    for (int c = 0; c < WKV / ABN; ++c) {
        __syncthreads();
        const int kb = kbase + c * ABN;
        // stage K [64][128] and V^T [128][64] (both tf32); 64x32 float4 each
        #pragma unroll
        for (int i = 0; i < 8; ++i) {
            int idx = t + i * 256;              // 0..2047
            int row = idx >> 5, c4 = (idx & 31) << 2;
            float4 kv = *(const float4*)&g_k[(size_t)(kb + row) * DIM + h * HD + c4];
            *(uint4*)&Ks[row * KST + c4] =
                make_uint4(f2tf(kv.x), f2tf(kv.y), f2tf(kv.z), f2tf(kv.w));
            float4 vv = *(const float4*)&g_v[(size_t)(kb + row) * DIM + h * HD + c4];
            int col = (row + (c4 >> 2)) & 63;   // rotation swizzle
            VsT[(c4 + 0) * VST + col] = __uint_as_float(f2tf(vv.x));
            VsT[(c4 + 1) * VST + col] = __uint_as_float(f2tf(vv.y));
            VsT[(c4 + 2) * VST + col] = __uint_as_float(f2tf(vv.z));
            VsT[(c4 + 3) * VST + col] = __uint_as_float(f2tf(vv.w));
        }
        __syncthreads();

        // ---- S = Q K^T (16 x 64 per warp) ----
        float s[8][4];
        #pragma unroll
        for (int nf = 0; nf < 8; ++nf)
            #pragma unroll
            for (int r = 0; r < 4; ++r) s[nf][r] = 0.f;

        #pragma unroll
        for (int ks = 0; ks < 16; ++ks) {
            const int kc = ks * 8;
            #pragma unroll
            for (int nf = 0; nf < 8; ++nf) {
                const float* p = &Ks[(8 * nf + fr) * KST + kc + fc];
                uint32_t b[2] = { __float_as_uint(p[0]), __float_as_uint(p[4]) };
                MMA_TF32(s[nf], qf[ks], b);
            }
        }

        // ---- online softmax (warp-private rows) ----
        float mlo = -INFINITY, mhi = -INFINITY;
        #pragma unroll
        for (int nf = 0; nf < 8; ++nf) {
            mlo = fmaxf(mlo, fmaxf(s[nf][0], s[nf][1]));
            mhi = fmaxf(mhi, fmaxf(s[nf][2], s[nf][3]));
        }
        mlo = fmaxf(mlo, __shfl_xor_sync(0xffffffffu, mlo, 1));
        mlo = fmaxf(mlo, __shfl_xor_sync(0xffffffffu, mlo, 2));
        mhi = fmaxf(mhi, __shfl_xor_sync(0xffffffffu, mhi, 1));
        mhi = fmaxf(mhi, __shfl_xor_sync(0xffffffffu, mhi, 2));
        const float Mnlo = fmaxf(Mlo, mlo), Mnhi = fmaxf(Mhi, mhi);
        const float alo = __expf(Mlo - Mnlo), ahi = __expf(Mhi - Mnhi);
        Mlo = Mnlo; Mhi = Mnhi;

        float rlo = 0.f, rhi = 0.f;
        #pragma unroll
        for (int nf = 0; nf < 8; ++nf) {
            s[nf][0] = __uint_as_float(f2tf(__expf(s[nf][0] - Mnlo)));
            s[nf][1] = __uint_as_float(f2tf(__expf(s[nf][1] - Mnlo)));
            s[nf][2] = __uint_as_float(f2tf(__expf(s[nf][2] - Mnhi)));
            s[nf][3] = __uint_as_float(f2tf(__expf(s[nf][3] - Mnhi)));
            rlo += s[nf][0] + s[nf][1];
            rhi += s[nf][2] + s[nf][3];
        }
        rlo += __shfl_xor_sync(0xffffffffu, rlo, 1);
        rlo += __shfl_xor_sync(0xffffffffu, rlo, 2);
        rhi += __shfl_xor_sync(0xffffffffu, rhi, 1);
        rhi += __shfl_xor_sync(0xffffffffu, rhi, 2);
        Llo = Llo * alo + rlo;
        Lhi = Lhi * ahi + rhi;
        #pragma unroll
        for (int nf = 0; nf < 16; ++nf) {
            o[nf][0] *= alo; o[nf][1] *= alo;
            o[nf][2] *= ahi; o[nf][3] *= ahi;
        }
        #pragma unroll
        for (int nf = 0; nf < 8; ++nf) {
            *(float2*)&Ps[prow0 + 8 * nf + 2 * fc] = make_float2(s[nf][0], s[nf][1]);
            *(float2*)&Ps[prow8 + 8 * nf + 2 * fc] = make_float2(s[nf][2], s[nf][3]);
        }
        __syncwarp();

        // ---- O += P V ----
        #pragma unroll
        for (int k2 = 0; k2 < 8; ++k2) {
            const int kc = k2 * 8;
            uint32_t a[4];
            a[0] = __float_as_uint(Ps[prow0 + kc + fc]);
            a[1] = __float_as_uint(Ps[prow8 + kc + fc]);
            a[2] = __float_as_uint(Ps[prow0 + kc + fc + 4]);
            a[3] = __float_as_uint(Ps[prow8 + kc + fc + 4]);
            #pragma unroll
            for (int nf = 0; nf < 16; ++nf) {
                const int d = 8 * nf + fr;
                const int rot = d >> 2;
                uint32_t b[2];
                b[0] = __float_as_uint(VsT[d * VST + ((kc + fc + rot) & 63)]);
                b[1] = __float_as_uint(VsT[d * VST + ((kc + fc + 4 + rot) & 63)]);
                MMA_TF32(o[nf], a, b);
            }
        }
        __syncwarp();
    }

    // ---- epilogue ----
    const float il = 1.f / Llo, ih = 1.f / Lhi;
    const int row0 = q0 + 16 * w + fr;
    #pragma unroll
    for (int nf = 0; nf < 16; ++nf) {
        const int col = h * HD + 8 * nf + 2 * fc;
        *(float2*)&g_attn[(size_t)row0 * DIM + col] =
            make_float2(o[nf][0] * il, o[nf][1] * il);
        *(float2*)&g_attn[(size_t)(row0 + 8) * DIM + col] =
            make_float2(o[nf][2] * ih, o[nf][3] * ih);
    }
}

// ----------------------------------------------------------------
extern "C" void kernel_launch(void* const* d_in, const int* in_sizes, int n_in,
                              void* d_out, int out_size)
{
    const float* x     = (const float*)d_in[0];
    const float* freqs = (const float*)d_in[1];
    const float* Wq    = (const float*)d_in[2];
    const float* bq    = (const float*)d_in[3];
    const float* Wk    = (const float*)d_in[4];
    const float* bk    = (const float*)d_in[5];
    const float* Wv    = (const float*)d_in[6];
    const float* bv    = (const float*)d_in[7];
    const float* Wo    = (const float*)d_in[8];
    const float* bo    = (const float*)d_in[9];
    const float* gq    = (const float*)d_in[10];
    const float* gk    = (const float*)d_in[11];
    float* out = (float*)d_out;

    void *pq, *pk, *pv, *pa;
    cudaGetSymbolAddress(&pq, g_q);
    cudaGetSymbolAddress(&pk, g_k);
    cudaGetSymbolAddress(&pv, g_v);
    cudaGetSymbolAddress(&pa, g_attn);

    cudaFuncSetAttribute(tf32_gemm_nt, cudaFuncAttributeMaxDynamicSharedMemorySize, GEMM_SMEM);

    dim3 gg(DIM / 128, S_TOK / 128);
    tf32_gemm_nt<<<gg, 256, GEMM_SMEM>>>(x, Wq, bq, (float*)pq, S_TOK, DIM, DIM);
    tf32_gemm_nt<<<gg, 256, GEMM_SMEM>>>(x, Wk, bk, (float*)pk, S_TOK, DIM, DIM);
    tf32_gemm_nt<<<gg, 256, GEMM_SMEM>>>(x, Wv, bv, (float*)pv, S_TOK, DIM, DIM);

    normrope_kernel<<<S_TOK, 256>>>(gq, gk, freqs);

    cudaFuncSetAttribute(attn_mma_kernel, cudaFuncAttributeMaxDynamicSharedMemorySize, ATTN_SMEM);
    attn_mma_kernel<<<dim3(IMG / ABM, NF, NH), 256, ATTN_SMEM>>>();

    tf32_gemm_nt<<<gg, 256, GEMM_SMEM>>>((const float*)pa, Wo, bo, out, S_TOK, DIM, DIM);
}

// round 6
// speedup vs baseline: 2.9459x; 1.0129x over previous
#include <cuda_runtime.h>
#include <math.h>
#include <stdint.h>

#define S_TOK 5376
#define DIM   1536
#define NH    12
#define HD    128
#define NF    21
#define IMG   256
#define WKV   3840

// -------- scratch (device-global; no allocation allowed) --------
__device__ float g_q[(size_t)S_TOK * DIM];
__device__ float g_k[(size_t)S_TOK * DIM];
__device__ float g_v[(size_t)S_TOK * DIM];
__device__ float g_attn[(size_t)S_TOK * DIM];
__device__ float g_xtf[(size_t)S_TOK * DIM];
__device__ float g_wtf[(size_t)4 * DIM * DIM];

__device__ __forceinline__ uint32_t f2tf(float x) {
    uint32_t r;
    asm("cvt.rna.tf32.f32 %0, %1;" : "=r"(r) : "f"(x));
    return r;
}
__device__ __forceinline__ uint32_t smem_u32(const void* p) {
    uint32_t a;
    asm("{ .reg .u64 t; cvta.to.shared.u64 t, %1; cvt.u32.u64 %0, t; }" : "=r"(a) : "l"(p));
    return a;
}

#define MMA_TF32(c, a, b) \
    asm volatile("mma.sync.aligned.m16n8k8.row.col.f32.tf32.tf32.f32 " \
                 "{%0,%1,%2,%3}, {%4,%5,%6,%7}, {%8,%9}, {%0,%1,%2,%3};" \
                 : "+f"((c)[0]), "+f"((c)[1]), "+f"((c)[2]), "+f"((c)[3]) \
                 : "r"((a)[0]), "r"((a)[1]), "r"((a)[2]), "r"((a)[3]), \
                   "r"((b)[0]), "r"((b)[1]))

#define CP_ASYNC16(dst, src) \
    asm volatile("cp.async.cg.shared.global [%0], [%1], 16;" :: "r"(dst), "l"(src))
#define CP_COMMIT() asm volatile("cp.async.commit_group;" ::: "memory")
#define CP_WAIT0()  asm volatile("cp.async.wait_group 0;" ::: "memory")

// ---------------- tf32 pre-rounding pass -------------------------
__global__ __launch_bounds__(256) void tf32_round_kernel(
    const float4* __restrict__ in, float4* __restrict__ out, int n4)
{
    for (int i = blockIdx.x * blockDim.x + threadIdx.x; i < n4;
         i += gridDim.x * blockDim.x) {
        float4 v = in[i];
        out[i] = make_float4(__uint_as_float(f2tf(v.x)), __uint_as_float(f2tf(v.y)),
                             __uint_as_float(f2tf(v.z)), __uint_as_float(f2tf(v.w)));
    }
}

// ================= tf32 mma.sync GEMM (NT, cp.async) =============
// Operands MUST be pre-rounded to tf32 (low 13 bits zero).
#define GBM 128
#define GBN 128
#define GBK 32
#define LDST 36
#define GTILE (GBM * LDST)
#define GEMM_SMEM (4 * GTILE * 4)

__global__ __launch_bounds__(256) void tf32_gemm_nt(
    const float* __restrict__ A, const float* __restrict__ B,
    const float* __restrict__ bias, float* __restrict__ C,
    int M, int N, int K)
{
    extern __shared__ uint32_t sm[];
    uint32_t* As = sm;
    uint32_t* Bs = sm + 2 * GTILE;
    const uint32_t sA = smem_u32(As);
    const uint32_t sB = smem_u32(Bs);

    const int t    = threadIdx.x;
    const int lane = t & 31;
    const int wid  = t >> 5;
    const int m0   = blockIdx.y * GBM;
    const int n0   = blockIdx.x * GBN;
    const int wm   = (wid & 1) * 64;
    const int wn   = (wid >> 1) * 32;
    const int fr   = lane >> 2;
    const int fc   = lane & 3;

    float acc[4][4][4];
    #pragma unroll
    for (int mi = 0; mi < 4; ++mi)
        #pragma unroll
        for (int ni = 0; ni < 4; ++ni)
            #pragma unroll
            for (int r = 0; r < 4; ++r) acc[mi][ni][r] = 0.f;

    const int lrow = t >> 3, lf4 = (t & 7) * 4;   // this thread's 4 rows x 1 f4 slot
    auto load_async = [&](int buf, int k0) {
        #pragma unroll
        for (int i = 0; i < 4; ++i) {
            int row = lrow + i * 32;
            uint32_t off = (uint32_t)(buf * GTILE + row * LDST + lf4) * 4;
            CP_ASYNC16(sA + off, A + (size_t)(m0 + row) * K + k0 + lf4);
            CP_ASYNC16(sB + off, B + (size_t)(n0 + row) * K + k0 + lf4);
        }
        CP_COMMIT();
    };

    const int NCH = K / GBK;
    load_async(0, 0);

    for (int c = 0; c < NCH; ++c) {
        CP_WAIT0();
        __syncthreads();            // buf c ready; prev MMA reads of this buf done
        if (c + 1 < NCH) load_async((c + 1) & 1, (c + 1) * GBK);

        const uint32_t* Ab = &As[(c & 1) * GTILE];
        const uint32_t* Bb = &Bs[(c & 1) * GTILE];
        #pragma unroll
        for (int k8 = 0; k8 < 4; ++k8) {
            const int kc = k8 * 8;
            uint32_t af[4][4];
            #pragma unroll
            for (int mi = 0; mi < 4; ++mi) {
                const uint32_t* p = Ab + (wm + mi * 16) * LDST + kc;
                af[mi][0] = p[fr * LDST + fc];
                af[mi][1] = p[(fr + 8) * LDST + fc];
                af[mi][2] = p[fr * LDST + fc + 4];
                af[mi][3] = p[(fr + 8) * LDST + fc + 4];
            }
            uint32_t bf[4][2];
            #pragma unroll
            for (int ni = 0; ni < 4; ++ni) {
                const uint32_t* p = Bb + (wn + ni * 8 + fr) * LDST + kc + fc;
                bf[ni][0] = p[0];
                bf[ni][1] = p[4];
            }
            #pragma unroll
            for (int mi = 0; mi < 4; ++mi)
                #pragma unroll
                for (int ni = 0; ni < 4; ++ni)
                    MMA_TF32(acc[mi][ni], af[mi], bf[ni]);
        }
        __syncthreads();            // MMA reads done before next overwrite
    }

    const int c2 = fc * 2;
    #pragma unroll
    for (int mi = 0; mi < 4; ++mi) {
        #pragma unroll
        for (int ni = 0; ni < 4; ++ni) {
            int row = m0 + wm + mi * 16 + fr;
            int col = n0 + wn + ni * 8 + c2;
            float b0 = bias[col], b1 = bias[col + 1];
            float2 lo = make_float2(acc[mi][ni][0] + b0, acc[mi][ni][1] + b1);
            float2 hi = make_float2(acc[mi][ni][2] + b0, acc[mi][ni][3] + b1);
            *(float2*)&C[(size_t)row * N + col] = lo;
            *(float2*)&C[(size_t)(row + 8) * N + col] = hi;
        }
    }
}

// ----------------------------------------------------------------
// Fused RMSNorm + RoPE (unchanged)
// ----------------------------------------------------------------
__global__ __launch_bounds__(256) void normrope_kernel(
    const float* __restrict__ gq, const float* __restrict__ gk,
    const float* __restrict__ freqs)
{
    const int tok = blockIdx.x;
    const int t   = threadIdx.x;
    float* qr = g_q + (size_t)tok * DIM;
    float* kr = g_k + (size_t)tok * DIM;

    __shared__ float red[16];
    __shared__ float s_scq, s_sck;

    float sq = 0.f, sk = 0.f;
    for (int i = t; i < DIM; i += 256) {
        float a = qr[i]; sq += a * a;
        float b = kr[i]; sk += b * b;
    }
    #pragma unroll
    for (int m = 16; m >= 1; m >>= 1) {
        sq += __shfl_xor_sync(0xffffffffu, sq, m);
        sk += __shfl_xor_sync(0xffffffffu, sk, m);
    }
    if ((t & 31) == 0) { red[t >> 5] = sq; red[8 + (t >> 5)] = sk; }
    __syncthreads();
    if (t == 0) {
        float a = 0.f, b = 0.f;
        #pragma unroll
        for (int w = 0; w < 8; ++w) { a += red[w]; b += red[8 + w]; }
        s_scq = rsqrtf(a * (1.f / DIM) + 1e-6f);
        s_sck = rsqrtf(b * (1.f / DIM) + 1e-6f);
    }
    __syncthreads();
    const float scq = s_scq, sck = s_sck;

    for (int p = t; p < DIM / 2; p += 256) {
        int hh = p >> 6, i = p & 63;
        int c0 = hh * HD + 2 * i;
        float fr = freqs[(size_t)tok * (HD / 2) + i];
        float cs = cosf(fr), sn = sinf(fr);
        float qe = qr[c0] * scq * gq[c0];
        float qo = qr[c0 + 1] * scq * gq[c0 + 1];
        qr[c0]     = qe * cs - qo * sn;
        qr[c0 + 1] = qe * sn + qo * cs;
        float ke = kr[c0] * sck * gk[c0];
        float ko = kr[c0 + 1] * sck * gk[c0 + 1];
        kr[c0]     = ke * cs - ko * sn;
        kr[c0 + 1] = ke * sn + ko * cs;
    }
}

// ================= tensor-core flash attention ===================
#define ABM 128
#define ABN 64
#define KST 132
#define VST 68
#define PST 68
#define ATTN_SMEM ((64 * KST + 128 * VST + 128 * PST) * 4)

__global__ __launch_bounds__(256) void attn_mma_kernel()
{
    extern __shared__ float smf[];
    float* Ks  = smf;                       // [64][KST]  (tok, k)
    float* VsT = Ks + 64 * KST;             // [128][VST] (d, tok swizzled)
    float* Ps  = VsT + 128 * VST;           // [128][PST] (q, tok)

    const int t    = threadIdx.x;
    const int lane = t & 31;
    const int w    = t >> 5;
    const int fr   = lane >> 2;
    const int fc   = lane & 3;
    const int mt = blockIdx.x, f = blockIdx.y, h = blockIdx.z;
    const int q0 = f * IMG + mt * ABM;
    int st = f - 7; st = st < 0 ? 0 : (st > 6 ? 6 : st);
    const int kbase = st * IMG;
    const float scale = 0.08838834764831845f;  // 1/sqrt(128)

    uint32_t qf[16][4];
    {
        const float* Q0 = g_q + (size_t)(q0 + 16 * w + fr) * DIM + h * HD;
        const float* Q8 = Q0 + 8 * DIM;
        #pragma unroll
        for (int ks = 0; ks < 16; ++ks) {
            const int kc = ks * 8;
            qf[ks][0] = f2tf(Q0[kc + fc] * scale);
            qf[ks][1] = f2tf(Q8[kc + fc] * scale);
            qf[ks][2] = f2tf(Q0[kc + fc + 4] * scale);
            qf[ks][3] = f2tf(Q8[kc + fc + 4] * scale);
        }
    }

    float o[16][4];
    #pragma unroll
    for (int nf = 0; nf < 16; ++nf)
        #pragma unroll
        for (int r = 0; r < 4; ++r) o[nf][r] = 0.f;
    float Mlo = -INFINITY, Mhi = -INFINITY, Llo = 0.f, Lhi = 0.f;

    const int prow0 = (16 * w + fr) * PST;
    const int prow8 = (16 * w + fr + 8) * PST;

    for (int c = 0; c < WKV / ABN; ++c) {
        __syncthreads();
        const int kb = kbase + c * ABN;
        #pragma unroll
        for (int i = 0; i < 8; ++i) {
            int idx = t + i * 256;
            int row = idx >> 5, c4 = (idx & 31) << 2;
            float4 kv = *(const float4*)&g_k[(size_t)(kb + row) * DIM + h * HD + c4];
            *(uint4*)&Ks[row * KST + c4] =
                make_uint4(f2tf(kv.x), f2tf(kv.y), f2tf(kv.z), f2tf(kv.w));
            float4 vv = *(const float4*)&g_v[(size_t)(kb + row) * DIM + h * HD + c4];
            int col = (row + (c4 >> 2)) & 63;
            VsT[(c4 + 0) * VST + col] = __uint_as_float(f2tf(vv.x));
            VsT[(c4 + 1) * VST + col] = __uint_as_float(f2tf(vv.y));
            VsT[(c4 + 2) * VST + col] = __uint_as_float(f2tf(vv.z));
            VsT[(c4 + 3) * VST + col] = __uint_as_float(f2tf(vv.w));
        }
        __syncthreads();

        float s[8][4];
        #pragma unroll
        for (int nf = 0; nf < 8; ++nf)
            #pragma unroll
            for (int r = 0; r < 4; ++r) s[nf][r] = 0.f;

        #pragma unroll
        for (int ks = 0; ks < 16; ++ks) {
            const int kc = ks * 8;
            #pragma unroll
            for (int nf = 0; nf < 8; ++nf) {
                const float* p = &Ks[(8 * nf + fr) * KST + kc + fc];
                uint32_t b[2] = { __float_as_uint(p[0]), __float_as_uint(p[4]) };
                MMA_TF32(s[nf], qf[ks], b);
            }
        }

        float mlo = -INFINITY, mhi = -INFINITY;
        #pragma unroll
        for (int nf = 0; nf < 8; ++nf) {
            mlo = fmaxf(mlo, fmaxf(s[nf][0], s[nf][1]));
            mhi = fmaxf(mhi, fmaxf(s[nf][2], s[nf][3]));
        }
        mlo = fmaxf(mlo, __shfl_xor_sync(0xffffffffu, mlo, 1));
        mlo = fmaxf(mlo, __shfl_xor_sync(0xffffffffu, mlo, 2));
        mhi = fmaxf(mhi, __shfl_xor_sync(0xffffffffu, mhi, 1));
        mhi = fmaxf(mhi, __shfl_xor_sync(0xffffffffu, mhi, 2));
        const float Mnlo = fmaxf(Mlo, mlo), Mnhi = fmaxf(Mhi, mhi);
        const float alo = __expf(Mlo - Mnlo), ahi = __expf(Mhi - Mnhi);
        Mlo = Mnlo; Mhi = Mnhi;

        float rlo = 0.f, rhi = 0.f;
        #pragma unroll
        for (int nf = 0; nf < 8; ++nf) {
            s[nf][0] = __uint_as_float(f2tf(__expf(s[nf][0] - Mnlo)));
            s[nf][1] = __uint_as_float(f2tf(__expf(s[nf][1] - Mnlo)));
            s[nf][2] = __uint_as_float(f2tf(__expf(s[nf][2] - Mnhi)));
            s[nf][3] = __uint_as_float(f2tf(__expf(s[nf][3] - Mnhi)));
            rlo += s[nf][0] + s[nf][1];
            rhi += s[nf][2] + s[nf][3];
        }
        rlo += __shfl_xor_sync(0xffffffffu, rlo, 1);
        rlo += __shfl_xor_sync(0xffffffffu, rlo, 2);
        rhi += __shfl_xor_sync(0xffffffffu, rhi, 1);
        rhi += __shfl_xor_sync(0xffffffffu, rhi, 2);
        Llo = Llo * alo + rlo;
        Lhi = Lhi * ahi + rhi;
        #pragma unroll
        for (int nf = 0; nf < 16; ++nf) {
            o[nf][0] *= alo; o[nf][1] *= alo;
            o[nf][2] *= ahi; o[nf][3] *= ahi;
        }
        #pragma unroll
        for (int nf = 0; nf < 8; ++nf) {
            *(float2*)&Ps[prow0 + 8 * nf + 2 * fc] = make_float2(s[nf][0], s[nf][1]);
            *(float2*)&Ps[prow8 + 8 * nf + 2 * fc] = make_float2(s[nf][2], s[nf][3]);
        }
        __syncwarp();

        #pragma unroll
        for (int k2 = 0; k2 < 8; ++k2) {
            const int kc = k2 * 8;
            uint32_t a[4];
            a[0] = __float_as_uint(Ps[prow0 + kc + fc]);
            a[1] = __float_as_uint(Ps[prow8 + kc + fc]);
            a[2] = __float_as_uint(Ps[prow0 + kc + fc + 4]);
            a[3] = __float_as_uint(Ps[prow8 + kc + fc + 4]);
            #pragma unroll
            for (int nf = 0; nf < 16; ++nf) {
                const int d = 8 * nf + fr;
                const int rot = d >> 2;
                uint32_t b[2];
                b[0] = __float_as_uint(VsT[d * VST + ((kc + fc + rot) & 63)]);
                b[1] = __float_as_uint(VsT[d * VST + ((kc + fc + 4 + rot) & 63)]);
                MMA_TF32(o[nf], a, b);
            }
        }
        __syncwarp();
    }

    // epilogue: tf32-round output so the O-proj GEMM can cp.async it
    const float il = 1.f / Llo, ih = 1.f / Lhi;
    const int row0 = q0 + 16 * w + fr;
    #pragma unroll
    for (int nf = 0; nf < 16; ++nf) {
        const int col = h * HD + 8 * nf + 2 * fc;
        *(float2*)&g_attn[(size_t)row0 * DIM + col] =
            make_float2(__uint_as_float(f2tf(o[nf][0] * il)),
                        __uint_as_float(f2tf(o[nf][1] * il)));
        *(float2*)&g_attn[(size_t)(row0 + 8) * DIM + col] =
            make_float2(__uint_as_float(f2tf(o[nf][2] * ih)),
                        __uint_as_float(f2tf(o[nf][3] * ih)));
    }
}

// ----------------------------------------------------------------
extern "C" void kernel_launch(void* const* d_in, const int* in_sizes, int n_in,
                              void* d_out, int out_size)
{
    const float* x     = (const float*)d_in[0];
    const float* freqs = (const float*)d_in[1];
    const float* Wq    = (const float*)d_in[2];
    const float* bq    = (const float*)d_in[3];
    const float* Wk    = (const float*)d_in[4];
    const float* bk    = (const float*)d_in[5];
    const float* Wv    = (const float*)d_in[6];
    const float* bv    = (const float*)d_in[7];
    const float* Wo    = (const float*)d_in[8];
    const float* bo    = (const float*)d_in[9];
    const float* gq    = (const float*)d_in[10];
    const float* gk    = (const float*)d_in[11];
    float* out = (float*)d_out;

    void *pq, *pk, *pv, *pa, *pxt, *pwt;
    cudaGetSymbolAddress(&pq, g_q);
    cudaGetSymbolAddress(&pk, g_k);
    cudaGetSymbolAddress(&pv, g_v);
    cudaGetSymbolAddress(&pa, g_attn);
    cudaGetSymbolAddress(&pxt, g_xtf);
    cudaGetSymbolAddress(&pwt, g_wtf);
    float* xtf = (float*)pxt;
    float* wtf = (float*)pwt;

    // pre-round GEMM operands to tf32
    const int NW4 = DIM * DIM / 4;
    tf32_round_kernel<<<1184, 256>>>((const float4*)x, (float4*)xtf, S_TOK * DIM / 4);
    tf32_round_kernel<<<592, 256>>>((const float4*)Wq, (float4*)(wtf + 0 * (size_t)DIM * DIM), NW4);
    tf32_round_kernel<<<592, 256>>>((const float4*)Wk, (float4*)(wtf + 1 * (size_t)DIM * DIM), NW4);
    tf32_round_kernel<<<592, 256>>>((const float4*)Wv, (float4*)(wtf + 2 * (size_t)DIM * DIM), NW4);
    tf32_round_kernel<<<592, 256>>>((const float4*)Wo, (float4*)(wtf + 3 * (size_t)DIM * DIM), NW4);

    cudaFuncSetAttribute(tf32_gemm_nt, cudaFuncAttributeMaxDynamicSharedMemorySize, GEMM_SMEM);

    dim3 gg(DIM / 128, S_TOK / 128);
    tf32_gemm_nt<<<gg, 256, GEMM_SMEM>>>(xtf, wtf + 0 * (size_t)DIM * DIM, bq, (float*)pq, S_TOK, DIM, DIM);
    tf32_gemm_nt<<<gg, 256, GEMM_SMEM>>>(xtf, wtf + 1 * (size_t)DIM * DIM, bk, (float*)pk, S_TOK, DIM, DIM);
    tf32_gemm_nt<<<gg, 256, GEMM_SMEM>>>(xtf, wtf + 2 * (size_t)DIM * DIM, bv, (float*)pv, S_TOK, DIM, DIM);

    normrope_kernel<<<S_TOK, 256>>>(gq, gk, freqs);

    cudaFuncSetAttribute(attn_mma_kernel, cudaFuncAttributeMaxDynamicSharedMemorySize, ATTN_SMEM);
    attn_mma_kernel<<<dim3(IMG / ABM, NF, NH), 256, ATTN_SMEM>>>();

    tf32_gemm_nt<<<gg, 256, GEMM_SMEM>>>((const float*)pa, wtf + 3 * (size_t)DIM * DIM, bo, out, S_TOK, DIM, DIM);
}

// round 7
// speedup vs baseline: 3.0480x; 1.0347x over previous
#include <cuda_runtime.h>
#include <math.h>
#include <stdint.h>

#define S_TOK 5376
#define DIM   1536
#define NH    12
#define HD    128
#define NF    21
#define IMG   256
#define WKV   3840

// -------- scratch (device-global; no allocation allowed) --------
__device__ float g_q[(size_t)S_TOK * DIM];
__device__ float g_k[(size_t)S_TOK * DIM];
__device__ float g_v[(size_t)S_TOK * DIM];
__device__ float g_attn[(size_t)S_TOK * DIM];
__device__ float g_xtf[(size_t)S_TOK * DIM];
__device__ float g_wtf[(size_t)4 * DIM * DIM];   // concat Wq,Wk,Wv then Wo

__device__ __forceinline__ uint32_t f2tf(float x) {
    uint32_t r;
    asm("cvt.rna.tf32.f32 %0, %1;" : "=r"(r) : "f"(x));
    return r;
}
__device__ __forceinline__ uint32_t smem_u32(const void* p) {
    uint32_t a;
    asm("{ .reg .u64 t; cvta.to.shared.u64 t, %1; cvt.u32.u64 %0, t; }" : "=r"(a) : "l"(p));
    return a;
}

#define MMA_TF32(c, a, b) \
    asm volatile("mma.sync.aligned.m16n8k8.row.col.f32.tf32.tf32.f32 " \
                 "{%0,%1,%2,%3}, {%4,%5,%6,%7}, {%8,%9}, {%0,%1,%2,%3};" \
                 : "+f"((c)[0]), "+f"((c)[1]), "+f"((c)[2]), "+f"((c)[3]) \
                 : "r"((a)[0]), "r"((a)[1]), "r"((a)[2]), "r"((a)[3]), \
                   "r"((b)[0]), "r"((b)[1]))

#define CP_ASYNC16(dst, src) \
    asm volatile("cp.async.cg.shared.global [%0], [%1], 16;" :: "r"(dst), "l"(src))
#define CP_COMMIT() asm volatile("cp.async.commit_group;" ::: "memory")
#define CP_WAIT0()  asm volatile("cp.async.wait_group 0;" ::: "memory")
#define CP_WAIT1()  asm volatile("cp.async.wait_group 1;" ::: "memory")

// ---------------- tf32 pre-rounding pass -------------------------
__global__ __launch_bounds__(256) void tf32_round_kernel(
    const float4* __restrict__ in, float4* __restrict__ out, int n4)
{
    for (int i = blockIdx.x * blockDim.x + threadIdx.x; i < n4;
         i += gridDim.x * blockDim.x) {
        float4 v = in[i];
        out[i] = make_float4(__uint_as_float(f2tf(v.x)), __uint_as_float(f2tf(v.y)),
                             __uint_as_float(f2tf(v.z)), __uint_as_float(f2tf(v.w)));
    }
}

// ================= tf32 mma.sync GEMM core (NT) ==================
// Operands pre-rounded to tf32. 3-stage cp.async pipeline,
// CTA 128x128, K-chunk 32, 8 warps (2x4), warp tile 64x32.
#define GBM 128
#define GBN 128
#define GBK 32
#define LDST 36
#define GTILE (GBM * LDST)               // words per matrix per stage
#define GEMM_SMEM (6 * GTILE * 4)        // 3 stages x (A+B) = 110592 B

struct GemmCore {
    const float* A; const float* B; int K; int m0; int n0;
    uint32_t sA, sB;
    int t, lrow, lf4;

    __device__ __forceinline__ void load_async(int stage, int k0) const {
        #pragma unroll
        for (int i = 0; i < 4; ++i) {
            int row = lrow + i * 32;
            uint32_t off = (uint32_t)(stage * GTILE + row * LDST + lf4) * 4;
            CP_ASYNC16(sA + off, A + (size_t)(m0 + row) * K + k0 + lf4);
            CP_ASYNC16(sB + off, B + (size_t)(n0 + row) * K + k0 + lf4);
        }
        CP_COMMIT();
    }
};

// shared inner loop: compute one K-chunk from stage buffers
__device__ __forceinline__ void gemm_chunk(
    const uint32_t* __restrict__ Ab, const uint32_t* __restrict__ Bb,
    int wm, int wn, int fr, int fc, float acc[4][4][4])
{
    #pragma unroll
    for (int k8 = 0; k8 < 4; ++k8) {
        const int kc = k8 * 8;
        uint32_t af[4][4];
        #pragma unroll
        for (int mi = 0; mi < 4; ++mi) {
            const uint32_t* p = Ab + (wm + mi * 16) * LDST + kc;
            af[mi][0] = p[fr * LDST + fc];
            af[mi][1] = p[(fr + 8) * LDST + fc];
            af[mi][2] = p[fr * LDST + fc + 4];
            af[mi][3] = p[(fr + 8) * LDST + fc + 4];
        }
        uint32_t bf[4][2];
        #pragma unroll
        for (int ni = 0; ni < 4; ++ni) {
            const uint32_t* p = Bb + (wn + ni * 8 + fr) * LDST + kc + fc;
            bf[ni][0] = p[0];
            bf[ni][1] = p[4];
        }
        #pragma unroll
        for (int mi = 0; mi < 4; ++mi)
            #pragma unroll
            for (int ni = 0; ni < 4; ++ni)
                MMA_TF32(acc[mi][ni], af[mi], bf[ni]);
    }
}

#define GEMM_PROLOG_BODY(Aop, Bop, Kval)                                    \
    extern __shared__ uint32_t sm[];                                        \
    uint32_t* As = sm;                                                      \
    uint32_t* Bs = sm + 3 * GTILE;                                          \
    const int t    = threadIdx.x;                                           \
    const int lane = t & 31;                                                \
    const int wid  = t >> 5;                                                \
    const int wm   = (wid & 1) * 64;                                        \
    const int wn   = (wid >> 1) * 32;                                       \
    const int fr   = lane >> 2;                                             \
    const int fc   = lane & 3;                                              \
    float acc[4][4][4];                                                     \
    _Pragma("unroll")                                                       \
    for (int mi = 0; mi < 4; ++mi)                                          \
        _Pragma("unroll")                                                   \
        for (int ni = 0; ni < 4; ++ni)                                      \
            _Pragma("unroll")                                               \
            for (int r = 0; r < 4; ++r) acc[mi][ni][r] = 0.f;               \
    GemmCore core;                                                          \
    core.A = Aop; core.B = Bop; core.K = Kval; core.m0 = m0; core.n0 = n0;  \
    core.sA = smem_u32(As); core.sB = smem_u32(Bs);                         \
    core.t = t; core.lrow = t >> 3; core.lf4 = (t & 7) * 4;                 \
    const int NCH = (Kval) / GBK;                                           \
    core.load_async(0, 0);                                                  \
    core.load_async(1, GBK);                                                \
    for (int c = 0; c < NCH; ++c) {                                         \
        if (c + 1 < NCH) { CP_WAIT1(); } else { CP_WAIT0(); }               \
        __syncthreads();                                                    \
        if (c + 2 < NCH) core.load_async((c + 2) % 3, (c + 2) * GBK);       \
        const int stg = c % 3;                                              \
        gemm_chunk(&As[stg * GTILE], &Bs[stg * GTILE], wm, wn, fr, fc, acc);\
    }

// ---- generic NT GEMM (used for O-projection) ----
__global__ __launch_bounds__(256, 2) void tf32_gemm_nt(
    const float* __restrict__ A, const float* __restrict__ B,
    const float* __restrict__ bias, float* __restrict__ C,
    int M, int N, int K)
{
    const int m0 = blockIdx.y * GBM;
    const int n0 = blockIdx.x * GBN;
    GEMM_PROLOG_BODY(A, B, K)

    const int c2 = fc * 2;
    #pragma unroll
    for (int mi = 0; mi < 4; ++mi) {
        #pragma unroll
        for (int ni = 0; ni < 4; ++ni) {
            int row = m0 + wm + mi * 16 + fr;
            int col = n0 + wn + ni * 8 + c2;
            float b0 = bias[col], b1 = bias[col + 1];
            float2 lo = make_float2(acc[mi][ni][0] + b0, acc[mi][ni][1] + b1);
            float2 hi = make_float2(acc[mi][ni][2] + b0, acc[mi][ni][3] + b1);
            *(float2*)&C[(size_t)row * N + col] = lo;
            *(float2*)&C[(size_t)(row + 8) * N + col] = hi;
        }
    }
}

// ---- fused QKV GEMM: B = concat(Wq,Wk,Wv) [4608][1536] ----
__global__ __launch_bounds__(256, 2) void tf32_gemm_qkv(
    const float* __restrict__ A, const float* __restrict__ Bw,
    const float* __restrict__ bq, const float* __restrict__ bk,
    const float* __restrict__ bv,
    float* __restrict__ Cq, float* __restrict__ Ck, float* __restrict__ Cv)
{
    const int m0 = blockIdx.y * GBM;
    const int n0 = blockIdx.x * GBN;           // 0..4607 in steps of 128
    GEMM_PROLOG_BODY(A, Bw, DIM)

    const int which = blockIdx.x / 12;         // 0=q 1=k 2=v
    const int ncol0 = (blockIdx.x % 12) * 128;
    float* C = which == 0 ? Cq : (which == 1 ? Ck : Cv);
    const float* bias = which == 0 ? bq : (which == 1 ? bk : bv);

    const int c2 = fc * 2;
    #pragma unroll
    for (int mi = 0; mi < 4; ++mi) {
        #pragma unroll
        for (int ni = 0; ni < 4; ++ni) {
            int row = m0 + wm + mi * 16 + fr;
            int col = ncol0 + wn + ni * 8 + c2;
            float b0 = bias[col], b1 = bias[col + 1];
            float2 lo = make_float2(acc[mi][ni][0] + b0, acc[mi][ni][1] + b1);
            float2 hi = make_float2(acc[mi][ni][2] + b0, acc[mi][ni][3] + b1);
            *(float2*)&C[(size_t)row * DIM + col] = lo;
            *(float2*)&C[(size_t)(row + 8) * DIM + col] = hi;
        }
    }
}

// ----------------------------------------------------------------
// Fused RMSNorm + RoPE (unchanged)
// ----------------------------------------------------------------
__global__ __launch_bounds__(256) void normrope_kernel(
    const float* __restrict__ gq, const float* __restrict__ gk,
    const float* __restrict__ freqs)
{
    const int tok = blockIdx.x;
    const int t   = threadIdx.x;
    float* qr = g_q + (size_t)tok * DIM;
    float* kr = g_k + (size_t)tok * DIM;

    __shared__ float red[16];
    __shared__ float s_scq, s_sck;

    float sq = 0.f, sk = 0.f;
    for (int i = t; i < DIM; i += 256) {
        float a = qr[i]; sq += a * a;
        float b = kr[i]; sk += b * b;
    }
    #pragma unroll
    for (int m = 16; m >= 1; m >>= 1) {
        sq += __shfl_xor_sync(0xffffffffu, sq, m);
        sk += __shfl_xor_sync(0xffffffffu, sk, m);
    }
    if ((t & 31) == 0) { red[t >> 5] = sq; red[8 + (t >> 5)] = sk; }
    __syncthreads();
    if (t == 0) {
        float a = 0.f, b = 0.f;
        #pragma unroll
        for (int w = 0; w < 8; ++w) { a += red[w]; b += red[8 + w]; }
        s_scq = rsqrtf(a * (1.f / DIM) + 1e-6f);
        s_sck = rsqrtf(b * (1.f / DIM) + 1e-6f);
    }
    __syncthreads();
    const float scq = s_scq, sck = s_sck;

    for (int p = t; p < DIM / 2; p += 256) {
        int hh = p >> 6, i = p & 63;
        int c0 = hh * HD + 2 * i;
        float fr = freqs[(size_t)tok * (HD / 2) + i];
        float cs = cosf(fr), sn = sinf(fr);
        float qe = qr[c0] * scq * gq[c0];
        float qo = qr[c0 + 1] * scq * gq[c0 + 1];
        qr[c0]     = qe * cs - qo * sn;
        qr[c0 + 1] = qe * sn + qo * cs;
        float ke = kr[c0] * sck * gk[c0];
        float ko = kr[c0 + 1] * sck * gk[c0 + 1];
        kr[c0]     = ke * cs - ko * sn;
        kr[c0 + 1] = ke * sn + ko * cs;
    }
}

// ================= tensor-core flash attention ===================
#define ABM 128
#define ABN 64
#define KST 132
#define VST 68
#define PST 68
#define ATTN_SMEM ((64 * KST + 128 * VST + 128 * PST) * 4)

__global__ __launch_bounds__(256) void attn_mma_kernel()
{
    extern __shared__ float smf[];
    float* Ks  = smf;                       // [64][KST]  (tok, k)
    float* VsT = Ks + 64 * KST;             // [128][VST] (d, tok swizzled)
    float* Ps  = VsT + 128 * VST;           // [128][PST] (q, tok)

    const int t    = threadIdx.x;
    const int lane = t & 31;
    const int w    = t >> 5;
    const int fr   = lane >> 2;
    const int fc   = lane & 3;
    const int mt = blockIdx.x, f = blockIdx.y, h = blockIdx.z;
    const int q0 = f * IMG + mt * ABM;
    int st = f - 7; st = st < 0 ? 0 : (st > 6 ? 6 : st);
    const int kbase = st * IMG;
    const float scale = 0.08838834764831845f;  // 1/sqrt(128)

    uint32_t qf[16][4];
    {
        const float* Q0 = g_q + (size_t)(q0 + 16 * w + fr) * DIM + h * HD;
        const float* Q8 = Q0 + 8 * DIM;
        #pragma unroll
        for (int ks = 0; ks < 16; ++ks) {
            const int kc = ks * 8;
            qf[ks][0] = f2tf(Q0[kc + fc] * scale);
            qf[ks][1] = f2tf(Q8[kc + fc] * scale);
            qf[ks][2] = f2tf(Q0[kc + fc + 4] * scale);
            qf[ks][3] = f2tf(Q8[kc + fc + 4] * scale);
        }
    }

    float o[16][4];
    #pragma unroll
    for (int nf = 0; nf < 16; ++nf)
        #pragma unroll
        for (int r = 0; r < 4; ++r) o[nf][r] = 0.f;
    float Mlo = -INFINITY, Mhi = -INFINITY, Llo = 0.f, Lhi = 0.f;

    const int prow0 = (16 * w + fr) * PST;
    const int prow8 = (16 * w + fr + 8) * PST;

    for (int c = 0; c < WKV / ABN; ++c) {
        __syncthreads();
        const int kb = kbase + c * ABN;
        #pragma unroll
        for (int i = 0; i < 8; ++i) {
            int idx = t + i * 256;
            int row = idx >> 5, c4 = (idx & 31) << 2;
            float4 kv = *(const float4*)&g_k[(size_t)(kb + row) * DIM + h * HD + c4];
            *(uint4*)&Ks[row * KST + c4] =
                make_uint4(f2tf(kv.x), f2tf(kv.y), f2tf(kv.z), f2tf(kv.w));
            float4 vv = *(const float4*)&g_v[(size_t)(kb + row) * DIM + h * HD + c4];
            int col = (row + (c4 >> 2)) & 63;
            VsT[(c4 + 0) * VST + col] = __uint_as_float(f2tf(vv.x));
            VsT[(c4 + 1) * VST + col] = __uint_as_float(f2tf(vv.y));
            VsT[(c4 + 2) * VST + col] = __uint_as_float(f2tf(vv.z));
            VsT[(c4 + 3) * VST + col] = __uint_as_float(f2tf(vv.w));
        }
        __syncthreads();

        float s[8][4];
        #pragma unroll
        for (int nf = 0; nf < 8; ++nf)
            #pragma unroll
            for (int r = 0; r < 4; ++r) s[nf][r] = 0.f;

        #pragma unroll
        for (int ks = 0; ks < 16; ++ks) {
            const int kc = ks * 8;
            #pragma unroll
            for (int nf = 0; nf < 8; ++nf) {
                const float* p = &Ks[(8 * nf + fr) * KST + kc + fc];
                uint32_t b[2] = { __float_as_uint(p[0]), __float_as_uint(p[4]) };
                MMA_TF32(s[nf], qf[ks], b);
            }
        }

        float mlo = -INFINITY, mhi = -INFINITY;
        #pragma unroll
        for (int nf = 0; nf < 8; ++nf) {
            mlo = fmaxf(mlo, fmaxf(s[nf][0], s[nf][1]));
            mhi = fmaxf(mhi, fmaxf(s[nf][2], s[nf][3]));
        }
        mlo = fmaxf(mlo, __shfl_xor_sync(0xffffffffu, mlo, 1));
        mlo = fmaxf(mlo, __shfl_xor_sync(0xffffffffu, mlo, 2));
        mhi = fmaxf(mhi, __shfl_xor_sync(0xffffffffu, mhi, 1));
        mhi = fmaxf(mhi, __shfl_xor_sync(0xffffffffu, mhi, 2));
        const float Mnlo = fmaxf(Mlo, mlo), Mnhi = fmaxf(Mhi, mhi);
        const float alo = __expf(Mlo - Mnlo), ahi = __expf(Mhi - Mnhi);
        Mlo = Mnlo; Mhi = Mnhi;

        float rlo = 0.f, rhi = 0.f;
        #pragma unroll
        for (int nf = 0; nf < 8; ++nf) {
            s[nf][0] = __uint_as_float(f2tf(__expf(s[nf][0] - Mnlo)));
            s[nf][1] = __uint_as_float(f2tf(__expf(s[nf][1] - Mnlo)));
            s[nf][2] = __uint_as_float(f2tf(__expf(s[nf][2] - Mnhi)));
            s[nf][3] = __uint_as_float(f2tf(__expf(s[nf][3] - Mnhi)));
            rlo += s[nf][0] + s[nf][1];
            rhi += s[nf][2] + s[nf][3];
        }
        rlo += __shfl_xor_sync(0xffffffffu, rlo, 1);
        rlo += __shfl_xor_sync(0xffffffffu, rlo, 2);
        rhi += __shfl_xor_sync(0xffffffffu, rhi, 1);
        rhi += __shfl_xor_sync(0xffffffffu, rhi, 2);
        Llo = Llo * alo + rlo;
        Lhi = Lhi * ahi + rhi;
        #pragma unroll
        for (int nf = 0; nf < 16; ++nf) {
            o[nf][0] *= alo; o[nf][1] *= alo;
            o[nf][2] *= ahi; o[nf][3] *= ahi;
        }
        #pragma unroll
        for (int nf = 0; nf < 8; ++nf) {
            *(float2*)&Ps[prow0 + 8 * nf + 2 * fc] = make_float2(s[nf][0], s[nf][1]);
            *(float2*)&Ps[prow8 + 8 * nf + 2 * fc] = make_float2(s[nf][2], s[nf][3]);
        }
        __syncwarp();

        #pragma unroll
        for (int k2 = 0; k2 < 8; ++k2) {
            const int kc = k2 * 8;
            uint32_t a[4];
            a[0] = __float_as_uint(Ps[prow0 + kc + fc]);
            a[1] = __float_as_uint(Ps[prow8 + kc + fc]);
            a[2] = __float_as_uint(Ps[prow0 + kc + fc + 4]);
            a[3] = __float_as_uint(Ps[prow8 + kc + fc + 4]);
            #pragma unroll
            for (int nf = 0; nf < 16; ++nf) {
                const int d = 8 * nf + fr;
                const int rot = d >> 2;
                uint32_t b[2];
                b[0] = __float_as_uint(VsT[d * VST + ((kc + fc + rot) & 63)]);
                b[1] = __float_as_uint(VsT[d * VST + ((kc + fc + 4 + rot) & 63)]);
                MMA_TF32(o[nf], a, b);
            }
        }
        __syncwarp();
    }

    // epilogue: tf32-round output so the O-proj GEMM can cp.async it
    const float il = 1.f / Llo, ih = 1.f / Lhi;
    const int row0 = q0 + 16 * w + fr;
    #pragma unroll
    for (int nf = 0; nf < 16; ++nf) {
        const int col = h * HD + 8 * nf + 2 * fc;
        *(float2*)&g_attn[(size_t)row0 * DIM + col] =
            make_float2(__uint_as_float(f2tf(o[nf][0] * il)),
                        __uint_as_float(f2tf(o[nf][1] * il)));
        *(float2*)&g_attn[(size_t)(row0 + 8) * DIM + col] =
            make_float2(__uint_as_float(f2tf(o[nf][2] * ih)),
                        __uint_as_float(f2tf(o[nf][3] * ih)));
    }
}

// ----------------------------------------------------------------
extern "C" void kernel_launch(void* const* d_in, const int* in_sizes, int n_in,
                              void* d_out, int out_size)
{
    const float* x     = (const float*)d_in[0];
    const float* freqs = (const float*)d_in[1];
    const float* Wq    = (const float*)d_in[2];
    const float* bq    = (const float*)d_in[3];
    const float* Wk    = (const float*)d_in[4];
    const float* bk    = (const float*)d_in[5];
    const float* Wv    = (const float*)d_in[6];
    const float* bv    = (const float*)d_in[7];
    const float* Wo    = (const float*)d_in[8];
    const float* bo    = (const float*)d_in[9];
    const float* gq    = (const float*)d_in[10];
    const float* gk    = (const float*)d_in[11];
    float* out = (float*)d_out;

    void *pq, *pk, *pv, *pa, *pxt, *pwt;
    cudaGetSymbolAddress(&pq, g_q);
    cudaGetSymbolAddress(&pk, g_k);
    cudaGetSymbolAddress(&pv, g_v);
    cudaGetSymbolAddress(&pa, g_attn);
    cudaGetSymbolAddress(&pxt, g_xtf);
    cudaGetSymbolAddress(&pwt, g_wtf);
    float* xtf = (float*)pxt;
    float* wtf = (float*)pwt;

    // pre-round GEMM operands to tf32 (Wq,Wk,Wv concatenated, then Wo)
    const int NW4 = DIM * DIM / 4;
    tf32_round_kernel<<<1184, 256>>>((const float4*)x, (float4*)xtf, S_TOK * DIM / 4);
    tf32_round_kernel<<<592, 256>>>((const float4*)Wq, (float4*)(wtf + 0 * (size_t)DIM * DIM), NW4);
    tf32_round_kernel<<<592, 256>>>((const float4*)Wk, (float4*)(wtf + 1 * (size_t)DIM * DIM), NW4);
    tf32_round_kernel<<<592, 256>>>((const float4*)Wv, (float4*)(wtf + 2 * (size_t)DIM * DIM), NW4);
    tf32_round_kernel<<<592, 256>>>((const float4*)Wo, (float4*)(wtf + 3 * (size_t)DIM * DIM), NW4);

    cudaFuncSetAttribute(tf32_gemm_qkv, cudaFuncAttributeMaxDynamicSharedMemorySize, GEMM_SMEM);
    cudaFuncSetAttribute(tf32_gemm_nt, cudaFuncAttributeMaxDynamicSharedMemorySize, GEMM_SMEM);

    tf32_gemm_qkv<<<dim3(36, S_TOK / 128), 256, GEMM_SMEM>>>(
        xtf, wtf, bq, bk, bv, (float*)pq, (float*)pk, (float*)pv);

    normrope_kernel<<<S_TOK, 256>>>(gq, gk, freqs);

    cudaFuncSetAttribute(attn_mma_kernel, cudaFuncAttributeMaxDynamicSharedMemorySize, ATTN_SMEM);
    attn_mma_kernel<<<dim3(IMG / ABM, NF, NH), 256, ATTN_SMEM>>>();

    tf32_gemm_nt<<<dim3(12, S_TOK / 128), 256, GEMM_SMEM>>>(
        (const float*)pa, wtf + 3 * (size_t)DIM * DIM, bo, out, S_TOK, DIM, DIM);
}

// round 9
// speedup vs baseline: 5.0893x; 1.6697x over previous
#include <cuda_runtime.h>
#include <cuda_fp16.h>
#include <math.h>
#include <stdint.h>

#define S_TOK 5376
#define DIM   1536
#define NH    12
#define HD    128
#define NF    21
#define IMG   256
#define WKV   3840

// -------- scratch (device-global; no allocation allowed) --------
__device__ float  g_q[(size_t)S_TOK * DIM];          // fp32 q (pre-norm)
__device__ float  g_k[(size_t)S_TOK * DIM];          // fp32 k (pre-norm)
__device__ __half g_xh[(size_t)S_TOK * DIM];         // half x
__device__ __half g_wh[(size_t)4 * DIM * DIM];       // half Wq,Wk,Wv,Wo concat
__device__ __half g_qh[(size_t)S_TOK * DIM];         // half q (post rope, scaled)
__device__ __half g_kh[(size_t)S_TOK * DIM];         // half k (post rope)
__device__ __half g_vh[(size_t)S_TOK * DIM];         // half v
__device__ __half g_attnh[(size_t)S_TOK * DIM];      // half attention output

__device__ __forceinline__ uint32_t f2h2(float lo, float hi) {
    uint32_t r;
    asm("{ .reg .f16 l, h; cvt.rn.f16.f32 l, %1; cvt.rn.f16.f32 h, %2; mov.b32 %0, {l, h}; }"
        : "=r"(r) : "f"(lo), "f"(hi));
    return r;
}
__device__ __forceinline__ uint32_t smem_u32(const void* p) {
    uint32_t a;
    asm("{ .reg .u64 t; cvta.to.shared.u64 t, %1; cvt.u32.u64 %0, t; }" : "=r"(a) : "l"(p));
    return a;
}

#define MMA_F16(c, a, b) \
    asm volatile("mma.sync.aligned.m16n8k16.row.col.f32.f16.f16.f32 " \
                 "{%0,%1,%2,%3}, {%4,%5,%6,%7}, {%8,%9}, {%0,%1,%2,%3};" \
                 : "+f"((c)[0]), "+f"((c)[1]), "+f"((c)[2]), "+f"((c)[3]) \
                 : "r"((a)[0]), "r"((a)[1]), "r"((a)[2]), "r"((a)[3]), \
                   "r"((b)[0]), "r"((b)[1]))

#define CP_ASYNC16(dst, src) \
    asm volatile("cp.async.cg.shared.global [%0], [%1], 16;" :: "r"(dst), "l"(src))
#define CP_COMMIT() asm volatile("cp.async.commit_group;" ::: "memory")
#define CP_WAIT0()  asm volatile("cp.async.wait_group 0;" ::: "memory")
#define CP_WAIT1()  asm volatile("cp.async.wait_group 1;" ::: "memory")

// ---------------- fp32 -> fp16 conversion pass -------------------
__global__ __launch_bounds__(256) void cvt_half_kernel(
    const float4* __restrict__ in, uint2* __restrict__ out, int n4)
{
    for (int i = blockIdx.x * blockDim.x + threadIdx.x; i < n4;
         i += gridDim.x * blockDim.x) {
        float4 v = in[i];
        out[i] = make_uint2(f2h2(v.x, v.y), f2h2(v.z, v.w));
    }
}

// ================= fp16 mma.sync GEMM (NT) =======================
// C[m][n] = sum_k A[m][k]*B[n][k] (+bias). A,B half, k-contiguous.
// CTA 128x128, K-chunk 32 halves, 8 warps (2x4), warp tile 64x32.
#define GBM 128
#define GBN 128
#define GBK 32
#define AST 20                        // words per row (16 data + 4 pad)
#define GTILE (128 * AST)             // 2560 words per matrix per stage
#define GEMM_SMEM (6 * GTILE * 4)     // 3 stages x (A+B) = 61440 B

struct GemmCore {
    const __half* A; const __half* B; int K; int m0; int n0;
    uint32_t sA, sB;
    int lrow, lc16;
    __device__ __forceinline__ void load_async(int stage, int k0) const {
        #pragma unroll
        for (int i = 0; i < 2; ++i) {
            int row = lrow + i * 64;
            uint32_t off = (uint32_t)(stage * GTILE + row * AST + lc16 * 4) * 4;
            CP_ASYNC16(sA + off, A + (size_t)(m0 + row) * K + k0 + lc16 * 8);
            CP_ASYNC16(sB + off, B + (size_t)(n0 + row) * K + k0 + lc16 * 8);
        }
        CP_COMMIT();
    }
};

__device__ __forceinline__ void gemm_chunk_f16(
    const uint32_t* __restrict__ Ab, const uint32_t* __restrict__ Bb,
    int wm, int wn, int fr, int fc, float acc[4][4][4])
{
    #pragma unroll
    for (int ks = 0; ks < 2; ++ks) {
        const int kw = ks * 8;
        uint32_t af[4][4];
        #pragma unroll
        for (int mi = 0; mi < 4; ++mi) {
            const uint32_t* p = Ab + (wm + mi * 16) * AST + kw;
            af[mi][0] = p[fr * AST + fc];
            af[mi][1] = p[(fr + 8) * AST + fc];
            af[mi][2] = p[fr * AST + fc + 4];
            af[mi][3] = p[(fr + 8) * AST + fc + 4];
        }
        uint32_t bf[4][2];
        #pragma unroll
        for (int ni = 0; ni < 4; ++ni) {
            const uint32_t* p = Bb + (wn + ni * 8 + fr) * AST + kw;
            bf[ni][0] = p[fc];
            bf[ni][1] = p[fc + 4];
        }
        #pragma unroll
        for (int mi = 0; mi < 4; ++mi)
            #pragma unroll
            for (int ni = 0; ni < 4; ++ni)
                MMA_F16(acc[mi][ni], af[mi], bf[ni]);
    }
}

#define GEMM_PROLOG_BODY(Aop, Bop, Kval)                                     \
    extern __shared__ uint32_t sm[];                                         \
    uint32_t* As = sm;                                                       \
    uint32_t* Bs = sm + 3 * GTILE;                                           \
    const int t    = threadIdx.x;                                            \
    const int lane = t & 31;                                                 \
    const int wid  = t >> 5;                                                 \
    const int wm   = (wid & 1) * 64;                                         \
    const int wn   = (wid >> 1) * 32;                                        \
    const int fr   = lane >> 2;                                              \
    const int fc   = lane & 3;                                               \
    float acc[4][4][4];                                                      \
    _Pragma("unroll")                                                        \
    for (int mi = 0; mi < 4; ++mi)                                           \
        _Pragma("unroll")                                                    \
        for (int ni = 0; ni < 4; ++ni)                                       \
            _Pragma("unroll")                                                \
            for (int r = 0; r < 4; ++r) acc[mi][ni][r] = 0.f;                \
    GemmCore core;                                                           \
    core.A = Aop; core.B = Bop; core.K = Kval; core.m0 = m0; core.n0 = n0;   \
    core.sA = smem_u32(As); core.sB = smem_u32(Bs);                          \
    core.lrow = t >> 2; core.lc16 = t & 3;                                   \
    const int NCH = (Kval) / GBK;                                            \
    core.load_async(0, 0);                                                   \
    core.load_async(1, GBK);                                                 \
    for (int c = 0; c < NCH; ++c) {                                          \
        if (c + 1 < NCH) { CP_WAIT1(); } else { CP_WAIT0(); }                \
        __syncthreads();                                                     \
        if (c + 2 < NCH) core.load_async((c + 2) % 3, (c + 2) * GBK);        \
        const int stg = c % 3;                                               \
        gemm_chunk_f16(&As[stg * GTILE], &Bs[stg * GTILE], wm, wn, fr, fc, acc);\
    }

// ---- O-projection GEMM: half inputs, fp32 output + bias ----
__global__ __launch_bounds__(256, 2) void f16_gemm_nt(
    const __half* __restrict__ A, const __half* __restrict__ B,
    const float* __restrict__ bias, float* __restrict__ C,
    int M, int N, int K)
{
    const int m0 = blockIdx.y * GBM;
    const int n0 = blockIdx.x * GBN;
    GEMM_PROLOG_BODY(A, B, K)

    const int c2 = fc * 2;
    #pragma unroll
    for (int mi = 0; mi < 4; ++mi) {
        #pragma unroll
        for (int ni = 0; ni < 4; ++ni) {
            int row = m0 + wm + mi * 16 + fr;
            int col = n0 + wn + ni * 8 + c2;
            float b0 = bias[col], b1 = bias[col + 1];
            *(float2*)&C[(size_t)row * N + col] =
                make_float2(acc[mi][ni][0] + b0, acc[mi][ni][1] + b1);
            *(float2*)&C[(size_t)(row + 8) * N + col] =
                make_float2(acc[mi][ni][2] + b0, acc[mi][ni][3] + b1);
        }
    }
}

// ---- fused QKV GEMM: q,k -> fp32; v -> half ----
__global__ __launch_bounds__(256, 2) void f16_gemm_qkv(
    const __half* __restrict__ A, const __half* __restrict__ Bw,
    const float* __restrict__ bq, const float* __restrict__ bk,
    const float* __restrict__ bv,
    float* __restrict__ Cq, float* __restrict__ Ck, __half* __restrict__ Cv)
{
    const int m0 = blockIdx.y * GBM;
    const int n0 = blockIdx.x * GBN;
    GEMM_PROLOG_BODY(A, Bw, DIM)

    const int which = blockIdx.x / 12;         // 0=q 1=k 2=v
    const int ncol0 = (blockIdx.x % 12) * 128;
    const int c2 = fc * 2;
    if (which == 2) {
        #pragma unroll
        for (int mi = 0; mi < 4; ++mi)
            #pragma unroll
            for (int ni = 0; ni < 4; ++ni) {
                int row = m0 + wm + mi * 16 + fr;
                int col = ncol0 + wn + ni * 8 + c2;
                float b0 = bv[col], b1 = bv[col + 1];
                *(uint32_t*)&g_vh[(size_t)row * DIM + col] =
                    f2h2(acc[mi][ni][0] + b0, acc[mi][ni][1] + b1);
                *(uint32_t*)&g_vh[(size_t)(row + 8) * DIM + col] =
                    f2h2(acc[mi][ni][2] + b0, acc[mi][ni][3] + b1);
            }
    } else {
        float* C = which == 0 ? Cq : Ck;
        const float* bias = which == 0 ? bq : bk;
        #pragma unroll
        for (int mi = 0; mi < 4; ++mi)
            #pragma unroll
            for (int ni = 0; ni < 4; ++ni) {
                int row = m0 + wm + mi * 16 + fr;
                int col = ncol0 + wn + ni * 8 + c2;
                float b0 = bias[col], b1 = bias[col + 1];
                *(float2*)&C[(size_t)row * DIM + col] =
                    make_float2(acc[mi][ni][0] + b0, acc[mi][ni][1] + b1);
                *(float2*)&C[(size_t)(row + 8) * DIM + col] =
                    make_float2(acc[mi][ni][2] + b0, acc[mi][ni][3] + b1);
            }
    }
}

// ----------------------------------------------------------------
// Fused RMSNorm (with gains) + RoPE: fp32 in -> half out.
// q additionally scaled by 1/sqrt(HD).
// ----------------------------------------------------------------
__global__ __launch_bounds__(256) void normrope_kernel(
    const float* __restrict__ gq, const float* __restrict__ gk,
    const float* __restrict__ freqs)
{
    const int tok = blockIdx.x;
    const int t   = threadIdx.x;
    const float* qr = g_q + (size_t)tok * DIM;
    const float* kr = g_k + (size_t)tok * DIM;
    __half* qh = g_qh + (size_t)tok * DIM;
    __half* kh = g_kh + (size_t)tok * DIM;

    __shared__ float red[16];
    __shared__ float s_scq, s_sck;

    float sq = 0.f, sk = 0.f;
    for (int i = t; i < DIM; i += 256) {
        float a = qr[i]; sq += a * a;
        float b = kr[i]; sk += b * b;
    }
    #pragma unroll
    for (int m = 16; m >= 1; m >>= 1) {
        sq += __shfl_xor_sync(0xffffffffu, sq, m);
        sk += __shfl_xor_sync(0xffffffffu, sk, m);
    }
    if ((t & 31) == 0) { red[t >> 5] = sq; red[8 + (t >> 5)] = sk; }
    __syncthreads();
    if (t == 0) {
        float a = 0.f, b = 0.f;
        #pragma unroll
        for (int w = 0; w < 8; ++w) { a += red[w]; b += red[8 + w]; }
        s_scq = rsqrtf(a * (1.f / DIM) + 1e-6f);
        s_sck = rsqrtf(b * (1.f / DIM) + 1e-6f);
    }
    __syncthreads();
    const float scq = s_scq * 0.08838834764831845f;   // fold attn scale
    const float sck = s_sck;

    for (int p = t; p < DIM / 2; p += 256) {
        int hh = p >> 6, i = p & 63;
        int c0 = hh * HD + 2 * i;
        float fr = freqs[(size_t)tok * (HD / 2) + i];
        float cs = cosf(fr), sn = sinf(fr);
        float qe = qr[c0] * scq * gq[c0];
        float qo = qr[c0 + 1] * scq * gq[c0 + 1];
        *(uint32_t*)&qh[c0] = f2h2(qe * cs - qo * sn, qe * sn + qo * cs);
        float ke = kr[c0] * sck * gk[c0];
        float ko = kr[c0 + 1] * sck * gk[c0 + 1];
        *(uint32_t*)&kh[c0] = f2h2(ke * cs - ko * sn, ke * sn + ko * cs);
    }
}

// ================= fp16 tensor-core flash attention ==============
// BM=128 q rows (8 warps x 16), BN=64 kv, HD=128. m16n8k16.
// Ks: [64 tok][68w] (k halves), VsT: [128 d][36w] half2(tok even, odd)
// with col rotation (tp + d>>2)&31. Ps: [128 q][36w] half toks.
#define ABM 128
#define ABN 64
#define KSTW 68
#define VSTW 36
#define PSTW 36
#define ATTN_SMEM ((64 * KSTW + 128 * VSTW + 128 * PSTW) * 4)

__global__ __launch_bounds__(256) void attn_f16_kernel()
{
    extern __shared__ uint32_t smw[];
    uint32_t* Ks  = smw;                    // 64*68 words
    uint32_t* VsT = Ks + 64 * KSTW;         // 128*36 words
    uint32_t* Ps  = VsT + 128 * VSTW;       // 128*36 words
    const uint32_t sKs = smem_u32(Ks);

    const int t    = threadIdx.x;
    const int lane = t & 31;
    const int w    = t >> 5;
    const int fr   = lane >> 2;
    const int fc   = lane & 3;
    const int mt = blockIdx.x, f = blockIdx.y, h = blockIdx.z;
    const int q0 = f * IMG + mt * ABM;
    int st = f - 7; st = st < 0 ? 0 : (st > 6 ? 6 : st);
    const int kbase = st * IMG;

    // ---- preload Q as fp16 A-fragments (scale already folded) ----
    uint32_t qf[8][4];
    {
        const __half* Q0 = g_qh + (size_t)(q0 + 16 * w + fr) * DIM + h * HD;
        const __half* Q8 = Q0 + 8 * DIM;
        #pragma unroll
        for (int ks = 0; ks < 8; ++ks) {
            const int kc = ks * 16;
            qf[ks][0] = *(const uint32_t*)&Q0[kc + 2 * fc];
            qf[ks][1] = *(const uint32_t*)&Q8[kc + 2 * fc];
            qf[ks][2] = *(const uint32_t*)&Q0[kc + 2 * fc + 8];
            qf[ks][3] = *(const uint32_t*)&Q8[kc + 2 * fc + 8];
        }
    }

    float o[16][4];
    #pragma unroll
    for (int nf = 0; nf < 16; ++nf)
        #pragma unroll
        for (int r = 0; r < 4; ++r) o[nf][r] = 0.f;
    float Mlo = -INFINITY, Mhi = -INFINITY, Llo = 0.f, Lhi = 0.f;

    const int prow0 = (16 * w + fr) * PSTW;
    const int prow8 = (16 * w + fr + 8) * PSTW;

    for (int c = 0; c < WKV / ABN; ++c) {
        __syncthreads();
        const int kb = kbase + c * ABN;

        // K: cp.async 64 rows x 128 halves (256B/row, 16 chunks)
        #pragma unroll
        for (int i = 0; i < 4; ++i) {
            int idx = t + i * 256;              // 0..1023
            int row = idx >> 4, c16 = idx & 15;
            CP_ASYNC16(sKs + (uint32_t)(row * KSTW + c16 * 4) * 4,
                       g_kh + (size_t)(kb + row) * DIM + h * HD + c16 * 8);
        }
        CP_COMMIT();

        // V: transpose into half2(tok even, tok odd) with rotation
        #pragma unroll
        for (int i = 0; i < 4; ++i) {
            int idx = t + i * 256;              // 0..1023
            int tp = idx >> 5, dg = idx & 31;   // tok pair, d-group of 4
            const __half* v0 = g_vh + (size_t)(kb + 2 * tp) * DIM + h * HD + dg * 4;
            uint2 a = *(const uint2*)v0;
            uint2 b = *(const uint2*)(v0 + DIM);
            int col = (tp + dg) & 31;
            uint32_t* dst = VsT + (dg * 4) * VSTW + col;
            dst[0 * VSTW] = (a.x & 0xFFFFu) | (b.x << 16);
            dst[1 * VSTW] = (a.x >> 16) | (b.x & 0xFFFF0000u);
            dst[2 * VSTW] = (a.y & 0xFFFFu) | (b.y << 16);
            dst[3 * VSTW] = (a.y >> 16) | (b.y & 0xFFFF0000u);
        }
        CP_WAIT0();
        __syncthreads();

        // ---- S = Q K^T (16 x 64 per warp) ----
        float s[8][4];
        #pragma unroll
        for (int nf = 0; nf < 8; ++nf)
            #pragma unroll
            for (int r = 0; r < 4; ++r) s[nf][r] = 0.f;

        #pragma unroll
        for (int ks = 0; ks < 8; ++ks) {
            const int kw = ks * 8;
            #pragma unroll
            for (int nf = 0; nf < 8; ++nf) {
                const uint32_t* p = Ks + (8 * nf + fr) * KSTW + kw;
                uint32_t b[2] = { p[fc], p[fc + 4] };
                MMA_F16(s[nf], qf[ks], b);
            }
        }

        // ---- online softmax (warp-private rows) ----
        float mlo = -INFINITY, mhi = -INFINITY;
        #pragma unroll
        for (int nf = 0; nf < 8; ++nf) {
            mlo = fmaxf(mlo, fmaxf(s[nf][0], s[nf][1]));
            mhi = fmaxf(mhi, fmaxf(s[nf][2], s[nf][3]));
        }
        mlo = fmaxf(mlo, __shfl_xor_sync(0xffffffffu, mlo, 1));
        mlo = fmaxf(mlo, __shfl_xor_sync(0xffffffffu, mlo, 2));
        mhi = fmaxf(mhi, __shfl_xor_sync(0xffffffffu, mhi, 1));
        mhi = fmaxf(mhi, __shfl_xor_sync(0xffffffffu, mhi, 2));
        const float Mnlo = fmaxf(Mlo, mlo), Mnhi = fmaxf(Mhi, mhi);
        const float alo = __expf(Mlo - Mnlo), ahi = __expf(Mhi - Mnhi);
        Mlo = Mnlo; Mhi = Mnhi;

        float rlo = 0.f, rhi = 0.f;
        #pragma unroll
        for (int nf = 0; nf < 8; ++nf) {
            __half h0 = __float2half_rn(__expf(s[nf][0] - Mnlo));
            __half h1 = __float2half_rn(__expf(s[nf][1] - Mnlo));
            __half h2 = __float2half_rn(__expf(s[nf][2] - Mnhi));
            __half h3 = __float2half_rn(__expf(s[nf][3] - Mnhi));
            rlo += __half2float(h0) + __half2float(h1);
            rhi += __half2float(h2) + __half2float(h3);
            Ps[prow0 + 4 * nf + fc] =
                (uint32_t)__half_as_ushort(h0) | ((uint32_t)__half_as_ushort(h1) << 16);
            Ps[prow8 + 4 * nf + fc] =
                (uint32_t)__half_as_ushort(h2) | ((uint32_t)__half_as_ushort(h3) << 16);
        }
        rlo += __shfl_xor_sync(0xffffffffu, rlo, 1);
        rlo += __shfl_xor_sync(0xffffffffu, rlo, 2);
        rhi += __shfl_xor_sync(0xffffffffu, rhi, 1);
        rhi += __shfl_xor_sync(0xffffffffu, rhi, 2);
        Llo = Llo * alo + rlo;
        Lhi = Lhi * ahi + rhi;
        #pragma unroll
        for (int nf = 0; nf < 16; ++nf) {
            o[nf][0] *= alo; o[nf][1] *= alo;
            o[nf][2] *= ahi; o[nf][3] *= ahi;
        }
        __syncwarp();

        // ---- O += P V  (4 k16 steps over 64 toks) ----
        #pragma unroll
        for (int k2 = 0; k2 < 4; ++k2) {
            uint32_t a[4];
            a[0] = Ps[prow0 + 8 * k2 + fc];
            a[1] = Ps[prow8 + 8 * k2 + fc];
            a[2] = Ps[prow0 + 8 * k2 + fc + 4];
            a[3] = Ps[prow8 + 8 * k2 + fc + 4];
            #pragma unroll
            for (int nf = 0; nf < 16; ++nf) {
                const int d = 8 * nf + fr;
                const int rot = d >> 2;
                uint32_t b[2];
                b[0] = VsT[d * VSTW + ((fc + 8 * k2 + rot) & 31)];
                b[1] = VsT[d * VSTW + ((fc + 4 + 8 * k2 + rot) & 31)];
                MMA_F16(o[nf], a, b);
            }
        }
        __syncwarp();
    }

    // ---- epilogue: normalize, write half ----
    const float il = 1.f / Llo, ih = 1.f / Lhi;
    const int row0 = q0 + 16 * w + fr;
    #pragma unroll
    for (int nf = 0; nf < 16; ++nf) {
        const int col = h * HD + 8 * nf + 2 * fc;
        *(uint32_t*)&g_attnh[(size_t)row0 * DIM + col] =
            f2h2(o[nf][0] * il, o[nf][1] * il);
        *(uint32_t*)&g_attnh[(size_t)(row0 + 8) * DIM + col] =
            f2h2(o[nf][2] * ih, o[nf][3] * ih);
    }
}

// ----------------------------------------------------------------
extern "C" void kernel_launch(void* const* d_in, const int* in_sizes, int n_in,
                              void* d_out, int out_size)
{
    const float* x     = (const float*)d_in[0];
    const float* freqs = (const float*)d_in[1];
    const float* Wq    = (const float*)d_in[2];
    const float* bq    = (const float*)d_in[3];
    const float* Wk    = (const float*)d_in[4];
    const float* bk    = (const float*)d_in[5];
    const float* Wv    = (const float*)d_in[6];
    const float* bv    = (const float*)d_in[7];
    const float* Wo    = (const float*)d_in[8];
    const float* bo    = (const float*)d_in[9];
    const float* gq    = (const float*)d_in[10];
    const float* gk    = (const float*)d_in[11];
    float* out = (float*)d_out;

    void *pq, *pk, *pxh, *pwh, *pvh, *pah;
    cudaGetSymbolAddress(&pq, g_q);
    cudaGetSymbolAddress(&pk, g_k);
    cudaGetSymbolAddress(&pxh, g_xh);
    cudaGetSymbolAddress(&pwh, g_wh);
    cudaGetSymbolAddress(&pvh, g_vh);
    cudaGetSymbolAddress(&pah, g_attnh);
    __half* xh = (__half*)pxh;
    __half* wh = (__half*)pwh;

    // convert inputs to fp16
    const int NW4 = DIM * DIM / 4;
    cvt_half_kernel<<<1184, 256>>>((const float4*)x, (uint2*)xh, S_TOK * DIM / 4);
    cvt_half_kernel<<<592, 256>>>((const float4*)Wq, (uint2*)(wh + 0 * (size_t)DIM * DIM), NW4);
    cvt_half_kernel<<<592, 256>>>((const float4*)Wk, (uint2*)(wh + 1 * (size_t)DIM * DIM), NW4);
    cvt_half_kernel<<<592, 256>>>((const float4*)Wv, (uint2*)(wh + 2 * (size_t)DIM * DIM), NW4);
    cvt_half_kernel<<<592, 256>>>((const float4*)Wo, (uint2*)(wh + 3 * (size_t)DIM * DIM), NW4);

    cudaFuncSetAttribute(f16_gemm_qkv, cudaFuncAttributeMaxDynamicSharedMemorySize, GEMM_SMEM);
    cudaFuncSetAttribute(f16_gemm_nt, cudaFuncAttributeMaxDynamicSharedMemorySize, GEMM_SMEM);

    f16_gemm_qkv<<<dim3(36, S_TOK / 128), 256, GEMM_SMEM>>>(
        xh, wh, bq, bk, bv, (float*)pq, (float*)pk, (__half*)pvh);

    normrope_kernel<<<S_TOK, 256>>>(gq, gk, freqs);

    cudaFuncSetAttribute(attn_f16_kernel, cudaFuncAttributeMaxDynamicSharedMemorySize, ATTN_SMEM);
    attn_f16_kernel<<<dim3(IMG / ABM, NF, NH), 256, ATTN_SMEM>>>();

    f16_gemm_nt<<<dim3(12, S_TOK / 128), 256, GEMM_SMEM>>>(
        (const __half*)pah, wh + 3 * (size_t)DIM * DIM, bo, out, S_TOK, DIM, DIM);
}

// round 10
// speedup vs baseline: 6.1401x; 1.2065x over previous
#include <cuda_runtime.h>
#include <cuda_fp16.h>
#include <math.h>
#include <stdint.h>

#define S_TOK 5376
#define DIM   1536
#define NH    12
#define HD    128
#define NF    21
#define IMG   256
#define WKV   3840

// -------- scratch (device-global; no allocation allowed) --------
__device__ float  g_q[(size_t)S_TOK * DIM];          // fp32 q (pre-norm)
__device__ float  g_k[(size_t)S_TOK * DIM];          // fp32 k (pre-norm)
__device__ __half g_xh[(size_t)S_TOK * DIM];         // half x
__device__ __half g_wh[(size_t)4 * DIM * DIM];       // half Wq,Wk,Wv,Wo concat
__device__ __half g_qh[(size_t)S_TOK * DIM];         // half q (post rope, scaled)
__device__ __half g_kh[(size_t)S_TOK * DIM];         // half k (post rope)
__device__ __half g_vh[(size_t)S_TOK * DIM];         // half v
__device__ __half g_attnh[(size_t)S_TOK * DIM];      // half attention output

__device__ __forceinline__ uint32_t f2h2(float lo, float hi) {
    uint32_t r;
    asm("{ .reg .f16 l, h; cvt.rn.f16.f32 l, %1; cvt.rn.f16.f32 h, %2; mov.b32 %0, {l, h}; }"
        : "=r"(r) : "f"(lo), "f"(hi));
    return r;
}
__device__ __forceinline__ uint32_t smem_u32(const void* p) {
    uint32_t a;
    asm("{ .reg .u64 t; cvta.to.shared.u64 t, %1; cvt.u32.u64 %0, t; }" : "=r"(a) : "l"(p));
    return a;
}

#define MMA_F16(c, a, b) \
    asm volatile("mma.sync.aligned.m16n8k16.row.col.f32.f16.f16.f32 " \
                 "{%0,%1,%2,%3}, {%4,%5,%6,%7}, {%8,%9}, {%0,%1,%2,%3};" \
                 : "+f"((c)[0]), "+f"((c)[1]), "+f"((c)[2]), "+f"((c)[3]) \
                 : "r"((a)[0]), "r"((a)[1]), "r"((a)[2]), "r"((a)[3]), \
                   "r"((b)[0]), "r"((b)[1]))

#define LDSM_X4_TRANS(r0, r1, r2, r3, addr) \
    asm volatile("ldmatrix.sync.aligned.m8n8.x4.trans.shared.b16 {%0,%1,%2,%3}, [%4];" \
                 : "=r"(r0), "=r"(r1), "=r"(r2), "=r"(r3) : "r"(addr))

#define CP_ASYNC16(dst, src) \
    asm volatile("cp.async.cg.shared.global [%0], [%1], 16;" :: "r"(dst), "l"(src))
#define CP_COMMIT() asm volatile("cp.async.commit_group;" ::: "memory")
#define CP_WAIT0()  asm volatile("cp.async.wait_group 0;" ::: "memory")
#define CP_WAIT1()  asm volatile("cp.async.wait_group 1;" ::: "memory")

// ---------------- fp32 -> fp16 conversion pass -------------------
__global__ __launch_bounds__(256) void cvt_half_kernel(
    const float4* __restrict__ in, uint2* __restrict__ out, int n4)
{
    for (int i = blockIdx.x * blockDim.x + threadIdx.x; i < n4;
         i += gridDim.x * blockDim.x) {
        float4 v = in[i];
        out[i] = make_uint2(f2h2(v.x, v.y), f2h2(v.z, v.w));
    }
}

// ================= fp16 mma.sync GEMM (NT) =======================
// C[m][n] = sum_k A[m][k]*B[n][k] (+bias). A,B half, k-contiguous.
// CTA tile 256x128, K-chunk 32 halves, 512 threads, 16 warps (4x4),
// warp tile 64x32, 3-stage cp.async pipeline.
#define GBM 256
#define GBN 128
#define GBK 32
#define AST 20                        // words per row (16 data + 4 pad)
#define GTILE_A (256 * AST)           // 5120 words
#define GTILE_B (128 * AST)           // 2560 words
#define GSTAGE  (GTILE_A + GTILE_B)   // 7680 words per stage
#define GEMM_SMEM (3 * GSTAGE * 4)    // 92160 B

struct GemmCore {
    const __half* A; const __half* B; int K; int m0; int n0;
    uint32_t sBase;
    int lrow, lc16;
    __device__ __forceinline__ void load_async(int stage, int k0) const {
        uint32_t sb = sBase + (uint32_t)(stage * GSTAGE) * 4;
        CP_ASYNC16(sb + (uint32_t)(lrow * AST + lc16 * 4) * 4,
                   A + (size_t)(m0 + lrow) * K + k0 + lc16 * 8);
        CP_ASYNC16(sb + (uint32_t)((lrow + 128) * AST + lc16 * 4) * 4,
                   A + (size_t)(m0 + lrow + 128) * K + k0 + lc16 * 8);
        CP_ASYNC16(sb + (uint32_t)(GTILE_A + lrow * AST + lc16 * 4) * 4,
                   B + (size_t)(n0 + lrow) * K + k0 + lc16 * 8);
        CP_COMMIT();
    }
};

__device__ __forceinline__ void gemm_chunk_f16(
    const uint32_t* __restrict__ Ab, const uint32_t* __restrict__ Bb,
    int wm, int wn, int fr, int fc, float acc[4][4][4])
{
    #pragma unroll
    for (int ks = 0; ks < 2; ++ks) {
        const int kw = ks * 8;
        uint32_t af[4][4];
        #pragma unroll
        for (int mi = 0; mi < 4; ++mi) {
            const uint32_t* p = Ab + (wm + mi * 16) * AST + kw;
            af[mi][0] = p[fr * AST + fc];
            af[mi][1] = p[(fr + 8) * AST + fc];
            af[mi][2] = p[fr * AST + fc + 4];
            af[mi][3] = p[(fr + 8) * AST + fc + 4];
        }
        uint32_t bf[4][2];
        #pragma unroll
        for (int ni = 0; ni < 4; ++ni) {
            const uint32_t* p = Bb + (wn + ni * 8 + fr) * AST + kw;
            bf[ni][0] = p[fc];
            bf[ni][1] = p[fc + 4];
        }
        #pragma unroll
        for (int mi = 0; mi < 4; ++mi)
            #pragma unroll
            for (int ni = 0; ni < 4; ++ni)
                MMA_F16(acc[mi][ni], af[mi], bf[ni]);
    }
}

#define GEMM_PROLOG_BODY(Aop, Bop, Kval)                                     \
    extern __shared__ uint32_t sm[];                                         \
    const int t    = threadIdx.x;                                            \
    const int lane = t & 31;                                                 \
    const int wid  = t >> 5;                                                 \
    const int wm   = (wid & 3) * 64;                                         \
    const int wn   = (wid >> 2) * 32;                                        \
    const int fr   = lane >> 2;                                              \
    const int fc   = lane & 3;                                               \
    float acc[4][4][4];                                                      \
    _Pragma("unroll")                                                        \
    for (int mi = 0; mi < 4; ++mi)                                           \
        _Pragma("unroll")                                                    \
        for (int ni = 0; ni < 4; ++ni)                                       \
            _Pragma("unroll")                                                \
            for (int r = 0; r < 4; ++r) acc[mi][ni][r] = 0.f;                \
    GemmCore core;                                                           \
    core.A = Aop; core.B = Bop; core.K = Kval; core.m0 = m0; core.n0 = n0;   \
    core.sBase = smem_u32(sm);                                               \
    core.lrow = t >> 2; core.lc16 = t & 3;                                   \
    const int NCH = (Kval) / GBK;                                            \
    core.load_async(0, 0);                                                   \
    core.load_async(1, GBK);                                                 \
    for (int c = 0; c < NCH; ++c) {                                          \
        if (c + 1 < NCH) { CP_WAIT1(); } else { CP_WAIT0(); }                \
        __syncthreads();                                                     \
        if (c + 2 < NCH) core.load_async((c + 2) % 3, (c + 2) * GBK);        \
        const int stg = c % 3;                                               \
        gemm_chunk_f16(&sm[stg * GSTAGE], &sm[stg * GSTAGE + GTILE_A],       \
                       wm, wn, fr, fc, acc);                                 \
    }

// ---- O-projection GEMM: half inputs, fp32 output + bias ----
__global__ __launch_bounds__(512, 1) void f16_gemm_nt(
    const __half* __restrict__ A, const __half* __restrict__ B,
    const float* __restrict__ bias, float* __restrict__ C,
    int M, int N, int K)
{
    const int m0 = blockIdx.y * GBM;
    const int n0 = blockIdx.x * GBN;
    GEMM_PROLOG_BODY(A, B, K)

    const int c2 = fc * 2;
    #pragma unroll
    for (int mi = 0; mi < 4; ++mi) {
        #pragma unroll
        for (int ni = 0; ni < 4; ++ni) {
            int row = m0 + wm + mi * 16 + fr;
            int col = n0 + wn + ni * 8 + c2;
            float b0 = bias[col], b1 = bias[col + 1];
            *(float2*)&C[(size_t)row * N + col] =
                make_float2(acc[mi][ni][0] + b0, acc[mi][ni][1] + b1);
            *(float2*)&C[(size_t)(row + 8) * N + col] =
                make_float2(acc[mi][ni][2] + b0, acc[mi][ni][3] + b1);
        }
    }
}

// ---- fused QKV GEMM: q,k -> fp32; v -> half ----
__global__ __launch_bounds__(512, 1) void f16_gemm_qkv(
    const __half* __restrict__ A, const __half* __restrict__ Bw,
    const float* __restrict__ bq, const float* __restrict__ bk,
    const float* __restrict__ bv,
    float* __restrict__ Cq, float* __restrict__ Ck, __half* __restrict__ Cv)
{
    const int m0 = blockIdx.y * GBM;
    const int n0 = blockIdx.x * GBN;
    GEMM_PROLOG_BODY(A, Bw, DIM)

    const int which = blockIdx.x / 12;         // 0=q 1=k 2=v
    const int ncol0 = (blockIdx.x % 12) * 128;
    const int c2 = fc * 2;
    if (which == 2) {
        #pragma unroll
        for (int mi = 0; mi < 4; ++mi)
            #pragma unroll
            for (int ni = 0; ni < 4; ++ni) {
                int row = m0 + wm + mi * 16 + fr;
                int col = ncol0 + wn + ni * 8 + c2;
                float b0 = bv[col], b1 = bv[col + 1];
                *(uint32_t*)&g_vh[(size_t)row * DIM + col] =
                    f2h2(acc[mi][ni][0] + b0, acc[mi][ni][1] + b1);
                *(uint32_t*)&g_vh[(size_t)(row + 8) * DIM + col] =
                    f2h2(acc[mi][ni][2] + b0, acc[mi][ni][3] + b1);
            }
    } else {
        float* C = which == 0 ? Cq : Ck;
        const float* bias = which == 0 ? bq : bk;
        #pragma unroll
        for (int mi = 0; mi < 4; ++mi)
            #pragma unroll
            for (int ni = 0; ni < 4; ++ni) {
                int row = m0 + wm + mi * 16 + fr;
                int col = ncol0 + wn + ni * 8 + c2;
                float b0 = bias[col], b1 = bias[col + 1];
                *(float2*)&C[(size_t)row * DIM + col] =
                    make_float2(acc[mi][ni][0] + b0, acc[mi][ni][1] + b1);
                *(float2*)&C[(size_t)(row + 8) * DIM + col] =
                    make_float2(acc[mi][ni][2] + b0, acc[mi][ni][3] + b1);
            }
    }
}

// ----------------------------------------------------------------
// Fused RMSNorm (with gains) + RoPE: fp32 in -> half out.
// q additionally scaled by 1/sqrt(HD).
// ----------------------------------------------------------------
__global__ __launch_bounds__(256) void normrope_kernel(
    const float* __restrict__ gq, const float* __restrict__ gk,
    const float* __restrict__ freqs)
{
    const int tok = blockIdx.x;
    const int t   = threadIdx.x;
    const float* qr = g_q + (size_t)tok * DIM;
    const float* kr = g_k + (size_t)tok * DIM;
    __half* qh = g_qh + (size_t)tok * DIM;
    __half* kh = g_kh + (size_t)tok * DIM;

    __shared__ float red[16];
    __shared__ float s_scq, s_sck;

    float sq = 0.f, sk = 0.f;
    for (int i = t; i < DIM; i += 256) {
        float a = qr[i]; sq += a * a;
        float b = kr[i]; sk += b * b;
    }
    #pragma unroll
    for (int m = 16; m >= 1; m >>= 1) {
        sq += __shfl_xor_sync(0xffffffffu, sq, m);
        sk += __shfl_xor_sync(0xffffffffu, sk, m);
    }
    if ((t & 31) == 0) { red[t >> 5] = sq; red[8 + (t >> 5)] = sk; }
    __syncthreads();
    if (t == 0) {
        float a = 0.f, b = 0.f;
        #pragma unroll
        for (int w = 0; w < 8; ++w) { a += red[w]; b += red[8 + w]; }
        s_scq = rsqrtf(a * (1.f / DIM) + 1e-6f);
        s_sck = rsqrtf(b * (1.f / DIM) + 1e-6f);
    }
    __syncthreads();
    const float scq = s_scq * 0.08838834764831845f;   // fold attn scale
    const float sck = s_sck;

    for (int p = t; p < DIM / 2; p += 256) {
        int hh = p >> 6, i = p & 63;
        int c0 = hh * HD + 2 * i;
        float fr = freqs[(size_t)tok * (HD / 2) + i];
        float cs = cosf(fr), sn = sinf(fr);
        float qe = qr[c0] * scq * gq[c0];
        float qo = qr[c0 + 1] * scq * gq[c0 + 1];
        *(uint32_t*)&qh[c0] = f2h2(qe * cs - qo * sn, qe * sn + qo * cs);
        float ke = kr[c0] * sck * gk[c0];
        float ko = kr[c0 + 1] * sck * gk[c0 + 1];
        *(uint32_t*)&kh[c0] = f2h2(ke * cs - ko * sn, ke * sn + ko * cs);
    }
}

// ================= fp16 tensor-core flash attention ==============
// BM=128 q rows (8 warps x 16), BN=64 kv, HD=128. m16n8k16.
// K,V staged verbatim ([tok][d], stride 68w) via cp.async, double
// buffered. PV B-frags via ldmatrix.x4.trans. Ps: [128 q][36w].
#define ABM 128
#define ABN 64
#define KSTW 68
#define KVTILE (64 * KSTW)            // words per K (or V) buffer
#define PSTW 36
#define ATTN_SMEM ((4 * KVTILE + 128 * PSTW) * 4)   // 88064 B

__global__ __launch_bounds__(256) void attn_f16_kernel()
{
    extern __shared__ uint32_t smw[];
    uint32_t* Ps = smw + 4 * KVTILE;
    const uint32_t sBase = smem_u32(smw);

    const int t    = threadIdx.x;
    const int lane = t & 31;
    const int w    = t >> 5;
    const int fr   = lane >> 2;
    const int fc   = lane & 3;
    const int mt = blockIdx.x, f = blockIdx.y, h = blockIdx.z;
    const int q0 = f * IMG + mt * ABM;
    int st = f - 7; st = st < 0 ? 0 : (st > 6 ? 6 : st);
    const int kbase = st * IMG;

    // per-thread ldmatrix base offset within a V buffer (words):
    // row = lane&15, d-block = 8*(lane>>4) halves = 4*(lane>>4) words
    const uint32_t vofs = (uint32_t)((lane & 15) * KSTW + 4 * (lane >> 4)) * 4;

    // ---- preload Q as fp16 A-fragments (scale folded upstream) ----
    uint32_t qf[8][4];
    {
        const __half* Q0 = g_qh + (size_t)(q0 + 16 * w + fr) * DIM + h * HD;
        const __half* Q8 = Q0 + 8 * DIM;
        #pragma unroll
        for (int ks = 0; ks < 8; ++ks) {
            const int kc = ks * 16;
            qf[ks][0] = *(const uint32_t*)&Q0[kc + 2 * fc];
            qf[ks][1] = *(const uint32_t*)&Q8[kc + 2 * fc];
            qf[ks][2] = *(const uint32_t*)&Q0[kc + 2 * fc + 8];
            qf[ks][3] = *(const uint32_t*)&Q8[kc + 2 * fc + 8];
        }
    }

    float o[16][4];
    #pragma unroll
    for (int nf = 0; nf < 16; ++nf)
        #pragma unroll
        for (int r = 0; r < 4; ++r) o[nf][r] = 0.f;
    float Mlo = -INFINITY, Mhi = -INFINITY, Llo = 0.f, Lhi = 0.f;

    const int prow0 = (16 * w + fr) * PSTW;
    const int prow8 = (16 * w + fr + 8) * PSTW;

    // stage K+V for kv-tile cc into buffer buf
    auto stage_kv = [&](int buf, int cc) {
        const int kb = kbase + cc * ABN;
        const uint32_t sK = sBase + (uint32_t)(buf * 2 * KVTILE) * 4;
        const uint32_t sV = sK + (uint32_t)KVTILE * 4;
        #pragma unroll
        for (int i = 0; i < 4; ++i) {
            int idx = t + i * 256;              // 0..1023
            int row = idx >> 4, c16 = idx & 15;
            uint32_t off = (uint32_t)(row * KSTW + c16 * 4) * 4;
            CP_ASYNC16(sK + off, g_kh + (size_t)(kb + row) * DIM + h * HD + c16 * 8);
            CP_ASYNC16(sV + off, g_vh + (size_t)(kb + row) * DIM + h * HD + c16 * 8);
        }
        CP_COMMIT();
    };

    stage_kv(0, 0);

    for (int c = 0; c < WKV / ABN; ++c) {
        CP_WAIT0();
        __syncthreads();            // tile c resident; prev compute done
        if (c + 1 < WKV / ABN) stage_kv((c + 1) & 1, c + 1);

        const uint32_t* Kb = smw + (c & 1) * 2 * KVTILE;
        const uint32_t vbase = sBase + (uint32_t)((c & 1) * 2 * KVTILE + KVTILE) * 4 + vofs;

        // ---- S = Q K^T (16 x 64 per warp) ----
        float s[8][4];
        #pragma unroll
        for (int nf = 0; nf < 8; ++nf)
            #pragma unroll
            for (int r = 0; r < 4; ++r) s[nf][r] = 0.f;

        #pragma unroll
        for (int ks = 0; ks < 8; ++ks) {
            const int kw = ks * 8;
            #pragma unroll
            for (int nf = 0; nf < 8; ++nf) {
                const uint32_t* p = Kb + (8 * nf + fr) * KSTW + kw;
                uint32_t b[2] = { p[fc], p[fc + 4] };
                MMA_F16(s[nf], qf[ks], b);
            }
        }

        // ---- online softmax (warp-private rows) ----
        float mlo = -INFINITY, mhi = -INFINITY;
        #pragma unroll
        for (int nf = 0; nf < 8; ++nf) {
            mlo = fmaxf(mlo, fmaxf(s[nf][0], s[nf][1]));
            mhi = fmaxf(mhi, fmaxf(s[nf][2], s[nf][3]));
        }
        mlo = fmaxf(mlo, __shfl_xor_sync(0xffffffffu, mlo, 1));
        mlo = fmaxf(mlo, __shfl_xor_sync(0xffffffffu, mlo, 2));
        mhi = fmaxf(mhi, __shfl_xor_sync(0xffffffffu, mhi, 1));
        mhi = fmaxf(mhi, __shfl_xor_sync(0xffffffffu, mhi, 2));
        const float Mnlo = fmaxf(Mlo, mlo), Mnhi = fmaxf(Mhi, mhi);
        const float alo = __expf(Mlo - Mnlo), ahi = __expf(Mhi - Mnhi);
        Mlo = Mnlo; Mhi = Mnhi;

        float rlo = 0.f, rhi = 0.f;
        #pragma unroll
        for (int nf = 0; nf < 8; ++nf) {
            __half h0 = __float2half_rn(__expf(s[nf][0] - Mnlo));
            __half h1 = __float2half_rn(__expf(s[nf][1] - Mnlo));
            __half h2 = __float2half_rn(__expf(s[nf][2] - Mnhi));
            __half h3 = __float2half_rn(__expf(s[nf][3] - Mnhi));
            rlo += __half2float(h0) + __half2float(h1);
            rhi += __half2float(h2) + __half2float(h3);
            Ps[prow0 + 4 * nf + fc] =
                (uint32_t)__half_as_ushort(h0) | ((uint32_t)__half_as_ushort(h1) << 16);
            Ps[prow8 + 4 * nf + fc] =
                (uint32_t)__half_as_ushort(h2) | ((uint32_t)__half_as_ushort(h3) << 16);
        }
        rlo += __shfl_xor_sync(0xffffffffu, rlo, 1);
        rlo += __shfl_xor_sync(0xffffffffu, rlo, 2);
        rhi += __shfl_xor_sync(0xffffffffu, rhi, 1);
        rhi += __shfl_xor_sync(0xffffffffu, rhi, 2);
        Llo = Llo * alo + rlo;
        Lhi = Lhi * ahi + rhi;
        #pragma unroll
        for (int nf = 0; nf < 16; ++nf) {
            o[nf][0] *= alo; o[nf][1] *= alo;
            o[nf][2] *= ahi; o[nf][3] *= ahi;
        }
        __syncwarp();

        // ---- O += P V  (B-frags via ldmatrix.trans) ----
        #pragma unroll
        for (int k2 = 0; k2 < 4; ++k2) {
            uint32_t a[4];
            a[0] = Ps[prow0 + 8 * k2 + fc];
            a[1] = Ps[prow8 + 8 * k2 + fc];
            a[2] = Ps[prow0 + 8 * k2 + fc + 4];
            a[3] = Ps[prow8 + 8 * k2 + fc + 4];
            #pragma unroll
            for (int nfp = 0; nfp < 8; ++nfp) {
                uint32_t b0, b1, b2, b3;
                LDSM_X4_TRANS(b0, b1, b2, b3,
                              vbase + (uint32_t)(k2 * 16 * KSTW + 8 * nfp) * 4);
                uint32_t lo[2] = { b0, b1 };
                MMA_F16(o[2 * nfp], a, lo);
                uint32_t hi2[2] = { b2, b3 };
                MMA_F16(o[2 * nfp + 1], a, hi2);
            }
        }
        __syncwarp();
    }

    // ---- epilogue: normalize, write half ----
    const float il = 1.f / Llo, ih = 1.f / Lhi;
    const int row0 = q0 + 16 * w + fr;
    #pragma unroll
    for (int nf = 0; nf < 16; ++nf) {
        const int col = h * HD + 8 * nf + 2 * fc;
        *(uint32_t*)&g_attnh[(size_t)row0 * DIM + col] =
            f2h2(o[nf][0] * il, o[nf][1] * il);
        *(uint32_t*)&g_attnh[(size_t)(row0 + 8) * DIM + col] =
            f2h2(o[nf][2] * ih, o[nf][3] * ih);
    }
}

// ----------------------------------------------------------------
extern "C" void kernel_launch(void* const* d_in, const int* in_sizes, int n_in,
                              void* d_out, int out_size)
{
    const float* x     = (const float*)d_in[0];
    const float* freqs = (const float*)d_in[1];
    const float* Wq    = (const float*)d_in[2];
    const float* bq    = (const float*)d_in[3];
    const float* Wk    = (const float*)d_in[4];
    const float* bk    = (const float*)d_in[5];
    const float* Wv    = (const float*)d_in[6];
    const float* bv    = (const float*)d_in[7];
    const float* Wo    = (const float*)d_in[8];
    const float* bo    = (const float*)d_in[9];
    const float* gq    = (const float*)d_in[10];
    const float* gk    = (const float*)d_in[11];
    float* out = (float*)d_out;

    void *pq, *pk, *pxh, *pwh, *pvh, *pah;
    cudaGetSymbolAddress(&pq, g_q);
    cudaGetSymbolAddress(&pk, g_k);
    cudaGetSymbolAddress(&pxh, g_xh);
    cudaGetSymbolAddress(&pwh, g_wh);
    cudaGetSymbolAddress(&pvh, g_vh);
    cudaGetSymbolAddress(&pah, g_attnh);
    __half* xh = (__half*)pxh;
    __half* wh = (__half*)pwh;

    // convert inputs to fp16
    const int NW4 = DIM * DIM / 4;
    cvt_half_kernel<<<1184, 256>>>((const float4*)x, (uint2*)xh, S_TOK * DIM / 4);
    cvt_half_kernel<<<592, 256>>>((const float4*)Wq, (uint2*)(wh + 0 * (size_t)DIM * DIM), NW4);
    cvt_half_kernel<<<592, 256>>>((const float4*)Wk, (uint2*)(wh + 1 * (size_t)DIM * DIM), NW4);
    cvt_half_kernel<<<592, 256>>>((const float4*)Wv, (uint2*)(wh + 2 * (size_t)DIM * DIM), NW4);
    cvt_half_kernel<<<592, 256>>>((const float4*)Wo, (uint2*)(wh + 3 * (size_t)DIM * DIM), NW4);

    cudaFuncSetAttribute(f16_gemm_qkv, cudaFuncAttributeMaxDynamicSharedMemorySize, GEMM_SMEM);
    cudaFuncSetAttribute(f16_gemm_nt, cudaFuncAttributeMaxDynamicSharedMemorySize, GEMM_SMEM);

    f16_gemm_qkv<<<dim3(36, S_TOK / 256), 512, GEMM_SMEM>>>(
        xh, wh, bq, bk, bv, (float*)pq, (float*)pk, (__half*)pvh);

    normrope_kernel<<<S_TOK, 256>>>(gq, gk, freqs);

    cudaFuncSetAttribute(attn_f16_kernel, cudaFuncAttributeMaxDynamicSharedMemorySize, ATTN_SMEM);
    attn_f16_kernel<<<dim3(IMG / ABM, NF, NH), 256, ATTN_SMEM>>>();

    f16_gemm_nt<<<dim3(12, S_TOK / 256), 512, GEMM_SMEM>>>(
        (const __half*)pah, wh + 3 * (size_t)DIM * DIM, bo, out, S_TOK, DIM, DIM);
}

// round 11
// speedup vs baseline: 6.1509x; 1.0018x over previous
#include <cuda_runtime.h>
#include <cuda_fp16.h>
#include <math.h>
#include <stdint.h>

#define S_TOK 5376
#define DIM   1536
#define NH    12
#define HD    128
#define NF    21
#define IMG   256
#define WKV   3840

// -------- scratch (device-global; no allocation allowed) --------
__device__ float  g_q[(size_t)S_TOK * DIM];          // fp32 q (pre-norm)
__device__ float  g_k[(size_t)S_TOK * DIM];          // fp32 k (pre-norm)
__device__ __half g_xh[(size_t)S_TOK * DIM];         // half x
__device__ __half g_wh[(size_t)4 * DIM * DIM];       // half Wq,Wk,Wv,Wo concat
__device__ __half g_qh[(size_t)S_TOK * DIM];         // half q (post rope, scaled)
__device__ __half g_kh[(size_t)S_TOK * DIM];         // half k (post rope)
__device__ __half g_vh[(size_t)S_TOK * DIM];         // half v
__device__ __half g_attnh[(size_t)S_TOK * DIM];      // half attention output

__device__ __forceinline__ uint32_t f2h2(float lo, float hi) {
    uint32_t r;
    asm("{ .reg .f16 l, h; cvt.rn.f16.f32 l, %1; cvt.rn.f16.f32 h, %2; mov.b32 %0, {l, h}; }"
        : "=r"(r) : "f"(lo), "f"(hi));
    return r;
}
__device__ __forceinline__ uint32_t smem_u32(const void* p) {
    uint32_t a;
    asm("{ .reg .u64 t; cvta.to.shared.u64 t, %1; cvt.u32.u64 %0, t; }" : "=r"(a) : "l"(p));
    return a;
}

#define MMA_F16(c, a, b) \
    asm volatile("mma.sync.aligned.m16n8k16.row.col.f32.f16.f16.f32 " \
                 "{%0,%1,%2,%3}, {%4,%5,%6,%7}, {%8,%9}, {%0,%1,%2,%3};" \
                 : "+f"((c)[0]), "+f"((c)[1]), "+f"((c)[2]), "+f"((c)[3]) \
                 : "r"((a)[0]), "r"((a)[1]), "r"((a)[2]), "r"((a)[3]), \
                   "r"((b)[0]), "r"((b)[1]))

#define LDSM_X4_TRANS(r0, r1, r2, r3, addr) \
    asm volatile("ldmatrix.sync.aligned.m8n8.x4.trans.shared.b16 {%0,%1,%2,%3}, [%4];" \
                 : "=r"(r0), "=r"(r1), "=r"(r2), "=r"(r3) : "r"(addr))

#define CP_ASYNC16(dst, src) \
    asm volatile("cp.async.cg.shared.global [%0], [%1], 16;" :: "r"(dst), "l"(src))
#define CP_COMMIT() asm volatile("cp.async.commit_group;" ::: "memory")
#define CP_WAIT0()  asm volatile("cp.async.wait_group 0;" ::: "memory")
#define CP_WAIT1()  asm volatile("cp.async.wait_group 1;" ::: "memory")

// ---------------- fp32 -> fp16 conversion pass -------------------
__global__ __launch_bounds__(256) void cvt_half_kernel(
    const float4* __restrict__ in, uint2* __restrict__ out, int n4)
{
    for (int i = blockIdx.x * blockDim.x + threadIdx.x; i < n4;
         i += gridDim.x * blockDim.x) {
        float4 v = in[i];
        out[i] = make_uint2(f2h2(v.x, v.y), f2h2(v.z, v.w));
    }
}

// ================= fp16 mma.sync GEMM (NT) =======================
// C[m][n] = sum_k A[m][k]*B[n][k] (+bias). A,B half, k-contiguous.
// CTA tile 256x128, K-chunk 32 halves, 512 threads, 16 warps (4x4),
// warp tile 64x32, 3-stage cp.async pipeline.
#define GBM 256
#define GBN 128
#define GBK 32
#define AST 20                        // words per row (16 data + 4 pad)
#define GTILE_A (256 * AST)           // 5120 words
#define GTILE_B (128 * AST)           // 2560 words
#define GSTAGE  (GTILE_A + GTILE_B)   // 7680 words per stage
#define GEMM_SMEM (3 * GSTAGE * 4)    // 92160 B

struct GemmCore {
    const __half* A; const __half* B; int K; int m0; int n0;
    uint32_t sBase;
    int lrow, lc16;
    __device__ __forceinline__ void load_async(int stage, int k0) const {
        uint32_t sb = sBase + (uint32_t)(stage * GSTAGE) * 4;
        CP_ASYNC16(sb + (uint32_t)(lrow * AST + lc16 * 4) * 4,
                   A + (size_t)(m0 + lrow) * K + k0 + lc16 * 8);
        CP_ASYNC16(sb + (uint32_t)((lrow + 128) * AST + lc16 * 4) * 4,
                   A + (size_t)(m0 + lrow + 128) * K + k0 + lc16 * 8);
        CP_ASYNC16(sb + (uint32_t)(GTILE_A + lrow * AST + lc16 * 4) * 4,
                   B + (size_t)(n0 + lrow) * K + k0 + lc16 * 8);
        CP_COMMIT();
    }
};

__device__ __forceinline__ void gemm_chunk_f16(
    const uint32_t* __restrict__ Ab, const uint32_t* __restrict__ Bb,
    int wm, int wn, int fr, int fc, float acc[4][4][4])
{
    #pragma unroll
    for (int ks = 0; ks < 2; ++ks) {
        const int kw = ks * 8;
        uint32_t af[4][4];
        #pragma unroll
        for (int mi = 0; mi < 4; ++mi) {
            const uint32_t* p = Ab + (wm + mi * 16) * AST + kw;
            af[mi][0] = p[fr * AST + fc];
            af[mi][1] = p[(fr + 8) * AST + fc];
            af[mi][2] = p[fr * AST + fc + 4];
            af[mi][3] = p[(fr + 8) * AST + fc + 4];
        }
        uint32_t bf[4][2];
        #pragma unroll
        for (int ni = 0; ni < 4; ++ni) {
            const uint32_t* p = Bb + (wn + ni * 8 + fr) * AST + kw;
            bf[ni][0] = p[fc];
            bf[ni][1] = p[fc + 4];
        }
        #pragma unroll
        for (int mi = 0; mi < 4; ++mi)
            #pragma unroll
            for (int ni = 0; ni < 4; ++ni)
                MMA_F16(acc[mi][ni], af[mi], bf[ni]);
    }
}

#define GEMM_PROLOG_BODY(Aop, Bop, Kval)                                     \
    extern __shared__ uint32_t sm[];                                         \
    const int t    = threadIdx.x;                                            \
    const int lane = t & 31;                                                 \
    const int wid  = t >> 5;                                                 \
    const int wm   = (wid & 3) * 64;                                         \
    const int wn   = (wid >> 2) * 32;                                        \
    const int fr   = lane >> 2;                                              \
    const int fc   = lane & 3;                                               \
    float acc[4][4][4];                                                      \
    _Pragma("unroll")                                                        \
    for (int mi = 0; mi < 4; ++mi)                                           \
        _Pragma("unroll")                                                    \
        for (int ni = 0; ni < 4; ++ni)                                       \
            _Pragma("unroll")                                                \
            for (int r = 0; r < 4; ++r) acc[mi][ni][r] = 0.f;                \
    GemmCore core;                                                           \
    core.A = Aop; core.B = Bop; core.K = Kval; core.m0 = m0; core.n0 = n0;   \
    core.sBase = smem_u32(sm);                                               \
    core.lrow = t >> 2; core.lc16 = t & 3;                                   \
    const int NCH = (Kval) / GBK;                                            \
    core.load_async(0, 0);                                                   \
    core.load_async(1, GBK);                                                 \
    for (int c = 0; c < NCH; ++c) {                                          \
        if (c + 1 < NCH) { CP_WAIT1(); } else { CP_WAIT0(); }                \
        __syncthreads();                                                     \
        if (c + 2 < NCH) core.load_async((c + 2) % 3, (c + 2) * GBK);        \
        const int stg = c % 3;                                               \
        gemm_chunk_f16(&sm[stg * GSTAGE], &sm[stg * GSTAGE + GTILE_A],       \
                       wm, wn, fr, fc, acc);                                 \
    }

// ---- O-projection GEMM: half inputs, fp32 output + bias ----
__global__ __launch_bounds__(512, 1) void f16_gemm_nt(
    const __half* __restrict__ A, const __half* __restrict__ B,
    const float* __restrict__ bias, float* __restrict__ C,
    int M, int N, int K)
{
    const int m0 = blockIdx.y * GBM;
    const int n0 = blockIdx.x * GBN;
    GEMM_PROLOG_BODY(A, B, K)

    const int c2 = fc * 2;
    #pragma unroll
    for (int mi = 0; mi < 4; ++mi) {
        #pragma unroll
        for (int ni = 0; ni < 4; ++ni) {
            int row = m0 + wm + mi * 16 + fr;
            int col = n0 + wn + ni * 8 + c2;
            float b0 = bias[col], b1 = bias[col + 1];
            *(float2*)&C[(size_t)row * N + col] =
                make_float2(acc[mi][ni][0] + b0, acc[mi][ni][1] + b1);
            *(float2*)&C[(size_t)(row + 8) * N + col] =
                make_float2(acc[mi][ni][2] + b0, acc[mi][ni][3] + b1);
        }
    }
}

// ---- fused QKV GEMM: q,k -> fp32; v -> half ----
__global__ __launch_bounds__(512, 1) void f16_gemm_qkv(
    const __half* __restrict__ A, const __half* __restrict__ Bw,
    const float* __restrict__ bq, const float* __restrict__ bk,
    const float* __restrict__ bv,
    float* __restrict__ Cq, float* __restrict__ Ck, __half* __restrict__ Cv)
{
    const int m0 = blockIdx.y * GBM;
    const int n0 = blockIdx.x * GBN;
    GEMM_PROLOG_BODY(A, Bw, DIM)

    const int which = blockIdx.x / 12;         // 0=q 1=k 2=v
    const int ncol0 = (blockIdx.x % 12) * 128;
    const int c2 = fc * 2;
    if (which == 2) {
        #pragma unroll
        for (int mi = 0; mi < 4; ++mi)
            #pragma unroll
            for (int ni = 0; ni < 4; ++ni) {
                int row = m0 + wm + mi * 16 + fr;
                int col = ncol0 + wn + ni * 8 + c2;
                float b0 = bv[col], b1 = bv[col + 1];
                *(uint32_t*)&g_vh[(size_t)row * DIM + col] =
                    f2h2(acc[mi][ni][0] + b0, acc[mi][ni][1] + b1);
                *(uint32_t*)&g_vh[(size_t)(row + 8) * DIM + col] =
                    f2h2(acc[mi][ni][2] + b0, acc[mi][ni][3] + b1);
            }
    } else {
        float* C = which == 0 ? Cq : Ck;
        const float* bias = which == 0 ? bq : bk;
        #pragma unroll
        for (int mi = 0; mi < 4; ++mi)
            #pragma unroll
            for (int ni = 0; ni < 4; ++ni) {
                int row = m0 + wm + mi * 16 + fr;
                int col = ncol0 + wn + ni * 8 + c2;
                float b0 = bias[col], b1 = bias[col + 1];
                *(float2*)&C[(size_t)row * DIM + col] =
                    make_float2(acc[mi][ni][0] + b0, acc[mi][ni][1] + b1);
                *(float2*)&C[(size_t)(row + 8) * DIM + col] =
                    make_float2(acc[mi][ni][2] + b0, acc[mi][ni][3] + b1);
            }
    }
}

// ----------------------------------------------------------------
// Fused RMSNorm (with gains) + RoPE: fp32 in -> half out.
// q additionally scaled by 1/sqrt(HD).
// ----------------------------------------------------------------
__global__ __launch_bounds__(256) void normrope_kernel(
    const float* __restrict__ gq, const float* __restrict__ gk,
    const float* __restrict__ freqs)
{
    const int tok = blockIdx.x;
    const int t   = threadIdx.x;
    const float* qr = g_q + (size_t)tok * DIM;
    const float* kr = g_k + (size_t)tok * DIM;
    __half* qh = g_qh + (size_t)tok * DIM;
    __half* kh = g_kh + (size_t)tok * DIM;

    __shared__ float red[16];
    __shared__ float s_scq, s_sck;

    float sq = 0.f, sk = 0.f;
    for (int i = t; i < DIM; i += 256) {
        float a = qr[i]; sq += a * a;
        float b = kr[i]; sk += b * b;
    }
    #pragma unroll
    for (int m = 16; m >= 1; m >>= 1) {
        sq += __shfl_xor_sync(0xffffffffu, sq, m);
        sk += __shfl_xor_sync(0xffffffffu, sk, m);
    }
    if ((t & 31) == 0) { red[t >> 5] = sq; red[8 + (t >> 5)] = sk; }
    __syncthreads();
    if (t == 0) {
        float a = 0.f, b = 0.f;
        #pragma unroll
        for (int w = 0; w < 8; ++w) { a += red[w]; b += red[8 + w]; }
        s_scq = rsqrtf(a * (1.f / DIM) + 1e-6f);
        s_sck = rsqrtf(b * (1.f / DIM) + 1e-6f);
    }
    __syncthreads();
    const float scq = s_scq * 0.08838834764831845f;   // fold attn scale
    const float sck = s_sck;

    for (int p = t; p < DIM / 2; p += 256) {
        int hh = p >> 6, i = p & 63;
        int c0 = hh * HD + 2 * i;
        float fr = freqs[(size_t)tok * (HD / 2) + i];
        float cs = cosf(fr), sn = sinf(fr);
        float qe = qr[c0] * scq * gq[c0];
        float qo = qr[c0 + 1] * scq * gq[c0 + 1];
        *(uint32_t*)&qh[c0] = f2h2(qe * cs - qo * sn, qe * sn + qo * cs);
        float ke = kr[c0] * sck * gk[c0];
        float ko = kr[c0 + 1] * sck * gk[c0 + 1];
        *(uint32_t*)&kh[c0] = f2h2(ke * cs - ko * sn, ke * sn + ko * cs);
    }
}

// ================= fp16 tensor-core flash attention ==============
// BM=128 q rows (8 warps x 16), BN=64 kv, HD=128. m16n8k16.
// K,V staged verbatim ([tok][d], stride 68w) via cp.async, double
// buffered. PV B-frags via ldmatrix.x4.trans. Ps: [128 q][36w].
#define ABM 128
#define ABN 64
#define KSTW 68
#define KVTILE (64 * KSTW)            // words per K (or V) buffer
#define PSTW 36
#define ATTN_SMEM ((4 * KVTILE + 128 * PSTW) * 4)   // 88064 B

__global__ __launch_bounds__(256) void attn_f16_kernel()
{
    extern __shared__ uint32_t smw[];
    uint32_t* Ps = smw + 4 * KVTILE;
    const uint32_t sBase = smem_u32(smw);

    const int t    = threadIdx.x;
    const int lane = t & 31;
    const int w    = t >> 5;
    const int fr   = lane >> 2;
    const int fc   = lane & 3;
    const int mt = blockIdx.x, f = blockIdx.y, h = blockIdx.z;
    const int q0 = f * IMG + mt * ABM;
    int st = f - 7; st = st < 0 ? 0 : (st > 6 ? 6 : st);
    const int kbase = st * IMG;

    // per-thread ldmatrix base offset within a V buffer (words):
    // row = lane&15, d-block = 8*(lane>>4) halves = 4*(lane>>4) words
    const uint32_t vofs = (uint32_t)((lane & 15) * KSTW + 4 * (lane >> 4)) * 4;

    // ---- preload Q as fp16 A-fragments (scale folded upstream) ----
    uint32_t qf[8][4];
    {
        const __half* Q0 = g_qh + (size_t)(q0 + 16 * w + fr) * DIM + h * HD;
        const __half* Q8 = Q0 + 8 * DIM;
        #pragma unroll
        for (int ks = 0; ks < 8; ++ks) {
            const int kc = ks * 16;
            qf[ks][0] = *(const uint32_t*)&Q0[kc + 2 * fc];
            qf[ks][1] = *(const uint32_t*)&Q8[kc + 2 * fc];
            qf[ks][2] = *(const uint32_t*)&Q0[kc + 2 * fc + 8];
            qf[ks][3] = *(const uint32_t*)&Q8[kc + 2 * fc + 8];
        }
    }

    float o[16][4];
    #pragma unroll
    for (int nf = 0; nf < 16; ++nf)
        #pragma unroll
        for (int r = 0; r < 4; ++r) o[nf][r] = 0.f;
    float Mlo = -INFINITY, Mhi = -INFINITY, Llo = 0.f, Lhi = 0.f;

    const int prow0 = (16 * w + fr) * PSTW;
    const int prow8 = (16 * w + fr + 8) * PSTW;

    // stage K+V for kv-tile cc into buffer buf
    auto stage_kv = [&](int buf, int cc) {
        const int kb = kbase + cc * ABN;
        const uint32_t sK = sBase + (uint32_t)(buf * 2 * KVTILE) * 4;
        const uint32_t sV = sK + (uint32_t)KVTILE * 4;
        #pragma unroll
        for (int i = 0; i < 4; ++i) {
            int idx = t + i * 256;              // 0..1023
            int row = idx >> 4, c16 = idx & 15;
            uint32_t off = (uint32_t)(row * KSTW + c16 * 4) * 4;
            CP_ASYNC16(sK + off, g_kh + (size_t)(kb + row) * DIM + h * HD + c16 * 8);
            CP_ASYNC16(sV + off, g_vh + (size_t)(kb + row) * DIM + h * HD + c16 * 8);
        }
        CP_COMMIT();
    };

    stage_kv(0, 0);

    for (int c = 0; c < WKV / ABN; ++c) {
        CP_WAIT0();
        __syncthreads();            // tile c resident; prev compute done
        if (c + 1 < WKV / ABN) stage_kv((c + 1) & 1, c + 1);

        const uint32_t* Kb = smw + (c & 1) * 2 * KVTILE;
        const uint32_t vbase = sBase + (uint32_t)((c & 1) * 2 * KVTILE + KVTILE) * 4 + vofs;

        // ---- S = Q K^T (16 x 64 per warp) ----
        float s[8][4];
        #pragma unroll
        for (int nf = 0; nf < 8; ++nf)
            #pragma unroll
            for (int r = 0; r < 4; ++r) s[nf][r] = 0.f;

        #pragma unroll
        for (int ks = 0; ks < 8; ++ks) {
            const int kw = ks * 8;
            #pragma unroll
            for (int nf = 0; nf < 8; ++nf) {
                const uint32_t* p = Kb + (8 * nf + fr) * KSTW + kw;
                uint32_t b[2] = { p[fc], p[fc + 4] };
                MMA_F16(s[nf], qf[ks], b);
            }
        }

        // ---- online softmax (warp-private rows) ----
        float mlo = -INFINITY, mhi = -INFINITY;
        #pragma unroll
        for (int nf = 0; nf < 8; ++nf) {
            mlo = fmaxf(mlo, fmaxf(s[nf][0], s[nf][1]));
            mhi = fmaxf(mhi, fmaxf(s[nf][2], s[nf][3]));
        }
        mlo = fmaxf(mlo, __shfl_xor_sync(0xffffffffu, mlo, 1));
        mlo = fmaxf(mlo, __shfl_xor_sync(0xffffffffu, mlo, 2));
        mhi = fmaxf(mhi, __shfl_xor_sync(0xffffffffu, mhi, 1));
        mhi = fmaxf(mhi, __shfl_xor_sync(0xffffffffu, mhi, 2));
        const float Mnlo = fmaxf(Mlo, mlo), Mnhi = fmaxf(Mhi, mhi);
        const float alo = __expf(Mlo - Mnlo), ahi = __expf(Mhi - Mnhi);
        Mlo = Mnlo; Mhi = Mnhi;

        float rlo = 0.f, rhi = 0.f;
        #pragma unroll
        for (int nf = 0; nf < 8; ++nf) {
            __half h0 = __float2half_rn(__expf(s[nf][0] - Mnlo));
            __half h1 = __float2half_rn(__expf(s[nf][1] - Mnlo));
            __half h2 = __float2half_rn(__expf(s[nf][2] - Mnhi));
            __half h3 = __float2half_rn(__expf(s[nf][3] - Mnhi));
            rlo += __half2float(h0) + __half2float(h1);
            rhi += __half2float(h2) + __half2float(h3);
            Ps[prow0 + 4 * nf + fc] =
                (uint32_t)__half_as_ushort(h0) | ((uint32_t)__half_as_ushort(h1) << 16);
            Ps[prow8 + 4 * nf + fc] =
                (uint32_t)__half_as_ushort(h2) | ((uint32_t)__half_as_ushort(h3) << 16);
        }
        rlo += __shfl_xor_sync(0xffffffffu, rlo, 1);
        rlo += __shfl_xor_sync(0xffffffffu, rlo, 2);
        rhi += __shfl_xor_sync(0xffffffffu, rhi, 1);
        rhi += __shfl_xor_sync(0xffffffffu, rhi, 2);
        Llo = Llo * alo + rlo;
        Lhi = Lhi * ahi + rhi;
        #pragma unroll
        for (int nf = 0; nf < 16; ++nf) {
            o[nf][0] *= alo; o[nf][1] *= alo;
            o[nf][2] *= ahi; o[nf][3] *= ahi;
        }
        __syncwarp();

        // ---- O += P V  (B-frags via ldmatrix.trans) ----
        #pragma unroll
        for (int k2 = 0; k2 < 4; ++k2) {
            uint32_t a[4];
            a[0] = Ps[prow0 + 8 * k2 + fc];
            a[1] = Ps[prow8 + 8 * k2 + fc];
            a[2] = Ps[prow0 + 8 * k2 + fc + 4];
            a[3] = Ps[prow8 + 8 * k2 + fc + 4];
            #pragma unroll
            for (int nfp = 0; nfp < 8; ++nfp) {
                uint32_t b0, b1, b2, b3;
                LDSM_X4_TRANS(b0, b1, b2, b3,
                              vbase + (uint32_t)(k2 * 16 * KSTW + 8 * nfp) * 4);
                uint32_t lo[2] = { b0, b1 };
                MMA_F16(o[2 * nfp], a, lo);
                uint32_t hi2[2] = { b2, b3 };
                MMA_F16(o[2 * nfp + 1], a, hi2);
            }
        }
        __syncwarp();
    }

    // ---- epilogue: normalize, write half ----
    const float il = 1.f / Llo, ih = 1.f / Lhi;
    const int row0 = q0 + 16 * w + fr;
    #pragma unroll
    for (int nf = 0; nf < 16; ++nf) {
        const int col = h * HD + 8 * nf + 2 * fc;
        *(uint32_t*)&g_attnh[(size_t)row0 * DIM + col] =
            f2h2(o[nf][0] * il, o[nf][1] * il);
        *(uint32_t*)&g_attnh[(size_t)(row0 + 8) * DIM + col] =
            f2h2(o[nf][2] * ih, o[nf][3] * ih);
    }
}

// ----------------------------------------------------------------
extern "C" void kernel_launch(void* const* d_in, const int* in_sizes, int n_in,
                              void* d_out, int out_size)
{
    const float* x     = (const float*)d_in[0];
    const float* freqs = (const float*)d_in[1];
    const float* Wq    = (const float*)d_in[2];
    const float* bq    = (const float*)d_in[3];
    const float* Wk    = (const float*)d_in[4];
    const float* bk    = (const float*)d_in[5];
    const float* Wv    = (const float*)d_in[6];
    const float* bv    = (const float*)d_in[7];
    const float* Wo    = (const float*)d_in[8];
    const float* bo    = (const float*)d_in[9];
    const float* gq    = (const float*)d_in[10];
    const float* gk    = (const float*)d_in[11];
    float* out = (float*)d_out;

    void *pq, *pk, *pxh, *pwh, *pvh, *pah;
    cudaGetSymbolAddress(&pq, g_q);
    cudaGetSymbolAddress(&pk, g_k);
    cudaGetSymbolAddress(&pxh, g_xh);
    cudaGetSymbolAddress(&pwh, g_wh);
    cudaGetSymbolAddress(&pvh, g_vh);
    cudaGetSymbolAddress(&pah, g_attnh);
    __half* xh = (__half*)pxh;
    __half* wh = (__half*)pwh;

    // convert inputs to fp16
    const int NW4 = DIM * DIM / 4;
    cvt_half_kernel<<<1184, 256>>>((const float4*)x, (uint2*)xh, S_TOK * DIM / 4);
    cvt_half_kernel<<<592, 256>>>((const float4*)Wq, (uint2*)(wh + 0 * (size_t)DIM * DIM), NW4);
    cvt_half_kernel<<<592, 256>>>((const float4*)Wk, (uint2*)(wh + 1 * (size_t)DIM * DIM), NW4);
    cvt_half_kernel<<<592, 256>>>((const float4*)Wv, (uint2*)(wh + 2 * (size_t)DIM * DIM), NW4);
    cvt_half_kernel<<<592, 256>>>((const float4*)Wo, (uint2*)(wh + 3 * (size_t)DIM * DIM), NW4);

    cudaFuncSetAttribute(f16_gemm_qkv, cudaFuncAttributeMaxDynamicSharedMemorySize, GEMM_SMEM);
    cudaFuncSetAttribute(f16_gemm_nt, cudaFuncAttributeMaxDynamicSharedMemorySize, GEMM_SMEM);

    f16_gemm_qkv<<<dim3(36, S_TOK / 256), 512, GEMM_SMEM>>>(
        xh, wh, bq, bk, bv, (float*)pq, (float*)pk, (__half*)pvh);

    normrope_kernel<<<S_TOK, 256>>>(gq, gk, freqs);

    cudaFuncSetAttribute(attn_f16_kernel, cudaFuncAttributeMaxDynamicSharedMemorySize, ATTN_SMEM);
    attn_f16_kernel<<<dim3(IMG / ABM, NF, NH), 256, ATTN_SMEM>>>();

    f16_gemm_nt<<<dim3(12, S_TOK / 256), 512, GEMM_SMEM>>>(
        (const __half*)pah, wh + 3 * (size_t)DIM * DIM, bo, out, S_TOK, DIM, DIM);
}

// round 14
// speedup vs baseline: 6.4865x; 1.0546x over previous
#include <cuda_runtime.h>
#include <cuda_fp16.h>
#include <math.h>
#include <stdint.h>

#define S_TOK 5376
#define DIM   1536
#define NH    12
#define HD    128
#define NF    21
#define IMG   256
#define WKV   3840

// -------- scratch (device-global; no allocation allowed) --------
__device__ float  g_q[(size_t)S_TOK * DIM];          // fp32 q (pre-norm)
__device__ float  g_k[(size_t)S_TOK * DIM];          // fp32 k (pre-norm)
__device__ __half g_xh[(size_t)S_TOK * DIM];         // half x
__device__ __half g_wh[(size_t)4 * DIM * DIM];       // half Wq,Wk,Wv,Wo concat
__device__ __half g_qh[(size_t)S_TOK * DIM];         // half q (post rope, scaled)
__device__ __half g_kh[(size_t)S_TOK * DIM];         // half k (post rope)
__device__ __half g_vh[(size_t)S_TOK * DIM];         // half v
__device__ __half g_attnh[(size_t)S_TOK * DIM];      // half attention output

__device__ __forceinline__ uint32_t f2h2(float lo, float hi) {
    uint32_t r;
    asm("{ .reg .f16 l, h; cvt.rn.f16.f32 l, %1; cvt.rn.f16.f32 h, %2; mov.b32 %0, {l, h}; }"
        : "=r"(r) : "f"(lo), "f"(hi));
    return r;
}
__device__ __forceinline__ uint32_t smem_u32(const void* p) {
    uint32_t a;
    asm("{ .reg .u64 t; cvta.to.shared.u64 t, %1; cvt.u32.u64 %0, t; }" : "=r"(a) : "l"(p));
    return a;
}
__device__ __forceinline__ float ex2(float x) {
    float r;
    asm("ex2.approx.f32 %0, %1;" : "=f"(r) : "f"(x));
    return r;
}

#define MMA_F16(c, a, b) \
    asm volatile("mma.sync.aligned.m16n8k16.row.col.f32.f16.f16.f32 " \
                 "{%0,%1,%2,%3}, {%4,%5,%6,%7}, {%8,%9}, {%0,%1,%2,%3};" \
                 : "+f"((c)[0]), "+f"((c)[1]), "+f"((c)[2]), "+f"((c)[3]) \
                 : "r"((a)[0]), "r"((a)[1]), "r"((a)[2]), "r"((a)[3]), \
                   "r"((b)[0]), "r"((b)[1]))

#define LDSM_X4_TRANS(r0, r1, r2, r3, addr) \
    asm volatile("ldmatrix.sync.aligned.m8n8.x4.trans.shared.b16 {%0,%1,%2,%3}, [%4];" \
                 : "=r"(r0), "=r"(r1), "=r"(r2), "=r"(r3) : "r"(addr))

#define CP_ASYNC16(dst, src) \
    asm volatile("cp.async.cg.shared.global [%0], [%1], 16;" :: "r"(dst), "l"(src))
#define CP_COMMIT() asm volatile("cp.async.commit_group;" ::: "memory")
#define CP_WAIT0()  asm volatile("cp.async.wait_group 0;" ::: "memory")
#define CP_WAIT1()  asm volatile("cp.async.wait_group 1;" ::: "memory")

// ---------------- fused fp32 -> fp16 conversion pass -------------
// Converts x plus all four weight matrices in ONE launch.
__global__ __launch_bounds__(256) void cvt_all_kernel(
    const float4* __restrict__ x,  const float4* __restrict__ wq,
    const float4* __restrict__ wk, const float4* __restrict__ wv,
    const float4* __restrict__ wo, uint2* __restrict__ xh,
    uint2* __restrict__ wh)
{
    const int XB = S_TOK * DIM / 4;
    const int WB = DIM * DIM / 4;
    const int total = XB + 4 * WB;
    for (int i = blockIdx.x * blockDim.x + threadIdx.x; i < total;
         i += gridDim.x * blockDim.x) {
        const float4* src; uint2* dst; int off;
        if (i < XB) { src = x; dst = xh; off = i; }
        else {
            int j = i - XB;
            int r = j / WB;
            off = j - r * WB;
            src = (r == 0) ? wq : (r == 1) ? wk : (r == 2) ? wv : wo;
            dst = wh + (size_t)r * WB;
        }
        float4 v = src[off];
        dst[off] = make_uint2(f2h2(v.x, v.y), f2h2(v.z, v.w));
    }
}

// ================= fp16 mma.sync GEMM (NT) =======================
// CTA tile 256x128, K-chunk 32 halves, 512 threads, 16 warps (4x4),
// warp tile 64x32, 3-stage cp.async pipeline.
#define GBM 256
#define GBN 128
#define GBK 32
#define AST 20                        // words per row (16 data + 4 pad)
#define GTILE_A (256 * AST)
#define GTILE_B (128 * AST)
#define GSTAGE  (GTILE_A + GTILE_B)
#define GEMM_SMEM (3 * GSTAGE * 4)    // 92160 B

struct GemmCore {
    const __half* A; const __half* B; int K; int m0; int n0;
    uint32_t sBase;
    int lrow, lc16;
    __device__ __forceinline__ void load_async(int stage, int k0) const {
        uint32_t sb = sBase + (uint32_t)(stage * GSTAGE) * 4;
        CP_ASYNC16(sb + (uint32_t)(lrow * AST + lc16 * 4) * 4,
                   A + (size_t)(m0 + lrow) * K + k0 + lc16 * 8);
        CP_ASYNC16(sb + (uint32_t)((lrow + 128) * AST + lc16 * 4) * 4,
                   A + (size_t)(m0 + lrow + 128) * K + k0 + lc16 * 8);
        CP_ASYNC16(sb + (uint32_t)(GTILE_A + lrow * AST + lc16 * 4) * 4,
                   B + (size_t)(n0 + lrow) * K + k0 + lc16 * 8);
        CP_COMMIT();
    }
};

__device__ __forceinline__ void gemm_chunk_f16(
    const uint32_t* __restrict__ Ab, const uint32_t* __restrict__ Bb,
    int wm, int wn, int fr, int fc, float acc[4][4][4])
{
    #pragma unroll
    for (int ks = 0; ks < 2; ++ks) {
        const int kw = ks * 8;
        uint32_t af[4][4];
        #pragma unroll
        for (int mi = 0; mi < 4; ++mi) {
            const uint32_t* p = Ab + (wm + mi * 16) * AST + kw;
            af[mi][0] = p[fr * AST + fc];
            af[mi][1] = p[(fr + 8) * AST + fc];
            af[mi][2] = p[fr * AST + fc + 4];
            af[mi][3] = p[(fr + 8) * AST + fc + 4];
        }
        uint32_t bf[4][2];
        #pragma unroll
        for (int ni = 0; ni < 4; ++ni) {
            const uint32_t* p = Bb + (wn + ni * 8 + fr) * AST + kw;
            bf[ni][0] = p[fc];
            bf[ni][1] = p[fc + 4];
        }
        #pragma unroll
        for (int mi = 0; mi < 4; ++mi)
            #pragma unroll
            for (int ni = 0; ni < 4; ++ni)
                MMA_F16(acc[mi][ni], af[mi], bf[ni]);
    }
}

#define GEMM_PROLOG_BODY(Aop, Bop, Kval)                                     \
    extern __shared__ uint32_t sm[];                                         \
    const int t    = threadIdx.x;                                            \
    const int lane = t & 31;                                                 \
    const int wid  = t >> 5;                                                 \
    const int wm   = (wid & 3) * 64;                                         \
    const int wn   = (wid >> 2) * 32;                                        \
    const int fr   = lane >> 2;                                              \
    const int fc   = lane & 3;                                               \
    float acc[4][4][4];                                                      \
    _Pragma("unroll")                                                        \
    for (int mi = 0; mi < 4; ++mi)                                           \
        _Pragma("unroll")                                                    \
        for (int ni = 0; ni < 4; ++ni)                                       \
            _Pragma("unroll")                                                \
            for (int r = 0; r < 4; ++r) acc[mi][ni][r] = 0.f;                \
    GemmCore core;                                                           \
    core.A = Aop; core.B = Bop; core.K = Kval; core.m0 = m0; core.n0 = n0;   \
    core.sBase = smem_u32(sm);                                               \
    core.lrow = t >> 2; core.lc16 = t & 3;                                   \
    const int NCH = (Kval) / GBK;                                            \
    core.load_async(0, 0);                                                   \
    core.load_async(1, GBK);                                                 \
    for (int c = 0; c < NCH; ++c) {                                          \
        if (c + 1 < NCH) { CP_WAIT1(); } else { CP_WAIT0(); }                \
        __syncthreads();                                                     \
        if (c + 2 < NCH) core.load_async((c + 2) % 3, (c + 2) * GBK);        \
        const int stg = c % 3;                                               \
        gemm_chunk_f16(&sm[stg * GSTAGE], &sm[stg * GSTAGE + GTILE_A],       \
                       wm, wn, fr, fc, acc);                                 \
    }

// ---- O-projection GEMM: half inputs, fp32 output + bias ----
__global__ __launch_bounds__(512, 1) void f16_gemm_nt(
    const __half* __restrict__ A, const __half* __restrict__ B,
    const float* __restrict__ bias, float* __restrict__ C,
    int M, int N, int K)
{
    const int m0 = blockIdx.y * GBM;
    const int n0 = blockIdx.x * GBN;
    GEMM_PROLOG_BODY(A, B, K)

    const int c2 = fc * 2;
    #pragma unroll
    for (int mi = 0; mi < 4; ++mi) {
        #pragma unroll
        for (int ni = 0; ni < 4; ++ni) {
            int row = m0 + wm + mi * 16 + fr;
            int col = n0 + wn + ni * 8 + c2;
            float b0 = bias[col], b1 = bias[col + 1];
            *(float2*)&C[(size_t)row * N + col] =
                make_float2(acc[mi][ni][0] + b0, acc[mi][ni][1] + b1);
            *(float2*)&C[(size_t)(row + 8) * N + col] =
                make_float2(acc[mi][ni][2] + b0, acc[mi][ni][3] + b1);
        }
    }
}

// ---- fused QKV GEMM: q,k -> fp32; v -> half ----
__global__ __launch_bounds__(512, 1) void f16_gemm_qkv(
    const __half* __restrict__ A, const __half* __restrict__ Bw,
    const float* __restrict__ bq, const float* __restrict__ bk,
    const float* __restrict__ bv,
    float* __restrict__ Cq, float* __restrict__ Ck, __half* __restrict__ Cv)
{
    const int m0 = blockIdx.y * GBM;
    const int n0 = blockIdx.x * GBN;
    GEMM_PROLOG_BODY(A, Bw, DIM)

    const int which = blockIdx.x / 12;         // 0=q 1=k 2=v
    const int ncol0 = (blockIdx.x % 12) * 128;
    const int c2 = fc * 2;
    if (which == 2) {
        #pragma unroll
        for (int mi = 0; mi < 4; ++mi)
            #pragma unroll
            for (int ni = 0; ni < 4; ++ni) {
                int row = m0 + wm + mi * 16 + fr;
                int col = ncol0 + wn + ni * 8 + c2;
                float b0 = bv[col], b1 = bv[col + 1];
                *(uint32_t*)&g_vh[(size_t)row * DIM + col] =
                    f2h2(acc[mi][ni][0] + b0, acc[mi][ni][1] + b1);
                *(uint32_t*)&g_vh[(size_t)(row + 8) * DIM + col] =
                    f2h2(acc[mi][ni][2] + b0, acc[mi][ni][3] + b1);
            }
    } else {
        float* C = which == 0 ? Cq : Ck;
        const float* bias = which == 0 ? bq : bk;
        #pragma unroll
        for (int mi = 0; mi < 4; ++mi)
            #pragma unroll
            for (int ni = 0; ni < 4; ++ni) {
                int row = m0 + wm + mi * 16 + fr;
                int col = ncol0 + wn + ni * 8 + c2;
                float b0 = bias[col], b1 = bias[col + 1];
                *(float2*)&C[(size_t)row * DIM + col] =
                    make_float2(acc[mi][ni][0] + b0, acc[mi][ni][1] + b1);
                *(float2*)&C[(size_t)(row + 8) * DIM + col] =
                    make_float2(acc[mi][ni][2] + b0, acc[mi][ni][3] + b1);
            }
    }
}

// ----------------------------------------------------------------
// Fused RMSNorm (with gains) + RoPE: fp32 in -> half out.
// q scaled by (1/sqrt(HD)) * log2(e) so attention can use raw ex2.
// ----------------------------------------------------------------
__global__ __launch_bounds__(256) void normrope_kernel(
    const float* __restrict__ gq, const float* __restrict__ gk,
    const float* __restrict__ freqs)
{
    const int tok = blockIdx.x;
    const int t   = threadIdx.x;
    const float* qr = g_q + (size_t)tok * DIM;
    const float* kr = g_k + (size_t)tok * DIM;
    __half* qh = g_qh + (size_t)tok * DIM;
    __half* kh = g_kh + (size_t)tok * DIM;

    __shared__ float red[16];
    __shared__ float s_scq, s_sck;

    float sq = 0.f, sk = 0.f;
    for (int i = t; i < DIM; i += 256) {
        float a = qr[i]; sq += a * a;
        float b = kr[i]; sk += b * b;
    }
    #pragma unroll
    for (int m = 16; m >= 1; m >>= 1) {
        sq += __shfl_xor_sync(0xffffffffu, sq, m);
        sk += __shfl_xor_sync(0xffffffffu, sk, m);
    }
    if ((t & 31) == 0) { red[t >> 5] = sq; red[8 + (t >> 5)] = sk; }
    __syncthreads();
    if (t == 0) {
        float a = 0.f, b = 0.f;
        #pragma unroll
        for (int w = 0; w < 8; ++w) { a += red[w]; b += red[8 + w]; }
        s_scq = rsqrtf(a * (1.f / DIM) + 1e-6f);
        s_sck = rsqrtf(b * (1.f / DIM) + 1e-6f);
    }
    __syncthreads();
    // fold attn scale 1/sqrt(128) AND log2(e) into q
    const float scq = s_scq * (0.08838834764831845f * 1.4426950408889634f);
    const float sck = s_sck;

    for (int p = t; p < DIM / 2; p += 256) {
        int hh = p >> 6, i = p & 63;
        int c0 = hh * HD + 2 * i;
        float fr = freqs[(size_t)tok * (HD / 2) + i];
        float cs = cosf(fr), sn = sinf(fr);
        float qe = qr[c0] * scq * gq[c0];
        float qo = qr[c0 + 1] * scq * gq[c0 + 1];
        *(uint32_t*)&qh[c0] = f2h2(qe * cs - qo * sn, qe * sn + qo * cs);
        float ke = kr[c0] * sck * gk[c0];
        float ko = kr[c0 + 1] * sck * gk[c0 + 1];
        *(uint32_t*)&kh[c0] = f2h2(ke * cs - ko * sn, ke * sn + ko * cs);
    }
}

// ================= fp16 tensor-core flash attention ==============
// BM=128 q rows (8 warps x 16), BN=64 kv, HD=128. m16n8k16.
// Scores are in log2 domain (q pre-scaled by log2e) -> raw ex2.
#define ABM 128
#define ABN 64
#define KSTW 68
#define KVTILE (64 * KSTW)
#define PSTW 36
#define ATTN_SMEM ((4 * KVTILE + 128 * PSTW) * 4)   // 88064 B

__global__ __launch_bounds__(256, 2) void attn_f16_kernel()
{
    extern __shared__ uint32_t smw[];
    uint32_t* Ps = smw + 4 * KVTILE;
    const uint32_t sBase = smem_u32(smw);

    const int t    = threadIdx.x;
    const int lane = t & 31;
    const int w    = t >> 5;
    const int fr   = lane >> 2;
    const int fc   = lane & 3;
    const int mt = blockIdx.x, f = blockIdx.y, h = blockIdx.z;
    const int q0 = f * IMG + mt * ABM;
    int st = f - 7; st = st < 0 ? 0 : (st > 6 ? 6 : st);
    const int kbase = st * IMG;

    const uint32_t vofs = (uint32_t)((lane & 15) * KSTW + 4 * (lane >> 4)) * 4;

    uint32_t qf[8][4];
    {
        const __half* Q0 = g_qh + (size_t)(q0 + 16 * w + fr) * DIM + h * HD;
        const __half* Q8 = Q0 + 8 * DIM;
        #pragma unroll
        for (int ks = 0; ks < 8; ++ks) {
            const int kc = ks * 16;
            qf[ks][0] = *(const uint32_t*)&Q0[kc + 2 * fc];
            qf[ks][1] = *(const uint32_t*)&Q8[kc + 2 * fc];
            qf[ks][2] = *(const uint32_t*)&Q0[kc + 2 * fc + 8];
            qf[ks][3] = *(const uint32_t*)&Q8[kc + 2 * fc + 8];
        }
    }

    float o[16][4];
    #pragma unroll
    for (int nf = 0; nf < 16; ++nf)
        #pragma unroll
        for (int r = 0; r < 4; ++r) o[nf][r] = 0.f;
    float Mlo = -INFINITY, Mhi = -INFINITY, Llo = 0.f, Lhi = 0.f;

    const int prow0 = (16 * w + fr) * PSTW;
    const int prow8 = (16 * w + fr + 8) * PSTW;

    auto stage_kv = [&](int buf, int cc) {
        const int kb = kbase + cc * ABN;
        const uint32_t sK = sBase + (uint32_t)(buf * 2 * KVTILE) * 4;
        const uint32_t sV = sK + (uint32_t)KVTILE * 4;
        #pragma unroll
        for (int i = 0; i < 4; ++i) {
            int idx = t + i * 256;
            int row = idx >> 4, c16 = idx & 15;
            uint32_t off = (uint32_t)(row * KSTW + c16 * 4) * 4;
            CP_ASYNC16(sK + off, g_kh + (size_t)(kb + row) * DIM + h * HD + c16 * 8);
            CP_ASYNC16(sV + off, g_vh + (size_t)(kb + row) * DIM + h * HD + c16 * 8);
        }
        CP_COMMIT();
    };

    stage_kv(0, 0);

    for (int c = 0; c < WKV / ABN; ++c) {
        CP_WAIT0();
        __syncthreads();
        if (c + 1 < WKV / ABN) stage_kv((c + 1) & 1, c + 1);

        const uint32_t* Kb = smw + (c & 1) * 2 * KVTILE;
        const uint32_t vbase = sBase + (uint32_t)((c & 1) * 2 * KVTILE + KVTILE) * 4 + vofs;

        // ---- S = Q K^T (scores already in log2 domain) ----
        float s[8][4];
        #pragma unroll
        for (int nf = 0; nf < 8; ++nf)
            #pragma unroll
            for (int r = 0; r < 4; ++r) s[nf][r] = 0.f;

        #pragma unroll
        for (int ks = 0; ks < 8; ++ks) {
            const int kw = ks * 8;
            #pragma unroll
            for (int nf = 0; nf < 8; ++nf) {
                const uint32_t* p = Kb + (8 * nf + fr) * KSTW + kw;
                uint32_t b[2] = { p[fc], p[fc + 4] };
                MMA_F16(s[nf], qf[ks], b);
            }
        }

        // ---- online softmax (base-2) ----
        float mlo = -INFINITY, mhi = -INFINITY;
        #pragma unroll
        for (int nf = 0; nf < 8; ++nf) {
            mlo = fmaxf(mlo, fmaxf(s[nf][0], s[nf][1]));
            mhi = fmaxf(mhi, fmaxf(s[nf][2], s[nf][3]));
        }
        mlo = fmaxf(mlo, __shfl_xor_sync(0xffffffffu, mlo, 1));
        mlo = fmaxf(mlo, __shfl_xor_sync(0xffffffffu, mlo, 2));
        mhi = fmaxf(mhi, __shfl_xor_sync(0xffffffffu, mhi, 1));
        mhi = fmaxf(mhi, __shfl_xor_sync(0xffffffffu, mhi, 2));
        const float Mnlo = fmaxf(Mlo, mlo), Mnhi = fmaxf(Mhi, mhi);
        const float alo = ex2(Mlo - Mnlo), ahi = ex2(Mhi - Mnhi);
        Mlo = Mnlo; Mhi = Mnhi;

        float rlo = 0.f, rhi = 0.f;
        #pragma unroll
        for (int nf = 0; nf < 8; ++nf) {
            __half h0 = __float2half_rn(ex2(s[nf][0] - Mnlo));
            __half h1 = __float2half_rn(ex2(s[nf][1] - Mnlo));
            __half h2 = __float2half_rn(ex2(s[nf][2] - Mnhi));
            __half h3 = __float2half_rn(ex2(s[nf][3] - Mnhi));
            rlo += __half2float(h0) + __half2float(h1);
            rhi += __half2float(h2) + __half2float(h3);
            Ps[prow0 + 4 * nf + fc] =
                (uint32_t)__half_as_ushort(h0) | ((uint32_t)__half_as_ushort(h1) << 16);
            Ps[prow8 + 4 * nf + fc] =
                (uint32_t)__half_as_ushort(h2) | ((uint32_t)__half_as_ushort(h3) << 16);
        }
        rlo += __shfl_xor_sync(0xffffffffu, rlo, 1);
        rlo += __shfl_xor_sync(0xffffffffu, rlo, 2);
        rhi += __shfl_xor_sync(0xffffffffu, rhi, 1);
        rhi += __shfl_xor_sync(0xffffffffu, rhi, 2);
        Llo = Llo * alo + rlo;
        Lhi = Lhi * ahi + rhi;
        #pragma unroll
        for (int nf = 0; nf < 16; ++nf) {
            o[nf][0] *= alo; o[nf][1] *= alo;
            o[nf][2] *= ahi; o[nf][3] *= ahi;
        }
        __syncwarp();

        // ---- O += P V  (B-frags via ldmatrix.trans) ----
        #pragma unroll
        for (int k2 = 0; k2 < 4; ++k2) {
            uint32_t a[4];
            a[0] = Ps[prow0 + 8 * k2 + fc];
            a[1] = Ps[prow8 + 8 * k2 + fc];
            a[2] = Ps[prow0 + 8 * k2 + fc + 4];
            a[3] = Ps[prow8 + 8 * k2 + fc + 4];
            #pragma unroll
            for (int nfp = 0; nfp < 8; ++nfp) {
                uint32_t b0, b1, b2, b3;
                LDSM_X4_TRANS(b0, b1, b2, b3,
                              vbase + (uint32_t)(k2 * 16 * KSTW + 8 * nfp) * 4);
                uint32_t lo[2] = { b0, b1 };
                MMA_F16(o[2 * nfp], a, lo);
                uint32_t hi2[2] = { b2, b3 };
                MMA_F16(o[2 * nfp + 1], a, hi2);
            }
        }
        __syncwarp();
    }

    // ---- epilogue: normalize, write half ----
    const float il = 1.f / Llo, ih = 1.f / Lhi;
    const int row0 = q0 + 16 * w + fr;
    #pragma unroll
    for (int nf = 0; nf < 16; ++nf) {
        const int col = h * HD + 8 * nf + 2 * fc;
        *(uint32_t*)&g_attnh[(size_t)row0 * DIM + col] =
            f2h2(o[nf][0] * il, o[nf][1] * il);
        *(uint32_t*)&g_attnh[(size_t)(row0 + 8) * DIM + col] =
            f2h2(o[nf][2] * ih, o[nf][3] * ih);
    }
}

// ----------------------------------------------------------------
extern "C" void kernel_launch(void* const* d_in, const int* in_sizes, int n_in,
                              void* d_out, int out_size)
{
    const float* x     = (const float*)d_in[0];
    const float* freqs = (const float*)d_in[1];
    const float* Wq    = (const float*)d_in[2];
    const float* bq    = (const float*)d_in[3];
    const float* Wk    = (const float*)d_in[4];
    const float* bk    = (const float*)d_in[5];
    const float* Wv    = (const float*)d_in[6];
    const float* bv    = (const float*)d_in[7];
    const float* Wo    = (const float*)d_in[8];
    const float* bo    = (const float*)d_in[9];
    const float* gq    = (const float*)d_in[10];
    const float* gk    = (const float*)d_in[11];
    float* out = (float*)d_out;

    void *pq, *pk, *pxh, *pwh, *pvh, *pah;
    cudaGetSymbolAddress(&pq, g_q);
    cudaGetSymbolAddress(&pk, g_k);
    cudaGetSymbolAddress(&pxh, g_xh);
    cudaGetSymbolAddress(&pwh, g_wh);
    cudaGetSymbolAddress(&pvh, g_vh);
    cudaGetSymbolAddress(&pah, g_attnh);
    __half* xh = (__half*)pxh;
    __half* wh = (__half*)pwh;

    // one fused conversion launch (x + 4 weights)
    cvt_all_kernel<<<2368, 256>>>((const float4*)x, (const float4*)Wq,
                                  (const float4*)Wk, (const float4*)Wv,
                                  (const float4*)Wo, (uint2*)xh, (uint2*)wh);

    cudaFuncSetAttribute(f16_gemm_qkv, cudaFuncAttributeMaxDynamicSharedMemorySize, GEMM_SMEM);
    cudaFuncSetAttribute(f16_gemm_nt, cudaFuncAttributeMaxDynamicSharedMemorySize, GEMM_SMEM);

    f16_gemm_qkv<<<dim3(36, S_TOK / 256), 512, GEMM_SMEM>>>(
        xh, wh, bq, bk, bv, (float*)pq, (float*)pk, (__half*)pvh);

    normrope_kernel<<<S_TOK, 256>>>(gq, gk, freqs);

    cudaFuncSetAttribute(attn_f16_kernel, cudaFuncAttributeMaxDynamicSharedMemorySize, ATTN_SMEM);
    attn_f16_kernel<<<dim3(IMG / ABM, NF, NH), 256, ATTN_SMEM>>>();

    f16_gemm_nt<<<dim3(12, S_TOK / 256), 512, GEMM_SMEM>>>(
        (const __half*)pah, wh + 3 * (size_t)DIM * DIM, bo, out, S_TOK, DIM, DIM);
}

// round 16
// speedup vs baseline: 6.8736x; 1.0597x over previous
#include <cuda_runtime.h>
#include <cuda_fp16.h>
#include <math.h>
#include <stdint.h>

#define S_TOK 5376
#define DIM   1536
#define NH    12
#define HD    128
#define NF    21
#define IMG   256
#define WKV   3840

// -------- scratch (device-global; no allocation allowed) --------
__device__ float  g_q[(size_t)S_TOK * DIM];
__device__ float  g_k[(size_t)S_TOK * DIM];
__device__ __half g_xh[(size_t)S_TOK * DIM];
__device__ __half g_wh[(size_t)4 * DIM * DIM];
__device__ __half g_qh[(size_t)S_TOK * DIM];
__device__ __half g_kh[(size_t)S_TOK * DIM];
__device__ __half g_vh[(size_t)S_TOK * DIM];
__device__ __half g_attnh[(size_t)S_TOK * DIM];

__device__ __forceinline__ uint32_t f2h2(float lo, float hi) {
    uint32_t r;
    asm("{ .reg .f16 l, h; cvt.rn.f16.f32 l, %1; cvt.rn.f16.f32 h, %2; mov.b32 %0, {l, h}; }"
        : "=r"(r) : "f"(lo), "f"(hi));
    return r;
}
__device__ __forceinline__ uint32_t smem_u32(const void* p) {
    uint32_t a;
    asm("{ .reg .u64 t; cvta.to.shared.u64 t, %1; cvt.u32.u64 %0, t; }" : "=r"(a) : "l"(p));
    return a;
}
__device__ __forceinline__ float ex2(float x) {
    float r;
    asm("ex2.approx.f32 %0, %1;" : "=f"(r) : "f"(x));
    return r;
}

#define MMA_F16(c, a, b) \
    asm volatile("mma.sync.aligned.m16n8k16.row.col.f32.f16.f16.f32 " \
                 "{%0,%1,%2,%3}, {%4,%5,%6,%7}, {%8,%9}, {%0,%1,%2,%3};" \
                 : "+f"((c)[0]), "+f"((c)[1]), "+f"((c)[2]), "+f"((c)[3]) \
                 : "r"((a)[0]), "r"((a)[1]), "r"((a)[2]), "r"((a)[3]), \
                   "r"((b)[0]), "r"((b)[1]))

#define LDSM_X4(r0, r1, r2, r3, addr) \
    asm volatile("ldmatrix.sync.aligned.m8n8.x4.shared.b16 {%0,%1,%2,%3}, [%4];" \
                 : "=r"(r0), "=r"(r1), "=r"(r2), "=r"(r3) : "r"(addr))

#define LDSM_X4_TRANS(r0, r1, r2, r3, addr) \
    asm volatile("ldmatrix.sync.aligned.m8n8.x4.trans.shared.b16 {%0,%1,%2,%3}, [%4];" \
                 : "=r"(r0), "=r"(r1), "=r"(r2), "=r"(r3) : "r"(addr))

#define CP_ASYNC16(dst, src) \
    asm volatile("cp.async.cg.shared.global [%0], [%1], 16;" :: "r"(dst), "l"(src))
#define CP_COMMIT() asm volatile("cp.async.commit_group;" ::: "memory")
#define CP_WAIT0()  asm volatile("cp.async.wait_group 0;" ::: "memory")
#define CP_WAIT1()  asm volatile("cp.async.wait_group 1;" ::: "memory")

// ---------------- fused fp32 -> fp16 conversion pass -------------
__global__ __launch_bounds__(256) void cvt_all_kernel(
    const float4* __restrict__ x,  const float4* __restrict__ wq,
    const float4* __restrict__ wk, const float4* __restrict__ wv,
    const float4* __restrict__ wo, uint2* __restrict__ xh,
    uint2* __restrict__ wh)
{
    const int XB = S_TOK * DIM / 4;
    const int WB = DIM * DIM / 4;
    const int total = XB + 4 * WB;
    for (int i = blockIdx.x * blockDim.x + threadIdx.x; i < total;
         i += gridDim.x * blockDim.x) {
        const float4* src; uint2* dst; int off;
        if (i < XB) { src = x; dst = xh; off = i; }
        else {
            int j = i - XB;
            int r = j / WB;
            off = j - r * WB;
            src = (r == 0) ? wq : (r == 1) ? wk : (r == 2) ? wv : wo;
            dst = wh + (size_t)r * WB;
        }
        float4 v = src[off];
        dst[off] = make_uint2(f2h2(v.x, v.y), f2h2(v.z, v.w));
    }
}

// ================= fp16 mma.sync GEMM (NT, ldmatrix) =============
// CTA tile 256x128, K-chunk 32 halves, 512 threads, 16 warps (4x4),
// warp tile 64x32, 3-stage cp.async pipeline, ldmatrix frag loads.
#define GBM 256
#define GBN 128
#define GBK 32
#define AST 20
#define GTILE_A (256 * AST)
#define GTILE_B (128 * AST)
#define GSTAGE  (GTILE_A + GTILE_B)
#define GEMM_SMEM (3 * GSTAGE * 4)    // 92160 B

struct GemmCore {
    const __half* A; const __half* B; int K; int m0; int n0;
    uint32_t sBase;
    int lrow, lc16;
    __device__ __forceinline__ void load_async(int stage, int k0) const {
        uint32_t sb = sBase + (uint32_t)(stage * GSTAGE) * 4;
        CP_ASYNC16(sb + (uint32_t)(lrow * AST + lc16 * 4) * 4,
                   A + (size_t)(m0 + lrow) * K + k0 + lc16 * 8);
        CP_ASYNC16(sb + (uint32_t)((lrow + 128) * AST + lc16 * 4) * 4,
                   A + (size_t)(m0 + lrow + 128) * K + k0 + lc16 * 8);
        CP_ASYNC16(sb + (uint32_t)(GTILE_A + lrow * AST + lc16 * 4) * 4,
                   B + (size_t)(n0 + lrow) * K + k0 + lc16 * 8);
        CP_COMMIT();
    }
};

// a_ldm/b_ldm: per-lane ldmatrix byte offsets (relative to tile base)
__device__ __forceinline__ void gemm_chunk_f16(
    uint32_t aBase, uint32_t bBase, uint32_t a_ldm, uint32_t b_ldm,
    float acc[4][4][4])
{
    #pragma unroll
    for (int ks = 0; ks < 2; ++ks) {
        uint32_t af[4][4];
        #pragma unroll
        for (int mi = 0; mi < 4; ++mi)
            LDSM_X4(af[mi][0], af[mi][1], af[mi][2], af[mi][3],
                    aBase + a_ldm + (uint32_t)((16 * mi * AST + ks * 8) * 4));
        uint32_t bf[4][2];
        #pragma unroll
        for (int nip = 0; nip < 2; ++nip) {
            uint32_t b0, b1, b2, b3;
            LDSM_X4(b0, b1, b2, b3,
                    bBase + b_ldm + (uint32_t)((16 * nip * AST + ks * 8) * 4));
            bf[2 * nip][0] = b0; bf[2 * nip][1] = b1;
            bf[2 * nip + 1][0] = b2; bf[2 * nip + 1][1] = b3;
        }
        #pragma unroll
        for (int mi = 0; mi < 4; ++mi)
            #pragma unroll
            for (int ni = 0; ni < 4; ++ni)
                MMA_F16(acc[mi][ni], af[mi], bf[ni]);
    }
}

#define GEMM_PROLOG_BODY(Aop, Bop, Kval)                                     \
    extern __shared__ uint32_t sm[];                                         \
    const int t    = threadIdx.x;                                            \
    const int lane = t & 31;                                                 \
    const int wid  = t >> 5;                                                 \
    const int wm   = (wid & 3) * 64;                                         \
    const int wn   = (wid >> 2) * 32;                                        \
    const int fr   = lane >> 2;                                              \
    const int fc   = lane & 3;                                               \
    const int lq   = lane >> 3;                                              \
    const int lr8  = lane & 7;                                               \
    const uint32_t a_ldm =                                                   \
        (uint32_t)(((wm + 8 * (lq & 1) + lr8) * AST + (lq >> 1) * 4) * 4);   \
    const uint32_t b_ldm =                                                   \
        (uint32_t)(((wn + 8 * (lq >> 1) + lr8) * AST + (lq & 1) * 4) * 4);   \
    float acc[4][4][4];                                                      \
    _Pragma("unroll")                                                        \
    for (int mi = 0; mi < 4; ++mi)                                           \
        _Pragma("unroll")                                                    \
        for (int ni = 0; ni < 4; ++ni)                                       \
            _Pragma("unroll")                                                \
            for (int r = 0; r < 4; ++r) acc[mi][ni][r] = 0.f;                \
    GemmCore core;                                                           \
    core.A = Aop; core.B = Bop; core.K = Kval; core.m0 = m0; core.n0 = n0;   \
    core.sBase = smem_u32(sm);                                               \
    core.lrow = t >> 2; core.lc16 = t & 3;                                   \
    const int NCH = (Kval) / GBK;                                            \
    core.load_async(0, 0);                                                   \
    core.load_async(1, GBK);                                                 \
    for (int c = 0; c < NCH; ++c) {                                          \
        if (c + 1 < NCH) { CP_WAIT1(); } else { CP_WAIT0(); }                \
        __syncthreads();                                                     \
        if (c + 2 < NCH) core.load_async((c + 2) % 3, (c + 2) * GBK);        \
        const int stg = c % 3;                                               \
        uint32_t aB = core.sBase + (uint32_t)(stg * GSTAGE) * 4;             \
        gemm_chunk_f16(aB, aB + (uint32_t)GTILE_A * 4, a_ldm, b_ldm, acc);   \
    }

// ---- O-projection GEMM: half inputs, fp32 output + bias ----
__global__ __launch_bounds__(512, 1) void f16_gemm_nt(
    const __half* __restrict__ A, const __half* __restrict__ B,
    const float* __restrict__ bias, float* __restrict__ C,
    int M, int N, int K)
{
    const int m0 = blockIdx.y * GBM;
    const int n0 = blockIdx.x * GBN;
    GEMM_PROLOG_BODY(A, B, K)

    const int c2 = fc * 2;
    #pragma unroll
    for (int mi = 0; mi < 4; ++mi) {
        #pragma unroll
        for (int ni = 0; ni < 4; ++ni) {
            int row = m0 + wm + mi * 16 + fr;
            int col = n0 + wn + ni * 8 + c2;
            float b0 = bias[col], b1 = bias[col + 1];
            *(float2*)&C[(size_t)row * N + col] =
                make_float2(acc[mi][ni][0] + b0, acc[mi][ni][1] + b1);
            *(float2*)&C[(size_t)(row + 8) * N + col] =
                make_float2(acc[mi][ni][2] + b0, acc[mi][ni][3] + b1);
        }
    }
}

// ---- fused QKV GEMM: q,k -> fp32; v -> half ----
__global__ __launch_bounds__(512, 1) void f16_gemm_qkv(
    const __half* __restrict__ A, const __half* __restrict__ Bw,
    const float* __restrict__ bq, const float* __restrict__ bk,
    const float* __restrict__ bv,
    float* __restrict__ Cq, float* __restrict__ Ck, __half* __restrict__ Cv)
{
    const int m0 = blockIdx.y * GBM;
    const int n0 = blockIdx.x * GBN;
    GEMM_PROLOG_BODY(A, Bw, DIM)

    const int which = blockIdx.x / 12;         // 0=q 1=k 2=v
    const int ncol0 = (blockIdx.x % 12) * 128;
    const int c2 = fc * 2;
    if (which == 2) {
        #pragma unroll
        for (int mi = 0; mi < 4; ++mi)
            #pragma unroll
            for (int ni = 0; ni < 4; ++ni) {
                int row = m0 + wm + mi * 16 + fr;
                int col = ncol0 + wn + ni * 8 + c2;
                float b0 = bv[col], b1 = bv[col + 1];
                *(uint32_t*)&g_vh[(size_t)row * DIM + col] =
                    f2h2(acc[mi][ni][0] + b0, acc[mi][ni][1] + b1);
                *(uint32_t*)&g_vh[(size_t)(row + 8) * DIM + col] =
                    f2h2(acc[mi][ni][2] + b0, acc[mi][ni][3] + b1);
            }
    } else {
        float* C = which == 0 ? Cq : Ck;
        const float* bias = which == 0 ? bq : bk;
        #pragma unroll
        for (int mi = 0; mi < 4; ++mi)
            #pragma unroll
            for (int ni = 0; ni < 4; ++ni) {
                int row = m0 + wm + mi * 16 + fr;
                int col = ncol0 + wn + ni * 8 + c2;
                float b0 = bias[col], b1 = bias[col + 1];
                *(float2*)&C[(size_t)row * DIM + col] =
                    make_float2(acc[mi][ni][0] + b0, acc[mi][ni][1] + b1);
                *(float2*)&C[(size_t)(row + 8) * DIM + col] =
                    make_float2(acc[mi][ni][2] + b0, acc[mi][ni][3] + b1);
            }
    }
}

// ----------------------------------------------------------------
// Fused RMSNorm (with gains) + RoPE: fp32 in -> half out.
// q scaled by (1/sqrt(HD)) * log2(e) so attention can use raw ex2.
// ----------------------------------------------------------------
__global__ __launch_bounds__(256) void normrope_kernel(
    const float* __restrict__ gq, const float* __restrict__ gk,
    const float* __restrict__ freqs)
{
    const int tok = blockIdx.x;
    const int t   = threadIdx.x;
    const float* qr = g_q + (size_t)tok * DIM;
    const float* kr = g_k + (size_t)tok * DIM;
    __half* qh = g_qh + (size_t)tok * DIM;
    __half* kh = g_kh + (size_t)tok * DIM;

    __shared__ float red[16];
    __shared__ float s_scq, s_sck;

    float sq = 0.f, sk = 0.f;
    for (int i = t; i < DIM; i += 256) {
        float a = qr[i]; sq += a * a;
        float b = kr[i]; sk += b * b;
    }
    #pragma unroll
    for (int m = 16; m >= 1; m >>= 1) {
        sq += __shfl_xor_sync(0xffffffffu, sq, m);
        sk += __shfl_xor_sync(0xffffffffu, sk, m);
    }
    if ((t & 31) == 0) { red[t >> 5] = sq; red[8 + (t >> 5)] = sk; }
    __syncthreads();
    if (t == 0) {
        float a = 0.f, b = 0.f;
        #pragma unroll
        for (int w = 0; w < 8; ++w) { a += red[w]; b += red[8 + w]; }
        s_scq = rsqrtf(a * (1.f / DIM) + 1e-6f);
        s_sck = rsqrtf(b * (1.f / DIM) + 1e-6f);
    }
    __syncthreads();
    const float scq = s_scq * (0.08838834764831845f * 1.4426950408889634f);
    const float sck = s_sck;

    for (int p = t; p < DIM / 2; p += 256) {
        int hh = p >> 6, i = p & 63;
        int c0 = hh * HD + 2 * i;
        float fr = freqs[(size_t)tok * (HD / 2) + i];
        float cs = cosf(fr), sn = sinf(fr);
        float qe = qr[c0] * scq * gq[c0];
        float qo = qr[c0 + 1] * scq * gq[c0 + 1];
        *(uint32_t*)&qh[c0] = f2h2(qe * cs - qo * sn, qe * sn + qo * cs);
        float ke = kr[c0] * sck * gk[c0];
        float ko = kr[c0 + 1] * sck * gk[c0 + 1];
        *(uint32_t*)&kh[c0] = f2h2(ke * cs - ko * sn, ke * sn + ko * cs);
    }
}

// ================= fp16 tensor-core flash attention ==============
// BM=128 q rows (8 warps x 16), BN=64 kv, HD=128. m16n8k16.
// K b-frags + P a-frags via ldmatrix.x4; V via ldmatrix.x4.trans.
#define ABM 128
#define ABN 64
#define KSTW 68
#define KVTILE (64 * KSTW)
#define PSTW 36
#define ATTN_SMEM ((4 * KVTILE + 128 * PSTW) * 4)   // 88064 B

__global__ __launch_bounds__(256, 2) void attn_f16_kernel()
{
    extern __shared__ uint32_t smw[];
    uint32_t* Ps = smw + 4 * KVTILE;
    const uint32_t sBase = smem_u32(smw);
    const uint32_t psBase = sBase + (uint32_t)(4 * KVTILE) * 4;

    const int t    = threadIdx.x;
    const int lane = t & 31;
    const int w    = t >> 5;
    const int fr   = lane >> 2;
    const int fc   = lane & 3;
    const int lq   = lane >> 3;
    const int lr8  = lane & 7;
    const int mt = blockIdx.x, f = blockIdx.y, h = blockIdx.z;
    const int q0 = f * IMG + mt * ABM;
    int st = f - 7; st = st < 0 ? 0 : (st > 6 ? 6 : st);
    const int kbase = st * IMG;

    // ldmatrix per-lane byte offsets
    const uint32_t vofs  = (uint32_t)((lane & 15) * KSTW + 4 * (lane >> 4)) * 4;
    const uint32_t k_ldm = (uint32_t)(((8 * (lq >> 1) + lr8) * KSTW + (lq & 1) * 4) * 4);
    const uint32_t p_ldm = (uint32_t)(((16 * w + 8 * (lq & 1) + lr8) * PSTW + (lq >> 1) * 4) * 4);

    uint32_t qf[8][4];
    {
        const __half* Q0 = g_qh + (size_t)(q0 + 16 * w + fr) * DIM + h * HD;
        const __half* Q8 = Q0 + 8 * DIM;
        #pragma unroll
        for (int ks = 0; ks < 8; ++ks) {
            const int kc = ks * 16;
            qf[ks][0] = *(const uint32_t*)&Q0[kc + 2 * fc];
            qf[ks][1] = *(const uint32_t*)&Q8[kc + 2 * fc];
            qf[ks][2] = *(const uint32_t*)&Q0[kc + 2 * fc + 8];
            qf[ks][3] = *(const uint32_t*)&Q8[kc + 2 * fc + 8];
        }
    }

    float o[16][4];
    #pragma unroll
    for (int nf = 0; nf < 16; ++nf)
        #pragma unroll
        for (int r = 0; r < 4; ++r) o[nf][r] = 0.f;
    float Mlo = -INFINITY, Mhi = -INFINITY, Llo = 0.f, Lhi = 0.f;

    const int prow0 = (16 * w + fr) * PSTW;
    const int prow8 = (16 * w + fr + 8) * PSTW;

    auto stage_kv = [&](int buf, int cc) {
        const int kb = kbase + cc * ABN;
        const uint32_t sK = sBase + (uint32_t)(buf * 2 * KVTILE) * 4;
        const uint32_t sV = sK + (uint32_t)KVTILE * 4;
        #pragma unroll
        for (int i = 0; i < 4; ++i) {
            int idx = t + i * 256;
            int row = idx >> 4, c16 = idx & 15;
            uint32_t off = (uint32_t)(row * KSTW + c16 * 4) * 4;
            CP_ASYNC16(sK + off, g_kh + (size_t)(kb + row) * DIM + h * HD + c16 * 8);
            CP_ASYNC16(sV + off, g_vh + (size_t)(kb + row) * DIM + h * HD + c16 * 8);
        }
        CP_COMMIT();
    };

    stage_kv(0, 0);

    for (int c = 0; c < WKV / ABN; ++c) {
        CP_WAIT0();
        __syncthreads();
        if (c + 1 < WKV / ABN) stage_kv((c + 1) & 1, c + 1);

        const uint32_t kTile = sBase + (uint32_t)((c & 1) * 2 * KVTILE) * 4;
        const uint32_t vbase = kTile + (uint32_t)KVTILE * 4 + vofs;

        // ---- S = Q K^T (b-frags via ldmatrix.x4) ----
        float s[8][4];
        #pragma unroll
        for (int nf = 0; nf < 8; ++nf)
            #pragma unroll
            for (int r = 0; r < 4; ++r) s[nf][r] = 0.f;

        #pragma unroll
        for (int ks = 0; ks < 8; ++ks) {
            #pragma unroll
            for (int nfp = 0; nfp < 4; ++nfp) {
                uint32_t b0, b1, b2, b3;
                LDSM_X4(b0, b1, b2, b3,
                        kTile + k_ldm + (uint32_t)((16 * nfp * KSTW + ks * 8) * 4));
                uint32_t lo[2] = { b0, b1 };
                MMA_F16(s[2 * nfp], qf[ks], lo);
                uint32_t hi2[2] = { b2, b3 };
                MMA_F16(s[2 * nfp + 1], qf[ks], hi2);
            }
        }

        // ---- online softmax (base-2) ----
        float mlo = -INFINITY, mhi = -INFINITY;
        #pragma unroll
        for (int nf = 0; nf < 8; ++nf) {
            mlo = fmaxf(mlo, fmaxf(s[nf][0], s[nf][1]));
            mhi = fmaxf(mhi, fmaxf(s[nf][2], s[nf][3]));
        }
        mlo = fmaxf(mlo, __shfl_xor_sync(0xffffffffu, mlo, 1));
        mlo = fmaxf(mlo, __shfl_xor_sync(0xffffffffu, mlo, 2));
        mhi = fmaxf(mhi, __shfl_xor_sync(0xffffffffu, mhi, 1));
        mhi = fmaxf(mhi, __shfl_xor_sync(0xffffffffu, mhi, 2));
        const float Mnlo = fmaxf(Mlo, mlo), Mnhi = fmaxf(Mhi, mhi);
        const float alo = ex2(Mlo - Mnlo), ahi = ex2(Mhi - Mnhi);
        Mlo = Mnlo; Mhi = Mnhi;

        float rlo = 0.f, rhi = 0.f;
        #pragma unroll
        for (int nf = 0; nf < 8; ++nf) {
            __half h0 = __float2half_rn(ex2(s[nf][0] - Mnlo));
            __half h1 = __float2half_rn(ex2(s[nf][1] - Mnlo));
            __half h2 = __float2half_rn(ex2(s[nf][2] - Mnhi));
            __half h3 = __float2half_rn(ex2(s[nf][3] - Mnhi));
            rlo += __half2float(h0) + __half2float(h1);
            rhi += __half2float(h2) + __half2float(h3);
            Ps[prow0 + 4 * nf + fc] =
                (uint32_t)__half_as_ushort(h0) | ((uint32_t)__half_as_ushort(h1) << 16);
            Ps[prow8 + 4 * nf + fc] =
                (uint32_t)__half_as_ushort(h2) | ((uint32_t)__half_as_ushort(h3) << 16);
        }
        rlo += __shfl_xor_sync(0xffffffffu, rlo, 1);
        rlo += __shfl_xor_sync(0xffffffffu, rlo, 2);
        rhi += __shfl_xor_sync(0xffffffffu, rhi, 1);
        rhi += __shfl_xor_sync(0xffffffffu, rhi, 2);
        Llo = Llo * alo + rlo;
        Lhi = Lhi * ahi + rhi;
        #pragma unroll
        for (int nf = 0; nf < 16; ++nf) {
            o[nf][0] *= alo; o[nf][1] *= alo;
            o[nf][2] *= ahi; o[nf][3] *= ahi;
        }
        __syncwarp();

        // ---- O += P V  (P a-frags + V b-frags via ldmatrix) ----
        #pragma unroll
        for (int k2 = 0; k2 < 4; ++k2) {
            uint32_t a[4];
            LDSM_X4(a[0], a[1], a[2], a[3], psBase + p_ldm + (uint32_t)(k2 * 8 * 4));
            #pragma unroll
            for (int nfp = 0; nfp < 8; ++nfp) {
                uint32_t b0, b1, b2, b3;
                LDSM_X4_TRANS(b0, b1, b2, b3,
                              vbase + (uint32_t)(k2 * 16 * KSTW + 8 * nfp) * 4);
                uint32_t lo[2] = { b0, b1 };
                MMA_F16(o[2 * nfp], a, lo);
                uint32_t hi2[2] = { b2, b3 };
                MMA_F16(o[2 * nfp + 1], a, hi2);
            }
        }
        __syncwarp();
    }

    // ---- epilogue: normalize, write half ----
    const float il = 1.f / Llo, ih = 1.f / Lhi;
    const int row0 = q0 + 16 * w + fr;
    #pragma unroll
    for (int nf = 0; nf < 16; ++nf) {
        const int col = h * HD + 8 * nf + 2 * fc;
        *(uint32_t*)&g_attnh[(size_t)row0 * DIM + col] =
            f2h2(o[nf][0] * il, o[nf][1] * il);
        *(uint32_t*)&g_attnh[(size_t)(row0 + 8) * DIM + col] =
            f2h2(o[nf][2] * ih, o[nf][3] * ih);
    }
}

// ----------------------------------------------------------------
extern "C" void kernel_launch(void* const* d_in, const int* in_sizes, int n_in,
                              void* d_out, int out_size)
{
    const float* x     = (const float*)d_in[0];
    const float* freqs = (const float*)d_in[1];
    const float* Wq    = (const float*)d_in[2];
    const float* bq    = (const float*)d_in[3];
    const float* Wk    = (const float*)d_in[4];
    const float* bk    = (const float*)d_in[5];
    const float* Wv    = (const float*)d_in[6];
    const float* bv    = (const float*)d_in[7];
    const float* Wo    = (const float*)d_in[8];
    const float* bo    = (const float*)d_in[9];
    const float* gq    = (const float*)d_in[10];
    const float* gk    = (const float*)d_in[11];
    float* out = (float*)d_out;

    void *pq, *pk, *pxh, *pwh, *pvh, *pah;
    cudaGetSymbolAddress(&pq, g_q);
    cudaGetSymbolAddress(&pk, g_k);
    cudaGetSymbolAddress(&pxh, g_xh);
    cudaGetSymbolAddress(&pwh, g_wh);
    cudaGetSymbolAddress(&pvh, g_vh);
    cudaGetSymbolAddress(&pah, g_attnh);
    __half* xh = (__half*)pxh;
    __half* wh = (__half*)pwh;

    cvt_all_kernel<<<2368, 256>>>((const float4*)x, (const float4*)Wq,
                                  (const float4*)Wk, (const float4*)Wv,
                                  (const float4*)Wo, (uint2*)xh, (uint2*)wh);

    cudaFuncSetAttribute(f16_gemm_qkv, cudaFuncAttributeMaxDynamicSharedMemorySize, GEMM_SMEM);
    cudaFuncSetAttribute(f16_gemm_nt, cudaFuncAttributeMaxDynamicSharedMemorySize, GEMM_SMEM);

    f16_gemm_qkv<<<dim3(36, S_TOK / 256), 512, GEMM_SMEM>>>(
        xh, wh, bq, bk, bv, (float*)pq, (float*)pk, (__half*)pvh);

    normrope_kernel<<<S_TOK, 256>>>(gq, gk, freqs);

    cudaFuncSetAttribute(attn_f16_kernel, cudaFuncAttributeMaxDynamicSharedMemorySize, ATTN_SMEM);
    attn_f16_kernel<<<dim3(IMG / ABM, NF, NH), 256, ATTN_SMEM>>>();

    f16_gemm_nt<<<dim3(12, S_TOK / 256), 512, GEMM_SMEM>>>(
        (const __half*)pah, wh + 3 * (size_t)DIM * DIM, bo, out, S_TOK, DIM, DIM);
}